// round 4
// baseline (speedup 1.0000x reference)
#include <cuda_runtime.h>
#include <math.h>
#include <stdint.h>

#define BB 2
#define TT 2048
#define DD 2048
#define HH 16
#define KVH 4
#define HD 128
#define RD 64

// ---------------- device scratch (no allocs allowed) ----------------
__device__ float g_qs[4096 * 2048];   // roped Q, [B*T, H*HD]
__device__ float g_att[4096 * 2048];  // attention out, [B*T, H*HD]

__device__ __forceinline__ uint32_t f2tf(float x) {
    uint32_t r;
    asm("cvt.rna.tf32.f32 %0, %1;" : "=r"(r) : "f"(x));
    return r;
}
__device__ __forceinline__ float tfs(float x) {
    uint32_t r = f2tf(x);
    return __uint_as_float(r);
}
__device__ __forceinline__ uint32_t u(float x) { return __float_as_uint(x); }

#define MMA_TF32(d0,d1,d2,d3,a0,a1,a2,a3,b0,b1)                         \
    asm volatile(                                                        \
        "mma.sync.aligned.m16n8k8.row.col.f32.tf32.tf32.f32 "           \
        "{%0,%1,%2,%3}, {%4,%5,%6,%7}, {%8,%9}, {%0,%1,%2,%3};"         \
        : "+f"(d0), "+f"(d1), "+f"(d2), "+f"(d3)                         \
        : "r"(a0), "r"(a1), "r"(a2), "r"(a3), "r"(b0), "r"(b1))

// -------- TF32 tensor-core GEMM, double-buffered smem -----------------
// C[M,N] = A[M,K] @ B[K,N], 128x128 tile, BK=16, 256 threads = 8 warps,
// warp tile 64x32. MODE epilogues:
//  0: plain row-major C
//  1: RoPE (cols d<RD of each 128-head) -> C row-major ([token][H*HD])
//  2: RoPE + transpose -> C[B,KV,T,HD]
//  3: transpose -> C[B,KV,T,HD]
#define SAS 136

template <int MODE>
__global__ __launch_bounds__(256) void gemm_tf32(
    const float* __restrict__ A, const float* __restrict__ B,
    float* __restrict__ C, int M, int N, int K,
    const float* __restrict__ fcos, const float* __restrict__ fsin) {
    __shared__ float As[2][16 * SAS];  // [k][m], tf32 bits
    __shared__ float Bs[2][16 * SAS];  // [k][n], tf32 bits
    int tid = threadIdx.x, lane = tid & 31;
    int w = tid >> 5, wm = w & 1, wn = w >> 1;
    int m0 = wm * 64, n0 = wn * 32;
    int g = lane >> 2, tig = lane & 3;
    int brow = blockIdx.y * 128, bcol = blockIdx.x * 128;

    int arow = tid & 63, akc = (tid >> 6) * 4;
    int bkr = tid >> 5, bc4 = (tid & 31) * 4;

    const float* Ap  = A + (size_t)(brow + arow) * K + akc;
    const float* Ap2 = Ap + (size_t)64 * K;
    const float* Bp  = B + (size_t)bkr * N + bcol + bc4;
    const float* Bp2 = Bp + (size_t)8 * N;

    float acc[4][4][4];
    #pragma unroll
    for (int mt = 0; mt < 4; mt++)
        #pragma unroll
        for (int nt = 0; nt < 4; nt++)
            #pragma unroll
            for (int i = 0; i < 4; i++) acc[mt][nt][i] = 0.f;

    // prologue: tile 0 -> buf 0
    {
        float4 a1 = *(const float4*)(Ap);
        float4 a2 = *(const float4*)(Ap2);
        float4 b1 = *(const float4*)(Bp);
        float4 b2 = *(const float4*)(Bp2);
        As[0][(akc + 0) * SAS + arow] = tfs(a1.x);
        As[0][(akc + 1) * SAS + arow] = tfs(a1.y);
        As[0][(akc + 2) * SAS + arow] = tfs(a1.z);
        As[0][(akc + 3) * SAS + arow] = tfs(a1.w);
        As[0][(akc + 0) * SAS + arow + 64] = tfs(a2.x);
        As[0][(akc + 1) * SAS + arow + 64] = tfs(a2.y);
        As[0][(akc + 2) * SAS + arow + 64] = tfs(a2.z);
        As[0][(akc + 3) * SAS + arow + 64] = tfs(a2.w);
        Bs[0][bkr * SAS + bc4 + 0] = tfs(b1.x);
        Bs[0][bkr * SAS + bc4 + 1] = tfs(b1.y);
        Bs[0][bkr * SAS + bc4 + 2] = tfs(b1.z);
        Bs[0][bkr * SAS + bc4 + 3] = tfs(b1.w);
        Bs[0][(bkr + 8) * SAS + bc4 + 0] = tfs(b2.x);
        Bs[0][(bkr + 8) * SAS + bc4 + 1] = tfs(b2.y);
        Bs[0][(bkr + 8) * SAS + bc4 + 2] = tfs(b2.z);
        Bs[0][(bkr + 8) * SAS + bc4 + 3] = tfs(b2.w);
    }
    __syncthreads();

    int nk = K / 16;
    int buf = 0;
    for (int kt = 0; kt < nk; kt++) {
        float4 a1, a2, b1, b2;
        bool has_next = (kt + 1 < nk);
        if (has_next) {
            int k0 = (kt + 1) * 16;
            a1 = *(const float4*)(Ap + k0);
            a2 = *(const float4*)(Ap2 + k0);
            b1 = *(const float4*)(Bp + (size_t)k0 * N);
            b2 = *(const float4*)(Bp2 + (size_t)k0 * N);
        }

        const float* Asb = As[buf];
        const float* Bsb = Bs[buf];
        #pragma unroll
        for (int ks = 0; ks < 16; ks += 8) {
            uint32_t af[4][4], bf[4][2];
            #pragma unroll
            for (int mt = 0; mt < 4; mt++) {
                int rm = m0 + mt * 16;
                af[mt][0] = u(Asb[(ks + tig)     * SAS + rm + g]);
                af[mt][1] = u(Asb[(ks + tig)     * SAS + rm + g + 8]);
                af[mt][2] = u(Asb[(ks + tig + 4) * SAS + rm + g]);
                af[mt][3] = u(Asb[(ks + tig + 4) * SAS + rm + g + 8]);
            }
            #pragma unroll
            for (int nt = 0; nt < 4; nt++) {
                int cn = n0 + nt * 8;
                bf[nt][0] = u(Bsb[(ks + tig)     * SAS + cn + g]);
                bf[nt][1] = u(Bsb[(ks + tig + 4) * SAS + cn + g]);
            }
            #pragma unroll
            for (int mt = 0; mt < 4; mt++)
                #pragma unroll
                for (int nt = 0; nt < 4; nt++)
                    MMA_TF32(acc[mt][nt][0], acc[mt][nt][1],
                             acc[mt][nt][2], acc[mt][nt][3],
                             af[mt][0], af[mt][1], af[mt][2], af[mt][3],
                             bf[nt][0], bf[nt][1]);
        }

        if (has_next) {
            float* An = As[buf ^ 1];
            float* Bn = Bs[buf ^ 1];
            An[(akc + 0) * SAS + arow] = tfs(a1.x);
            An[(akc + 1) * SAS + arow] = tfs(a1.y);
            An[(akc + 2) * SAS + arow] = tfs(a1.z);
            An[(akc + 3) * SAS + arow] = tfs(a1.w);
            An[(akc + 0) * SAS + arow + 64] = tfs(a2.x);
            An[(akc + 1) * SAS + arow + 64] = tfs(a2.y);
            An[(akc + 2) * SAS + arow + 64] = tfs(a2.z);
            An[(akc + 3) * SAS + arow + 64] = tfs(a2.w);
            Bn[bkr * SAS + bc4 + 0] = tfs(b1.x);
            Bn[bkr * SAS + bc4 + 1] = tfs(b1.y);
            Bn[bkr * SAS + bc4 + 2] = tfs(b1.z);
            Bn[bkr * SAS + bc4 + 3] = tfs(b1.w);
            Bn[(bkr + 8) * SAS + bc4 + 0] = tfs(b2.x);
            Bn[(bkr + 8) * SAS + bc4 + 1] = tfs(b2.y);
            Bn[(bkr + 8) * SAS + bc4 + 2] = tfs(b2.z);
            Bn[(bkr + 8) * SAS + bc4 + 3] = tfs(b2.w);
            __syncthreads();
            buf ^= 1;
        }
    }

    // -------- epilogue --------
    #pragma unroll
    for (int mt = 0; mt < 4; mt++) {
        int row = brow + m0 + mt * 16 + g;      // token index (rows 0..M-1)
        int row2 = row + 8;
        #pragma unroll
        for (int nt = 0; nt < 4; nt++) {
            int col = bcol + n0 + nt * 8 + tig * 2;
            float c0 = acc[mt][nt][0], c1 = acc[mt][nt][1];
            float c2 = acc[mt][nt][2], c3 = acc[mt][nt][3];

            if (MODE == 0) {
                *(float2*)&C[(size_t)row  * N + col] = make_float2(c0, c1);
                *(float2*)&C[(size_t)row2 * N + col] = make_float2(c2, c3);
            } else {
                int d = col & (HD - 1);
                if (MODE != 3 && d < RD) {
                    int i = d >> 1;
                    int t1 = row  & (TT - 1);
                    int t2 = row2 & (TT - 1);
                    float cc1 = fcos[t1 * (RD / 2) + i];
                    float ss1 = fsin[t1 * (RD / 2) + i];
                    float cc2 = fcos[t2 * (RD / 2) + i];
                    float ss2 = fsin[t2 * (RD / 2) + i];
                    float r0 = c0 * cc1 - c1 * ss1;
                    float r1 = c0 * ss1 + c1 * cc1;
                    float r2 = c2 * cc2 - c3 * ss2;
                    float r3 = c2 * ss2 + c3 * cc2;
                    c0 = r0; c1 = r1; c2 = r2; c3 = r3;
                }
                if (MODE == 1) {
                    *(float2*)&C[(size_t)row  * N + col] = make_float2(c0, c1);
                    *(float2*)&C[(size_t)row2 * N + col] = make_float2(c2, c3);
                } else {
                    // transpose to [B, KV, T, HD]
                    int kv = col >> 7;
                    int b1i = row >> 11, t1 = row & (TT - 1);
                    int b2i = row2 >> 11, t2 = row2 & (TT - 1);
                    size_t dst1 = ((size_t)(b1i * KVH + kv) * TT + t1) * HD + d;
                    size_t dst2 = ((size_t)(b2i * KVH + kv) * TT + t2) * HD + d;
                    *(float2*)&C[dst1] = make_float2(c0, c1);
                    *(float2*)&C[dst2] = make_float2(c2, c3);
                }
            }
        }
    }
}

// ------------- tensor-core causal flash attention ---------------------
#define FST 132
#define QS_OFF 0
#define KS_OFF (64 * FST)
#define VS_OFF (KS_OFF + 32 * FST)
#define PS_OFF (VS_OFF + 32 * FST)
#define FSMEM_FLOATS (PS_OFF + 4 * 16 * 33)

__global__ __launch_bounds__(128) void flash_mma_kernel(
    const float* __restrict__ Q, const float* __restrict__ K,
    const float* __restrict__ V, float* __restrict__ O) {
    extern __shared__ float fsm[];
    float* Qs = fsm + QS_OFF;
    float* Ks = fsm + KS_OFF;
    float* Vs = fsm + VS_OFF;

    int tid = threadIdx.x, lane = tid & 31, w = tid >> 5;
    int g = lane >> 2, tig = lane & 3;
    int b = blockIdx.z, h = blockIdx.y, q0 = blockIdx.x * 64;
    int kvh = h >> 2;
    const float scale = 0.08838834764831845f;

    {
        int r = tid >> 2, cb = (tid & 3) * 4;
        const float* qg = Q + ((size_t)(b * TT + q0 + r)) * (HH * HD) + h * HD;
        const float* qg2 = qg + (size_t)32 * (HH * HD);
        #pragma unroll
        for (int i = 0; i < 8; i++) {
            float4 v = *(const float4*)(qg + cb + i * 16);
            Qs[r * FST + cb + i * 16 + 0] = tfs(v.x * scale);
            Qs[r * FST + cb + i * 16 + 1] = tfs(v.y * scale);
            Qs[r * FST + cb + i * 16 + 2] = tfs(v.z * scale);
            Qs[r * FST + cb + i * 16 + 3] = tfs(v.w * scale);
            float4 v2 = *(const float4*)(qg2 + cb + i * 16);
            Qs[(r + 32) * FST + cb + i * 16 + 0] = tfs(v2.x * scale);
            Qs[(r + 32) * FST + cb + i * 16 + 1] = tfs(v2.y * scale);
            Qs[(r + 32) * FST + cb + i * 16 + 2] = tfs(v2.z * scale);
            Qs[(r + 32) * FST + cb + i * 16 + 3] = tfs(v2.w * scale);
        }
    }
    __syncthreads();

    uint32_t qf[16][4];
    int qw = w * 16;
    #pragma unroll
    for (int kf = 0; kf < 16; kf++) {
        qf[kf][0] = u(Qs[(qw + g)     * FST + kf * 8 + tig]);
        qf[kf][1] = u(Qs[(qw + g + 8) * FST + kf * 8 + tig]);
        qf[kf][2] = u(Qs[(qw + g)     * FST + kf * 8 + tig + 4]);
        qf[kf][3] = u(Qs[(qw + g + 8) * FST + kf * 8 + tig + 4]);
    }

    float o[16][4];
    #pragma unroll
    for (int df = 0; df < 16; df++)
        o[df][0] = o[df][1] = o[df][2] = o[df][3] = 0.f;
    float m0 = -1e30f, m1 = -1e30f, l0 = 0.f, l1 = 0.f;

    int qglob = q0 + qw;
    int ntiles = q0 / 32 + 2;
    float* Pw = fsm + PS_OFF + w * (16 * 33);

    for (int tile = 0; tile < ntiles; tile++) {
        int kv0 = tile * 32;
        __syncthreads();
        {
            int r = tid >> 2, cb = (tid & 3) * 4;
            const float* kg = K + ((size_t)(b * KVH + kvh) * TT + kv0 + r) * HD;
            const float* vg = V + ((size_t)(b * KVH + kvh) * TT + kv0 + r) * HD;
            #pragma unroll
            for (int i = 0; i < 8; i++) {
                float4 kv4 = *(const float4*)(kg + cb + i * 16);
                Ks[r * FST + cb + i * 16 + 0] = tfs(kv4.x);
                Ks[r * FST + cb + i * 16 + 1] = tfs(kv4.y);
                Ks[r * FST + cb + i * 16 + 2] = tfs(kv4.z);
                Ks[r * FST + cb + i * 16 + 3] = tfs(kv4.w);
                float4 vv4 = *(const float4*)(vg + cb + i * 16);
                Vs[r * FST + cb + i * 16 + 0] = tfs(vv4.x);
                Vs[r * FST + cb + i * 16 + 1] = tfs(vv4.y);
                Vs[r * FST + cb + i * 16 + 2] = tfs(vv4.z);
                Vs[r * FST + cb + i * 16 + 3] = tfs(vv4.w);
            }
        }
        __syncthreads();

        float s[4][4];
        #pragma unroll
        for (int nf = 0; nf < 4; nf++) {
            s[nf][0] = s[nf][1] = s[nf][2] = s[nf][3] = 0.f;
            const float* kr = &Ks[(nf * 8 + g) * FST];
            #pragma unroll
            for (int kf = 0; kf < 16; kf++) {
                uint32_t b0 = u(kr[kf * 8 + tig]);
                uint32_t b1 = u(kr[kf * 8 + tig + 4]);
                MMA_TF32(s[nf][0], s[nf][1], s[nf][2], s[nf][3],
                         qf[kf][0], qf[kf][1], qf[kf][2], qf[kf][3], b0, b1);
            }
        }

        if (kv0 + 31 > qglob) {
            int r0 = qglob + g, r1 = qglob + g + 8;
            #pragma unroll
            for (int nf = 0; nf < 4; nf++) {
                int c = kv0 + nf * 8 + tig * 2;
                if (c     > r0) s[nf][0] = -1e30f;
                if (c + 1 > r0) s[nf][1] = -1e30f;
                if (c     > r1) s[nf][2] = -1e30f;
                if (c + 1 > r1) s[nf][3] = -1e30f;
            }
        }

        float mx0 = -1e30f, mx1 = -1e30f;
        #pragma unroll
        for (int nf = 0; nf < 4; nf++) {
            mx0 = fmaxf(mx0, fmaxf(s[nf][0], s[nf][1]));
            mx1 = fmaxf(mx1, fmaxf(s[nf][2], s[nf][3]));
        }
        mx0 = fmaxf(mx0, __shfl_xor_sync(0xffffffffu, mx0, 1));
        mx0 = fmaxf(mx0, __shfl_xor_sync(0xffffffffu, mx0, 2));
        mx1 = fmaxf(mx1, __shfl_xor_sync(0xffffffffu, mx1, 1));
        mx1 = fmaxf(mx1, __shfl_xor_sync(0xffffffffu, mx1, 2));
        float mn0 = fmaxf(m0, mx0), mn1 = fmaxf(m1, mx1);
        float sc0 = __expf(m0 - mn0), sc1 = __expf(m1 - mn1);
        m0 = mn0; m1 = mn1;

        float ps0 = 0.f, ps1 = 0.f;
        #pragma unroll
        for (int nf = 0; nf < 4; nf++) {
            float p0 = __expf(s[nf][0] - mn0);
            float p1 = __expf(s[nf][1] - mn0);
            float p2 = __expf(s[nf][2] - mn1);
            float p3 = __expf(s[nf][3] - mn1);
            ps0 += p0 + p1; ps1 += p2 + p3;
            Pw[(g    ) * 33 + nf * 8 + tig * 2    ] = tfs(p0);
            Pw[(g    ) * 33 + nf * 8 + tig * 2 + 1] = tfs(p1);
            Pw[(g + 8) * 33 + nf * 8 + tig * 2    ] = tfs(p2);
            Pw[(g + 8) * 33 + nf * 8 + tig * 2 + 1] = tfs(p3);
        }
        ps0 += __shfl_xor_sync(0xffffffffu, ps0, 1);
        ps0 += __shfl_xor_sync(0xffffffffu, ps0, 2);
        ps1 += __shfl_xor_sync(0xffffffffu, ps1, 1);
        ps1 += __shfl_xor_sync(0xffffffffu, ps1, 2);
        l0 = l0 * sc0 + ps0;
        l1 = l1 * sc1 + ps1;

        #pragma unroll
        for (int df = 0; df < 16; df++) {
            o[df][0] *= sc0; o[df][1] *= sc0;
            o[df][2] *= sc1; o[df][3] *= sc1;
        }
        __syncwarp();

        uint32_t pa[4][4];
        #pragma unroll
        for (int kf = 0; kf < 4; kf++) {
            pa[kf][0] = u(Pw[(g    ) * 33 + kf * 8 + tig]);
            pa[kf][1] = u(Pw[(g + 8) * 33 + kf * 8 + tig]);
            pa[kf][2] = u(Pw[(g    ) * 33 + kf * 8 + tig + 4]);
            pa[kf][3] = u(Pw[(g + 8) * 33 + kf * 8 + tig + 4]);
        }
        __syncwarp();

        #pragma unroll
        for (int df = 0; df < 16; df++) {
            #pragma unroll
            for (int kf = 0; kf < 4; kf++) {
                uint32_t b0 = u(Vs[(kf * 8 + tig)     * FST + df * 8 + g]);
                uint32_t b1 = u(Vs[(kf * 8 + tig + 4) * FST + df * 8 + g]);
                MMA_TF32(o[df][0], o[df][1], o[df][2], o[df][3],
                         pa[kf][0], pa[kf][1], pa[kf][2], pa[kf][3], b0, b1);
            }
        }
    }

    float inv0 = 1.f / l0, inv1 = 1.f / l1;
    float* ob0 = O + ((size_t)(b * TT + qglob + g))     * (HH * HD) + h * HD;
    float* ob1 = O + ((size_t)(b * TT + qglob + g + 8)) * (HH * HD) + h * HD;
    #pragma unroll
    for (int df = 0; df < 16; df++) {
        int col = df * 8 + tig * 2;
        *(float2*)(ob0 + col) = make_float2(o[df][0] * inv0, o[df][1] * inv0);
        *(float2*)(ob1 + col) = make_float2(o[df][2] * inv1, o[df][3] * inv1);
    }
}

// ---------------- launch --------------------------------------------
extern "C" void kernel_launch(void* const* d_in, const int* in_sizes, int n_in,
                              void* d_out, int out_size) {
    const float* x    = (const float*)d_in[0];
    const float* fcos = (const float*)d_in[1];
    const float* fsin = (const float*)d_in[2];
    const float* Wq   = (const float*)d_in[3];
    const float* Wk   = (const float*)d_in[4];
    const float* Wv   = (const float*)d_in[5];
    const float* Wo   = (const float*)d_in[6];

    float* y    = (float*)d_out;
    float* outK = y + (size_t)BB * TT * DD;
    float* outV = outK + (size_t)BB * KVH * TT * HD;

    float *qs, *att;
    cudaGetSymbolAddress((void**)&qs,  g_qs);
    cudaGetSymbolAddress((void**)&att, g_att);

    const int M = BB * TT;  // 4096
    const int FSMEM = FSMEM_FLOATS * 4;
    static int smem_set = 0;
    if (!smem_set) {
        cudaFuncSetAttribute(flash_mma_kernel,
                             cudaFuncAttributeMaxDynamicSharedMemorySize, FSMEM);
        smem_set = 1;
    }

    // Q = rope(x@Wq) -> g_qs ; K = rope(x@Wk) -> outK[B,KV,T,HD] ;
    // V = x@Wv -> outV[B,KV,T,HD]
    gemm_tf32<1><<<dim3(DD / 128, M / 128), 256>>>(
        x, Wq, qs, M, HH * HD, DD, fcos, fsin);
    gemm_tf32<2><<<dim3((KVH * HD) / 128, M / 128), 256>>>(
        x, Wk, outK, M, KVH * HD, DD, fcos, fsin);
    gemm_tf32<3><<<dim3((KVH * HD) / 128, M / 128), 256>>>(
        x, Wv, outV, M, KVH * HD, DD, fcos, fsin);

    flash_mma_kernel<<<dim3(TT / 64, HH, BB), 128, FSMEM>>>(qs, outK, outV, att);

    gemm_tf32<0><<<dim3(DD / 128, M / 128), 256>>>(
        att, Wo, y, M, DD, DD, fcos, fsin);
}

// round 5
// speedup vs baseline: 1.0748x; 1.0748x over previous
#include <cuda_runtime.h>
#include <math.h>
#include <stdint.h>

#define BB 2
#define TT 2048
#define DD 2048
#define HH 16
#define KVH 4
#define HD 128
#define RD 64

// ---------------- device scratch (no allocs allowed) ----------------
__device__ float g_qs[4096 * 2048];   // roped Q, [B*T, H*HD]
__device__ float g_att[4096 * 2048];  // attention out, [B*T, H*HD]

__device__ __forceinline__ uint32_t f2tf(float x) {
    uint32_t r;
    asm("cvt.rna.tf32.f32 %0, %1;" : "=r"(r) : "f"(x));
    return r;
}
__device__ __forceinline__ float tfs(float x) {
    uint32_t r = f2tf(x);
    return __uint_as_float(r);
}
__device__ __forceinline__ uint32_t u(float x) { return __float_as_uint(x); }

#define MMA_TF32(d0,d1,d2,d3,a0,a1,a2,a3,b0,b1)                         \
    asm volatile(                                                        \
        "mma.sync.aligned.m16n8k8.row.col.f32.tf32.tf32.f32 "           \
        "{%0,%1,%2,%3}, {%4,%5,%6,%7}, {%8,%9}, {%0,%1,%2,%3};"         \
        : "+f"(d0), "+f"(d1), "+f"(d2), "+f"(d3)                         \
        : "r"(a0), "r"(a1), "r"(a2), "r"(a3), "r"(b0), "r"(b1))

// -------- TF32 tensor-core GEMM, single-buffered, BK=32 ---------------
// C[M,N] = A[M,K] @ B[K,N], 128x128 tile, 256 threads = 8 warps,
// warp tile 64x32. MODE epilogues:
//  0: plain row-major C
//  1: RoPE -> C row-major ([token][H*HD])
//  2: RoPE + transpose -> C[B,KV,T,HD]
//  3: transpose -> C[B,KV,T,HD]
#define SAS 136

template <int MODE>
__global__ __launch_bounds__(256, 2) void gemm_tf32(
    const float* __restrict__ A, const float* __restrict__ B,
    float* __restrict__ C, int M, int N, int K,
    const float* __restrict__ fcos, const float* __restrict__ fsin) {
    __shared__ float As[32 * SAS];  // [k][m], tf32 bits
    __shared__ float Bs[32 * SAS];  // [k][n], tf32 bits
    int tid = threadIdx.x, lane = tid & 31;
    int w = tid >> 5, wm = w & 1, wn = w >> 1;
    int m0 = wm * 64, n0 = wn * 32;
    int g = lane >> 2, tig = lane & 3;
    int brow = blockIdx.y * 128, bcol = blockIdx.x * 128;

    int arow = tid & 63, akc = (tid >> 6) * 4;      // k cols akc..+3, akc+16..+19
    int bkr = tid >> 5, bc4 = (tid & 31) * 4;       // k rows bkr,+8,+16,+24

    const float* Ap  = A + (size_t)(brow + arow) * K + akc;
    const float* Ap2 = Ap + (size_t)64 * K;
    const float* Bp  = B + (size_t)bkr * N + bcol + bc4;

    float acc[4][4][4];
    #pragma unroll
    for (int mt = 0; mt < 4; mt++)
        #pragma unroll
        for (int nt = 0; nt < 4; nt++)
            #pragma unroll
            for (int i = 0; i < 4; i++) acc[mt][nt][i] = 0.f;

    for (int k0 = 0; k0 < K; k0 += 32) {
        float4 a1 = *(const float4*)(Ap + k0);
        float4 a2 = *(const float4*)(Ap2 + k0);
        float4 a3 = *(const float4*)(Ap + k0 + 16);
        float4 a4 = *(const float4*)(Ap2 + k0 + 16);
        float4 b1 = *(const float4*)(Bp + (size_t)k0 * N);
        float4 b2 = *(const float4*)(Bp + (size_t)(k0 + 8) * N);
        float4 b3 = *(const float4*)(Bp + (size_t)(k0 + 16) * N);
        float4 b4 = *(const float4*)(Bp + (size_t)(k0 + 24) * N);
        __syncthreads();
        As[(akc + 0) * SAS + arow] = tfs(a1.x);
        As[(akc + 1) * SAS + arow] = tfs(a1.y);
        As[(akc + 2) * SAS + arow] = tfs(a1.z);
        As[(akc + 3) * SAS + arow] = tfs(a1.w);
        As[(akc + 0) * SAS + arow + 64] = tfs(a2.x);
        As[(akc + 1) * SAS + arow + 64] = tfs(a2.y);
        As[(akc + 2) * SAS + arow + 64] = tfs(a2.z);
        As[(akc + 3) * SAS + arow + 64] = tfs(a2.w);
        As[(akc + 16) * SAS + arow] = tfs(a3.x);
        As[(akc + 17) * SAS + arow] = tfs(a3.y);
        As[(akc + 18) * SAS + arow] = tfs(a3.z);
        As[(akc + 19) * SAS + arow] = tfs(a3.w);
        As[(akc + 16) * SAS + arow + 64] = tfs(a4.x);
        As[(akc + 17) * SAS + arow + 64] = tfs(a4.y);
        As[(akc + 18) * SAS + arow + 64] = tfs(a4.z);
        As[(akc + 19) * SAS + arow + 64] = tfs(a4.w);
        Bs[bkr * SAS + bc4 + 0] = tfs(b1.x);
        Bs[bkr * SAS + bc4 + 1] = tfs(b1.y);
        Bs[bkr * SAS + bc4 + 2] = tfs(b1.z);
        Bs[bkr * SAS + bc4 + 3] = tfs(b1.w);
        Bs[(bkr + 8) * SAS + bc4 + 0] = tfs(b2.x);
        Bs[(bkr + 8) * SAS + bc4 + 1] = tfs(b2.y);
        Bs[(bkr + 8) * SAS + bc4 + 2] = tfs(b2.z);
        Bs[(bkr + 8) * SAS + bc4 + 3] = tfs(b2.w);
        Bs[(bkr + 16) * SAS + bc4 + 0] = tfs(b3.x);
        Bs[(bkr + 16) * SAS + bc4 + 1] = tfs(b3.y);
        Bs[(bkr + 16) * SAS + bc4 + 2] = tfs(b3.z);
        Bs[(bkr + 16) * SAS + bc4 + 3] = tfs(b3.w);
        Bs[(bkr + 24) * SAS + bc4 + 0] = tfs(b4.x);
        Bs[(bkr + 24) * SAS + bc4 + 1] = tfs(b4.y);
        Bs[(bkr + 24) * SAS + bc4 + 2] = tfs(b4.z);
        Bs[(bkr + 24) * SAS + bc4 + 3] = tfs(b4.w);
        __syncthreads();

        #pragma unroll
        for (int ks = 0; ks < 32; ks += 8) {
            uint32_t af[4][4], bf[4][2];
            #pragma unroll
            for (int mt = 0; mt < 4; mt++) {
                int rm = m0 + mt * 16;
                af[mt][0] = u(As[(ks + tig)     * SAS + rm + g]);
                af[mt][1] = u(As[(ks + tig)     * SAS + rm + g + 8]);
                af[mt][2] = u(As[(ks + tig + 4) * SAS + rm + g]);
                af[mt][3] = u(As[(ks + tig + 4) * SAS + rm + g + 8]);
            }
            #pragma unroll
            for (int nt = 0; nt < 4; nt++) {
                int cn = n0 + nt * 8;
                bf[nt][0] = u(Bs[(ks + tig)     * SAS + cn + g]);
                bf[nt][1] = u(Bs[(ks + tig + 4) * SAS + cn + g]);
            }
            #pragma unroll
            for (int mt = 0; mt < 4; mt++)
                #pragma unroll
                for (int nt = 0; nt < 4; nt++)
                    MMA_TF32(acc[mt][nt][0], acc[mt][nt][1],
                             acc[mt][nt][2], acc[mt][nt][3],
                             af[mt][0], af[mt][1], af[mt][2], af[mt][3],
                             bf[nt][0], bf[nt][1]);
        }
    }

    // -------- epilogue --------
    #pragma unroll
    for (int mt = 0; mt < 4; mt++) {
        int row = brow + m0 + mt * 16 + g;
        int row2 = row + 8;
        #pragma unroll
        for (int nt = 0; nt < 4; nt++) {
            int col = bcol + n0 + nt * 8 + tig * 2;
            float c0 = acc[mt][nt][0], c1 = acc[mt][nt][1];
            float c2 = acc[mt][nt][2], c3 = acc[mt][nt][3];

            if (MODE == 0) {
                *(float2*)&C[(size_t)row  * N + col] = make_float2(c0, c1);
                *(float2*)&C[(size_t)row2 * N + col] = make_float2(c2, c3);
            } else {
                int d = col & (HD - 1);
                if (MODE != 3 && d < RD) {
                    int i = d >> 1;
                    int t1 = row  & (TT - 1);
                    int t2 = row2 & (TT - 1);
                    float cc1 = fcos[t1 * (RD / 2) + i];
                    float ss1 = fsin[t1 * (RD / 2) + i];
                    float cc2 = fcos[t2 * (RD / 2) + i];
                    float ss2 = fsin[t2 * (RD / 2) + i];
                    float r0 = c0 * cc1 - c1 * ss1;
                    float r1 = c0 * ss1 + c1 * cc1;
                    float r2 = c2 * cc2 - c3 * ss2;
                    float r3 = c2 * ss2 + c3 * cc2;
                    c0 = r0; c1 = r1; c2 = r2; c3 = r3;
                }
                if (MODE == 1) {
                    *(float2*)&C[(size_t)row  * N + col] = make_float2(c0, c1);
                    *(float2*)&C[(size_t)row2 * N + col] = make_float2(c2, c3);
                } else {
                    int kv = col >> 7;
                    int b1i = row >> 11, t1 = row & (TT - 1);
                    int b2i = row2 >> 11, t2 = row2 & (TT - 1);
                    size_t dst1 = ((size_t)(b1i * KVH + kv) * TT + t1) * HD + d;
                    size_t dst2 = ((size_t)(b2i * KVH + kv) * TT + t2) * HD + d;
                    *(float2*)&C[dst1] = make_float2(c0, c1);
                    *(float2*)&C[dst2] = make_float2(c2, c3);
                }
            }
        }
    }
}

// ------------- tensor-core causal flash attention ---------------------
// Smem overlay: Q staging [0, 64*132) is consumed into registers before
// the K/V/P region (same bytes) is first written.
#define FST 132
#define KS_OFF 0
#define VS_OFF (32 * FST)
#define PS_OFF (64 * FST)
#define FSMEM_FLOATS (PS_OFF + 4 * 16 * 33)

__global__ __launch_bounds__(128, 3) void flash_mma_kernel(
    const float* __restrict__ Q, const float* __restrict__ K,
    const float* __restrict__ V, float* __restrict__ O) {
    extern __shared__ float fsm[];
    float* Qs = fsm;              // transient staging (overlaps Ks/Vs)
    float* Ks = fsm + KS_OFF;
    float* Vs = fsm + VS_OFF;

    int tid = threadIdx.x, lane = tid & 31, w = tid >> 5;
    int g = lane >> 2, tig = lane & 3;
    int b = blockIdx.z, h = blockIdx.y, q0 = blockIdx.x * 64;
    int kvh = h >> 2;
    const float scale = 0.08838834764831845f;

    {
        int r = tid >> 2, cb = (tid & 3) * 4;
        const float* qg = Q + ((size_t)(b * TT + q0 + r)) * (HH * HD) + h * HD;
        const float* qg2 = qg + (size_t)32 * (HH * HD);
        #pragma unroll
        for (int i = 0; i < 8; i++) {
            float4 v = *(const float4*)(qg + cb + i * 16);
            Qs[r * FST + cb + i * 16 + 0] = tfs(v.x * scale);
            Qs[r * FST + cb + i * 16 + 1] = tfs(v.y * scale);
            Qs[r * FST + cb + i * 16 + 2] = tfs(v.z * scale);
            Qs[r * FST + cb + i * 16 + 3] = tfs(v.w * scale);
            float4 v2 = *(const float4*)(qg2 + cb + i * 16);
            Qs[(r + 32) * FST + cb + i * 16 + 0] = tfs(v2.x * scale);
            Qs[(r + 32) * FST + cb + i * 16 + 1] = tfs(v2.y * scale);
            Qs[(r + 32) * FST + cb + i * 16 + 2] = tfs(v2.z * scale);
            Qs[(r + 32) * FST + cb + i * 16 + 3] = tfs(v2.w * scale);
        }
    }
    __syncthreads();

    uint32_t qf[16][4];
    int qw = w * 16;
    #pragma unroll
    for (int kf = 0; kf < 16; kf++) {
        qf[kf][0] = u(Qs[(qw + g)     * FST + kf * 8 + tig]);
        qf[kf][1] = u(Qs[(qw + g + 8) * FST + kf * 8 + tig]);
        qf[kf][2] = u(Qs[(qw + g)     * FST + kf * 8 + tig + 4]);
        qf[kf][3] = u(Qs[(qw + g + 8) * FST + kf * 8 + tig + 4]);
    }

    float o[16][4];
    #pragma unroll
    for (int df = 0; df < 16; df++)
        o[df][0] = o[df][1] = o[df][2] = o[df][3] = 0.f;
    float m0 = -1e30f, m1 = -1e30f, l0 = 0.f, l1 = 0.f;

    int qglob = q0 + qw;
    int ntiles = q0 / 32 + 2;
    float* Pw = fsm + PS_OFF + w * (16 * 33);

    for (int tile = 0; tile < ntiles; tile++) {
        int kv0 = tile * 32;
        __syncthreads();   // guards Q-staging overlay on iter 0, K/V reuse after
        {
            int r = tid >> 2, cb = (tid & 3) * 4;
            const float* kg = K + ((size_t)(b * KVH + kvh) * TT + kv0 + r) * HD;
            const float* vg = V + ((size_t)(b * KVH + kvh) * TT + kv0 + r) * HD;
            #pragma unroll
            for (int i = 0; i < 8; i++) {
                float4 kv4 = *(const float4*)(kg + cb + i * 16);
                Ks[r * FST + cb + i * 16 + 0] = tfs(kv4.x);
                Ks[r * FST + cb + i * 16 + 1] = tfs(kv4.y);
                Ks[r * FST + cb + i * 16 + 2] = tfs(kv4.z);
                Ks[r * FST + cb + i * 16 + 3] = tfs(kv4.w);
                float4 vv4 = *(const float4*)(vg + cb + i * 16);
                Vs[r * FST + cb + i * 16 + 0] = tfs(vv4.x);
                Vs[r * FST + cb + i * 16 + 1] = tfs(vv4.y);
                Vs[r * FST + cb + i * 16 + 2] = tfs(vv4.z);
                Vs[r * FST + cb + i * 16 + 3] = tfs(vv4.w);
            }
        }
        __syncthreads();

        float s[4][4];
        #pragma unroll
        for (int nf = 0; nf < 4; nf++) {
            s[nf][0] = s[nf][1] = s[nf][2] = s[nf][3] = 0.f;
            const float* kr = &Ks[(nf * 8 + g) * FST];
            #pragma unroll
            for (int kf = 0; kf < 16; kf++) {
                uint32_t b0 = u(kr[kf * 8 + tig]);
                uint32_t b1 = u(kr[kf * 8 + tig + 4]);
                MMA_TF32(s[nf][0], s[nf][1], s[nf][2], s[nf][3],
                         qf[kf][0], qf[kf][1], qf[kf][2], qf[kf][3], b0, b1);
            }
        }

        if (kv0 + 31 > qglob) {
            int r0 = qglob + g, r1 = qglob + g + 8;
            #pragma unroll
            for (int nf = 0; nf < 4; nf++) {
                int c = kv0 + nf * 8 + tig * 2;
                if (c     > r0) s[nf][0] = -1e30f;
                if (c + 1 > r0) s[nf][1] = -1e30f;
                if (c     > r1) s[nf][2] = -1e30f;
                if (c + 1 > r1) s[nf][3] = -1e30f;
            }
        }

        float mx0 = -1e30f, mx1 = -1e30f;
        #pragma unroll
        for (int nf = 0; nf < 4; nf++) {
            mx0 = fmaxf(mx0, fmaxf(s[nf][0], s[nf][1]));
            mx1 = fmaxf(mx1, fmaxf(s[nf][2], s[nf][3]));
        }
        mx0 = fmaxf(mx0, __shfl_xor_sync(0xffffffffu, mx0, 1));
        mx0 = fmaxf(mx0, __shfl_xor_sync(0xffffffffu, mx0, 2));
        mx1 = fmaxf(mx1, __shfl_xor_sync(0xffffffffu, mx1, 1));
        mx1 = fmaxf(mx1, __shfl_xor_sync(0xffffffffu, mx1, 2));
        float mn0 = fmaxf(m0, mx0), mn1 = fmaxf(m1, mx1);
        float sc0 = __expf(m0 - mn0), sc1 = __expf(m1 - mn1);
        m0 = mn0; m1 = mn1;

        float ps0 = 0.f, ps1 = 0.f;
        #pragma unroll
        for (int nf = 0; nf < 4; nf++) {
            float p0 = __expf(s[nf][0] - mn0);
            float p1 = __expf(s[nf][1] - mn0);
            float p2 = __expf(s[nf][2] - mn1);
            float p3 = __expf(s[nf][3] - mn1);
            ps0 += p0 + p1; ps1 += p2 + p3;
            Pw[(g    ) * 33 + nf * 8 + tig * 2    ] = tfs(p0);
            Pw[(g    ) * 33 + nf * 8 + tig * 2 + 1] = tfs(p1);
            Pw[(g + 8) * 33 + nf * 8 + tig * 2    ] = tfs(p2);
            Pw[(g + 8) * 33 + nf * 8 + tig * 2 + 1] = tfs(p3);
        }
        ps0 += __shfl_xor_sync(0xffffffffu, ps0, 1);
        ps0 += __shfl_xor_sync(0xffffffffu, ps0, 2);
        ps1 += __shfl_xor_sync(0xffffffffu, ps1, 1);
        ps1 += __shfl_xor_sync(0xffffffffu, ps1, 2);
        l0 = l0 * sc0 + ps0;
        l1 = l1 * sc1 + ps1;

        #pragma unroll
        for (int df = 0; df < 16; df++) {
            o[df][0] *= sc0; o[df][1] *= sc0;
            o[df][2] *= sc1; o[df][3] *= sc1;
        }
        __syncwarp();

        uint32_t pa[4][4];
        #pragma unroll
        for (int kf = 0; kf < 4; kf++) {
            pa[kf][0] = u(Pw[(g    ) * 33 + kf * 8 + tig]);
            pa[kf][1] = u(Pw[(g + 8) * 33 + kf * 8 + tig]);
            pa[kf][2] = u(Pw[(g    ) * 33 + kf * 8 + tig + 4]);
            pa[kf][3] = u(Pw[(g + 8) * 33 + kf * 8 + tig + 4]);
        }
        __syncwarp();

        #pragma unroll
        for (int df = 0; df < 16; df++) {
            #pragma unroll
            for (int kf = 0; kf < 4; kf++) {
                uint32_t b0 = u(Vs[(kf * 8 + tig)     * FST + df * 8 + g]);
                uint32_t b1 = u(Vs[(kf * 8 + tig + 4) * FST + df * 8 + g]);
                MMA_TF32(o[df][0], o[df][1], o[df][2], o[df][3],
                         pa[kf][0], pa[kf][1], pa[kf][2], pa[kf][3], b0, b1);
            }
        }
    }

    float inv0 = 1.f / l0, inv1 = 1.f / l1;
    float* ob0 = O + ((size_t)(b * TT + qglob + g))     * (HH * HD) + h * HD;
    float* ob1 = O + ((size_t)(b * TT + qglob + g + 8)) * (HH * HD) + h * HD;
    #pragma unroll
    for (int df = 0; df < 16; df++) {
        int col = df * 8 + tig * 2;
        *(float2*)(ob0 + col) = make_float2(o[df][0] * inv0, o[df][1] * inv0);
        *(float2*)(ob1 + col) = make_float2(o[df][2] * inv1, o[df][3] * inv1);
    }
}

// ---------------- launch --------------------------------------------
extern "C" void kernel_launch(void* const* d_in, const int* in_sizes, int n_in,
                              void* d_out, int out_size) {
    const float* x    = (const float*)d_in[0];
    const float* fcos = (const float*)d_in[1];
    const float* fsin = (const float*)d_in[2];
    const float* Wq   = (const float*)d_in[3];
    const float* Wk   = (const float*)d_in[4];
    const float* Wv   = (const float*)d_in[5];
    const float* Wo   = (const float*)d_in[6];

    float* y    = (float*)d_out;
    float* outK = y + (size_t)BB * TT * DD;
    float* outV = outK + (size_t)BB * KVH * TT * HD;

    float *qs, *att;
    cudaGetSymbolAddress((void**)&qs,  g_qs);
    cudaGetSymbolAddress((void**)&att, g_att);

    const int M = BB * TT;  // 4096
    const int FSMEM = FSMEM_FLOATS * 4;
    static int smem_set = 0;
    if (!smem_set) {
        cudaFuncSetAttribute(flash_mma_kernel,
                             cudaFuncAttributeMaxDynamicSharedMemorySize, FSMEM);
        smem_set = 1;
    }

    gemm_tf32<1><<<dim3(DD / 128, M / 128), 256>>>(
        x, Wq, qs, M, HH * HD, DD, fcos, fsin);
    gemm_tf32<2><<<dim3((KVH * HD) / 128, M / 128), 256>>>(
        x, Wk, outK, M, KVH * HD, DD, fcos, fsin);
    gemm_tf32<3><<<dim3((KVH * HD) / 128, M / 128), 256>>>(
        x, Wv, outV, M, KVH * HD, DD, fcos, fsin);

    flash_mma_kernel<<<dim3(TT / 64, HH, BB), 128, FSMEM>>>(qs, outK, outV, att);

    gemm_tf32<0><<<dim3(DD / 128, M / 128), 256>>>(
        att, Wo, y, M, DD, DD, fcos, fsin);
}

// round 6
// speedup vs baseline: 1.3131x; 1.2216x over previous
#include <cuda_runtime.h>
#include <math.h>
#include <stdint.h>

#define BB 2
#define TT 2048
#define DD 2048
#define HH 16
#define KVH 4
#define HD 128
#define RD 64

// ---------------- device scratch (no allocs allowed) ----------------
__device__ float g_qs[4096 * 2048];   // roped Q, [B*T, H*HD]
__device__ float g_att[4096 * 2048];  // attention out, [B*T, H*HD]

__device__ __forceinline__ uint32_t f2tf(float x) {
    uint32_t r;
    asm("cvt.rna.tf32.f32 %0, %1;" : "=r"(r) : "f"(x));
    return r;
}
__device__ __forceinline__ float tfs(float x) {
    uint32_t r = f2tf(x);
    return __uint_as_float(r);
}
__device__ __forceinline__ uint32_t u(float x) { return __float_as_uint(x); }
__device__ __forceinline__ uint32_t ctf(float x) { return f2tf(x); }

#define MMA_TF32(d0,d1,d2,d3,a0,a1,a2,a3,b0,b1)                         \
    asm volatile(                                                        \
        "mma.sync.aligned.m16n8k8.row.col.f32.tf32.tf32.f32 "           \
        "{%0,%1,%2,%3}, {%4,%5,%6,%7}, {%8,%9}, {%0,%1,%2,%3};"         \
        : "+f"(d0), "+f"(d1), "+f"(d2), "+f"(d3)                         \
        : "r"(a0), "r"(a1), "r"(a2), "r"(a3), "r"(b0), "r"(b1))

#define CP_ASYNC16(smem_u32, gptr)                                       \
    asm volatile("cp.async.cg.shared.global [%0], [%1], 16;"             \
                 :: "r"(smem_u32), "l"(gptr))
#define CP_COMMIT() asm volatile("cp.async.commit_group;" ::: "memory")
#define CP_WAIT1()  asm volatile("cp.async.wait_group 1;"  ::: "memory")

// -------- TF32 tensor-core GEMM, cp.async 3-stage pipeline ------------
// C[M,N] = A[M,K] @ B[K,N], 128x128 tile, BK=32, 256 threads = 8 warps,
// warp tile 64x32. A stored [m][k] stride 36, B [k][n] stride 132 (raw
// f32; cvt to tf32 at fragment load). MODE epilogues:
//  0: plain  1: RoPE  2: RoPE+transpose->[B,KV,T,HD]  3: transpose
#define AST 36
#define BST 132
#define A_BYTES (128 * AST * 4)
#define B_BYTES (32 * BST * 4)
#define STAGE_FLOATS (128 * AST + 32 * BST)
#define GSMEM_BYTES (3 * STAGE_FLOATS * 4)

template <int MODE>
__global__ __launch_bounds__(256, 2) void gemm_tf32(
    const float* __restrict__ A, const float* __restrict__ B,
    float* __restrict__ C, int M, int N, int K,
    const float* __restrict__ fcos, const float* __restrict__ fsin) {
    extern __shared__ float gsm[];
    uint32_t smem_u = (uint32_t)__cvta_generic_to_shared(gsm);

    int tid = threadIdx.x, lane = tid & 31;
    int w = tid >> 5, wm = w & 1, wn = w >> 1;
    int m0 = wm * 64, n0 = wn * 32;
    int g = lane >> 2, tig = lane & 3;
    int brow = blockIdx.y * 128, bcol = blockIdx.x * 128;

    // cp.async source coords (per 16B chunk c = tid + i*256)
    int a_row[4], a_kc[4], b_row[4], b_nc[4];
    #pragma unroll
    for (int i = 0; i < 4; i++) {
        int c = tid + i * 256;
        a_row[i] = c >> 3;  a_kc[i] = (c & 7) * 4;
        b_row[i] = c >> 5;  b_nc[i] = (c & 31) * 4;
    }

    float acc[4][4][4];
    #pragma unroll
    for (int mt = 0; mt < 4; mt++)
        #pragma unroll
        for (int nt = 0; nt < 4; nt++)
            #pragma unroll
            for (int i = 0; i < 4; i++) acc[mt][nt][i] = 0.f;

    int nk = K / 32;

    // issue one stage's copies
    auto issue = [&](int kt, int stage) {
        uint32_t sa = smem_u + stage * STAGE_FLOATS * 4;
        uint32_t sb = sa + A_BYTES;
        int k0 = kt * 32;
        #pragma unroll
        for (int i = 0; i < 4; i++) {
            const float* src = A + (size_t)(brow + a_row[i]) * K + k0 + a_kc[i];
            CP_ASYNC16(sa + (a_row[i] * AST + a_kc[i]) * 4, src);
        }
        #pragma unroll
        for (int i = 0; i < 4; i++) {
            const float* src = B + (size_t)(k0 + b_row[i]) * N + bcol + b_nc[i];
            CP_ASYNC16(sb + (b_row[i] * BST + b_nc[i]) * 4, src);
        }
    };

    issue(0, 0); CP_COMMIT();
    issue(1, 1); CP_COMMIT();

    for (int kt = 0; kt < nk; kt++) {
        CP_WAIT1();
        __syncthreads();
        if (kt + 2 < nk) issue(kt + 2, (kt + 2) % 3);
        CP_COMMIT();

        const float* As = gsm + (kt % 3) * STAGE_FLOATS;
        const float* Bs = As + 128 * AST;

        #pragma unroll
        for (int ks = 0; ks < 32; ks += 8) {
            uint32_t af[4][4], bf[4][2];
            #pragma unroll
            for (int mt = 0; mt < 4; mt++) {
                int rm = m0 + mt * 16;
                af[mt][0] = ctf(As[(rm + g)     * AST + ks + tig]);
                af[mt][1] = ctf(As[(rm + g + 8) * AST + ks + tig]);
                af[mt][2] = ctf(As[(rm + g)     * AST + ks + tig + 4]);
                af[mt][3] = ctf(As[(rm + g + 8) * AST + ks + tig + 4]);
            }
            #pragma unroll
            for (int nt = 0; nt < 4; nt++) {
                int cn = n0 + nt * 8;
                bf[nt][0] = ctf(Bs[(ks + tig)     * BST + cn + g]);
                bf[nt][1] = ctf(Bs[(ks + tig + 4) * BST + cn + g]);
            }
            #pragma unroll
            for (int mt = 0; mt < 4; mt++)
                #pragma unroll
                for (int nt = 0; nt < 4; nt++)
                    MMA_TF32(acc[mt][nt][0], acc[mt][nt][1],
                             acc[mt][nt][2], acc[mt][nt][3],
                             af[mt][0], af[mt][1], af[mt][2], af[mt][3],
                             bf[nt][0], bf[nt][1]);
        }
    }

    // -------- epilogue --------
    #pragma unroll
    for (int mt = 0; mt < 4; mt++) {
        int row = brow + m0 + mt * 16 + g;
        int row2 = row + 8;
        #pragma unroll
        for (int nt = 0; nt < 4; nt++) {
            int col = bcol + n0 + nt * 8 + tig * 2;
            float c0 = acc[mt][nt][0], c1 = acc[mt][nt][1];
            float c2 = acc[mt][nt][2], c3 = acc[mt][nt][3];

            if (MODE == 0) {
                *(float2*)&C[(size_t)row  * N + col] = make_float2(c0, c1);
                *(float2*)&C[(size_t)row2 * N + col] = make_float2(c2, c3);
            } else {
                int d = col & (HD - 1);
                if (MODE != 3 && d < RD) {
                    int i = d >> 1;
                    int t1 = row  & (TT - 1);
                    int t2 = row2 & (TT - 1);
                    float cc1 = fcos[t1 * (RD / 2) + i];
                    float ss1 = fsin[t1 * (RD / 2) + i];
                    float cc2 = fcos[t2 * (RD / 2) + i];
                    float ss2 = fsin[t2 * (RD / 2) + i];
                    float r0 = c0 * cc1 - c1 * ss1;
                    float r1 = c0 * ss1 + c1 * cc1;
                    float r2 = c2 * cc2 - c3 * ss2;
                    float r3 = c2 * ss2 + c3 * cc2;
                    c0 = r0; c1 = r1; c2 = r2; c3 = r3;
                }
                if (MODE == 1) {
                    *(float2*)&C[(size_t)row  * N + col] = make_float2(c0, c1);
                    *(float2*)&C[(size_t)row2 * N + col] = make_float2(c2, c3);
                } else {
                    int kv = col >> 7;
                    int b1i = row >> 11, t1 = row & (TT - 1);
                    int b2i = row2 >> 11, t2 = row2 & (TT - 1);
                    size_t dst1 = ((size_t)(b1i * KVH + kv) * TT + t1) * HD + d;
                    size_t dst2 = ((size_t)(b2i * KVH + kv) * TT + t2) * HD + d;
                    *(float2*)&C[dst1] = make_float2(c0, c1);
                    *(float2*)&C[dst2] = make_float2(c2, c3);
                }
            }
        }
    }
}

// ------------- tensor-core causal flash attention (as R5) -------------
#define FST 132
#define KS_OFF 0
#define VS_OFF (32 * FST)
#define PS_OFF (64 * FST)
#define FSMEM_FLOATS (PS_OFF + 4 * 16 * 33)

__global__ __launch_bounds__(128, 3) void flash_mma_kernel(
    const float* __restrict__ Q, const float* __restrict__ K,
    const float* __restrict__ V, float* __restrict__ O) {
    extern __shared__ float fsm[];
    float* Qs = fsm;
    float* Ks = fsm + KS_OFF;
    float* Vs = fsm + VS_OFF;

    int tid = threadIdx.x, lane = tid & 31, w = tid >> 5;
    int g = lane >> 2, tig = lane & 3;
    int b = blockIdx.z, h = blockIdx.y, q0 = blockIdx.x * 64;
    int kvh = h >> 2;
    const float scale = 0.08838834764831845f;

    {
        int r = tid >> 2, cb = (tid & 3) * 4;
        const float* qg = Q + ((size_t)(b * TT + q0 + r)) * (HH * HD) + h * HD;
        const float* qg2 = qg + (size_t)32 * (HH * HD);
        #pragma unroll
        for (int i = 0; i < 8; i++) {
            float4 v = *(const float4*)(qg + cb + i * 16);
            Qs[r * FST + cb + i * 16 + 0] = tfs(v.x * scale);
            Qs[r * FST + cb + i * 16 + 1] = tfs(v.y * scale);
            Qs[r * FST + cb + i * 16 + 2] = tfs(v.z * scale);
            Qs[r * FST + cb + i * 16 + 3] = tfs(v.w * scale);
            float4 v2 = *(const float4*)(qg2 + cb + i * 16);
            Qs[(r + 32) * FST + cb + i * 16 + 0] = tfs(v2.x * scale);
            Qs[(r + 32) * FST + cb + i * 16 + 1] = tfs(v2.y * scale);
            Qs[(r + 32) * FST + cb + i * 16 + 2] = tfs(v2.z * scale);
            Qs[(r + 32) * FST + cb + i * 16 + 3] = tfs(v2.w * scale);
        }
    }
    __syncthreads();

    uint32_t qf[16][4];
    int qw = w * 16;
    #pragma unroll
    for (int kf = 0; kf < 16; kf++) {
        qf[kf][0] = u(Qs[(qw + g)     * FST + kf * 8 + tig]);
        qf[kf][1] = u(Qs[(qw + g + 8) * FST + kf * 8 + tig]);
        qf[kf][2] = u(Qs[(qw + g)     * FST + kf * 8 + tig + 4]);
        qf[kf][3] = u(Qs[(qw + g + 8) * FST + kf * 8 + tig + 4]);
    }

    float o[16][4];
    #pragma unroll
    for (int df = 0; df < 16; df++)
        o[df][0] = o[df][1] = o[df][2] = o[df][3] = 0.f;
    float m0 = -1e30f, m1 = -1e30f, l0 = 0.f, l1 = 0.f;

    int qglob = q0 + qw;
    int ntiles = q0 / 32 + 2;
    float* Pw = fsm + PS_OFF + w * (16 * 33);

    for (int tile = 0; tile < ntiles; tile++) {
        int kv0 = tile * 32;
        __syncthreads();
        {
            int r = tid >> 2, cb = (tid & 3) * 4;
            const float* kg = K + ((size_t)(b * KVH + kvh) * TT + kv0 + r) * HD;
            const float* vg = V + ((size_t)(b * KVH + kvh) * TT + kv0 + r) * HD;
            #pragma unroll
            for (int i = 0; i < 8; i++) {
                float4 kv4 = *(const float4*)(kg + cb + i * 16);
                Ks[r * FST + cb + i * 16 + 0] = tfs(kv4.x);
                Ks[r * FST + cb + i * 16 + 1] = tfs(kv4.y);
                Ks[r * FST + cb + i * 16 + 2] = tfs(kv4.z);
                Ks[r * FST + cb + i * 16 + 3] = tfs(kv4.w);
                float4 vv4 = *(const float4*)(vg + cb + i * 16);
                Vs[r * FST + cb + i * 16 + 0] = tfs(vv4.x);
                Vs[r * FST + cb + i * 16 + 1] = tfs(vv4.y);
                Vs[r * FST + cb + i * 16 + 2] = tfs(vv4.z);
                Vs[r * FST + cb + i * 16 + 3] = tfs(vv4.w);
            }
        }
        __syncthreads();

        float s[4][4];
        #pragma unroll
        for (int nf = 0; nf < 4; nf++) {
            s[nf][0] = s[nf][1] = s[nf][2] = s[nf][3] = 0.f;
            const float* kr = &Ks[(nf * 8 + g) * FST];
            #pragma unroll
            for (int kf = 0; kf < 16; kf++) {
                uint32_t b0 = u(kr[kf * 8 + tig]);
                uint32_t b1 = u(kr[kf * 8 + tig + 4]);
                MMA_TF32(s[nf][0], s[nf][1], s[nf][2], s[nf][3],
                         qf[kf][0], qf[kf][1], qf[kf][2], qf[kf][3], b0, b1);
            }
        }

        if (kv0 + 31 > qglob) {
            int r0 = qglob + g, r1 = qglob + g + 8;
            #pragma unroll
            for (int nf = 0; nf < 4; nf++) {
                int c = kv0 + nf * 8 + tig * 2;
                if (c     > r0) s[nf][0] = -1e30f;
                if (c + 1 > r0) s[nf][1] = -1e30f;
                if (c     > r1) s[nf][2] = -1e30f;
                if (c + 1 > r1) s[nf][3] = -1e30f;
            }
        }

        float mx0 = -1e30f, mx1 = -1e30f;
        #pragma unroll
        for (int nf = 0; nf < 4; nf++) {
            mx0 = fmaxf(mx0, fmaxf(s[nf][0], s[nf][1]));
            mx1 = fmaxf(mx1, fmaxf(s[nf][2], s[nf][3]));
        }
        mx0 = fmaxf(mx0, __shfl_xor_sync(0xffffffffu, mx0, 1));
        mx0 = fmaxf(mx0, __shfl_xor_sync(0xffffffffu, mx0, 2));
        mx1 = fmaxf(mx1, __shfl_xor_sync(0xffffffffu, mx1, 1));
        mx1 = fmaxf(mx1, __shfl_xor_sync(0xffffffffu, mx1, 2));
        float mn0 = fmaxf(m0, mx0), mn1 = fmaxf(m1, mx1);
        float sc0 = __expf(m0 - mn0), sc1 = __expf(m1 - mn1);
        m0 = mn0; m1 = mn1;

        float ps0 = 0.f, ps1 = 0.f;
        #pragma unroll
        for (int nf = 0; nf < 4; nf++) {
            float p0 = __expf(s[nf][0] - mn0);
            float p1 = __expf(s[nf][1] - mn0);
            float p2 = __expf(s[nf][2] - mn1);
            float p3 = __expf(s[nf][3] - mn1);
            ps0 += p0 + p1; ps1 += p2 + p3;
            Pw[(g    ) * 33 + nf * 8 + tig * 2    ] = tfs(p0);
            Pw[(g    ) * 33 + nf * 8 + tig * 2 + 1] = tfs(p1);
            Pw[(g + 8) * 33 + nf * 8 + tig * 2    ] = tfs(p2);
            Pw[(g + 8) * 33 + nf * 8 + tig * 2 + 1] = tfs(p3);
        }
        ps0 += __shfl_xor_sync(0xffffffffu, ps0, 1);
        ps0 += __shfl_xor_sync(0xffffffffu, ps0, 2);
        ps1 += __shfl_xor_sync(0xffffffffu, ps1, 1);
        ps1 += __shfl_xor_sync(0xffffffffu, ps1, 2);
        l0 = l0 * sc0 + ps0;
        l1 = l1 * sc1 + ps1;

        #pragma unroll
        for (int df = 0; df < 16; df++) {
            o[df][0] *= sc0; o[df][1] *= sc0;
            o[df][2] *= sc1; o[df][3] *= sc1;
        }
        __syncwarp();

        uint32_t pa[4][4];
        #pragma unroll
        for (int kf = 0; kf < 4; kf++) {
            pa[kf][0] = u(Pw[(g    ) * 33 + kf * 8 + tig]);
            pa[kf][1] = u(Pw[(g + 8) * 33 + kf * 8 + tig]);
            pa[kf][2] = u(Pw[(g    ) * 33 + kf * 8 + tig + 4]);
            pa[kf][3] = u(Pw[(g + 8) * 33 + kf * 8 + tig + 4]);
        }
        __syncwarp();

        #pragma unroll
        for (int df = 0; df < 16; df++) {
            #pragma unroll
            for (int kf = 0; kf < 4; kf++) {
                uint32_t b0 = u(Vs[(kf * 8 + tig)     * FST + df * 8 + g]);
                uint32_t b1 = u(Vs[(kf * 8 + tig + 4) * FST + df * 8 + g]);
                MMA_TF32(o[df][0], o[df][1], o[df][2], o[df][3],
                         pa[kf][0], pa[kf][1], pa[kf][2], pa[kf][3], b0, b1);
            }
        }
    }

    float inv0 = 1.f / l0, inv1 = 1.f / l1;
    float* ob0 = O + ((size_t)(b * TT + qglob + g))     * (HH * HD) + h * HD;
    float* ob1 = O + ((size_t)(b * TT + qglob + g + 8)) * (HH * HD) + h * HD;
    #pragma unroll
    for (int df = 0; df < 16; df++) {
        int col = df * 8 + tig * 2;
        *(float2*)(ob0 + col) = make_float2(o[df][0] * inv0, o[df][1] * inv0);
        *(float2*)(ob1 + col) = make_float2(o[df][2] * inv1, o[df][3] * inv1);
    }
}

// ---------------- launch --------------------------------------------
extern "C" void kernel_launch(void* const* d_in, const int* in_sizes, int n_in,
                              void* d_out, int out_size) {
    const float* x    = (const float*)d_in[0];
    const float* fcos = (const float*)d_in[1];
    const float* fsin = (const float*)d_in[2];
    const float* Wq   = (const float*)d_in[3];
    const float* Wk   = (const float*)d_in[4];
    const float* Wv   = (const float*)d_in[5];
    const float* Wo   = (const float*)d_in[6];

    float* y    = (float*)d_out;
    float* outK = y + (size_t)BB * TT * DD;
    float* outV = outK + (size_t)BB * KVH * TT * HD;

    float *qs, *att;
    cudaGetSymbolAddress((void**)&qs,  g_qs);
    cudaGetSymbolAddress((void**)&att, g_att);

    const int M = BB * TT;  // 4096
    const int FSMEM = FSMEM_FLOATS * 4;
    static int smem_set = 0;
    if (!smem_set) {
        cudaFuncSetAttribute(flash_mma_kernel,
                             cudaFuncAttributeMaxDynamicSharedMemorySize, FSMEM);
        cudaFuncSetAttribute(gemm_tf32<0>,
                             cudaFuncAttributeMaxDynamicSharedMemorySize, GSMEM_BYTES);
        cudaFuncSetAttribute(gemm_tf32<1>,
                             cudaFuncAttributeMaxDynamicSharedMemorySize, GSMEM_BYTES);
        cudaFuncSetAttribute(gemm_tf32<2>,
                             cudaFuncAttributeMaxDynamicSharedMemorySize, GSMEM_BYTES);
        cudaFuncSetAttribute(gemm_tf32<3>,
                             cudaFuncAttributeMaxDynamicSharedMemorySize, GSMEM_BYTES);
        smem_set = 1;
    }

    gemm_tf32<1><<<dim3(DD / 128, M / 128), 256, GSMEM_BYTES>>>(
        x, Wq, qs, M, HH * HD, DD, fcos, fsin);
    gemm_tf32<2><<<dim3((KVH * HD) / 128, M / 128), 256, GSMEM_BYTES>>>(
        x, Wk, outK, M, KVH * HD, DD, fcos, fsin);
    gemm_tf32<3><<<dim3((KVH * HD) / 128, M / 128), 256, GSMEM_BYTES>>>(
        x, Wv, outV, M, KVH * HD, DD, fcos, fsin);

    flash_mma_kernel<<<dim3(TT / 64, HH, BB), 128, FSMEM>>>(qs, outK, outV, att);

    gemm_tf32<0><<<dim3(DD / 128, M / 128), 256, GSMEM_BYTES>>>(
        att, Wo, y, M, DD, DD, fcos, fsin);
}

// round 7
// speedup vs baseline: 1.3557x; 1.0324x over previous
#include <cuda_runtime.h>
#include <math.h>
#include <stdint.h>

#define BB 2
#define TT 2048
#define DD 2048
#define HH 16
#define KVH 4
#define HD 128
#define RD 64

// ---------------- device scratch (no allocs allowed) ----------------
__device__ float g_qs[4096 * 2048];   // roped Q, [B*T, H*HD]
__device__ float g_att[4096 * 2048];  // attention out, [B*T, H*HD]

__device__ __forceinline__ uint32_t f2tf(float x) {
    uint32_t r;
    asm("cvt.rna.tf32.f32 %0, %1;" : "=r"(r) : "f"(x));
    return r;
}
__device__ __forceinline__ uint32_t ctf(float x) { return f2tf(x); }

#define MMA_TF32(d0,d1,d2,d3,a0,a1,a2,a3,b0,b1)                         \
    asm volatile(                                                        \
        "mma.sync.aligned.m16n8k8.row.col.f32.tf32.tf32.f32 "           \
        "{%0,%1,%2,%3}, {%4,%5,%6,%7}, {%8,%9}, {%0,%1,%2,%3};"         \
        : "+f"(d0), "+f"(d1), "+f"(d2), "+f"(d3)                         \
        : "r"(a0), "r"(a1), "r"(a2), "r"(a3), "r"(b0), "r"(b1))

#define CP_ASYNC16(smem_u32, gptr)                                       \
    asm volatile("cp.async.cg.shared.global [%0], [%1], 16;"             \
                 :: "r"(smem_u32), "l"(gptr))
#define CP_COMMIT() asm volatile("cp.async.commit_group;" ::: "memory")
#define CP_WAIT1()  asm volatile("cp.async.wait_group 1;"  ::: "memory")

// -------- TF32 tensor-core GEMM, cp.async 3-stage pipeline ------------
// (unchanged from R6 — it measured 695us for all four GEMMs)
#define AST 36
#define BST 132
#define A_BYTES (128 * AST * 4)
#define STAGE_FLOATS (128 * AST + 32 * BST)
#define GSMEM_BYTES (3 * STAGE_FLOATS * 4)

template <int MODE>
__global__ __launch_bounds__(256, 2) void gemm_tf32(
    const float* __restrict__ A, const float* __restrict__ B,
    float* __restrict__ C, int M, int N, int K,
    const float* __restrict__ fcos, const float* __restrict__ fsin) {
    extern __shared__ float gsm[];
    uint32_t smem_u = (uint32_t)__cvta_generic_to_shared(gsm);

    int tid = threadIdx.x, lane = tid & 31;
    int w = tid >> 5, wm = w & 1, wn = w >> 1;
    int m0 = wm * 64, n0 = wn * 32;
    int g = lane >> 2, tig = lane & 3;
    int brow = blockIdx.y * 128, bcol = blockIdx.x * 128;

    int a_row[4], a_kc[4], b_row[4], b_nc[4];
    #pragma unroll
    for (int i = 0; i < 4; i++) {
        int c = tid + i * 256;
        a_row[i] = c >> 3;  a_kc[i] = (c & 7) * 4;
        b_row[i] = c >> 5;  b_nc[i] = (c & 31) * 4;
    }

    float acc[4][4][4];
    #pragma unroll
    for (int mt = 0; mt < 4; mt++)
        #pragma unroll
        for (int nt = 0; nt < 4; nt++)
            #pragma unroll
            for (int i = 0; i < 4; i++) acc[mt][nt][i] = 0.f;

    int nk = K / 32;

    auto issue = [&](int kt, int stage) {
        uint32_t sa = smem_u + stage * STAGE_FLOATS * 4;
        uint32_t sb = sa + A_BYTES;
        int k0 = kt * 32;
        #pragma unroll
        for (int i = 0; i < 4; i++) {
            const float* src = A + (size_t)(brow + a_row[i]) * K + k0 + a_kc[i];
            CP_ASYNC16(sa + (a_row[i] * AST + a_kc[i]) * 4, src);
        }
        #pragma unroll
        for (int i = 0; i < 4; i++) {
            const float* src = B + (size_t)(k0 + b_row[i]) * N + bcol + b_nc[i];
            CP_ASYNC16(sb + (b_row[i] * BST + b_nc[i]) * 4, src);
        }
    };

    issue(0, 0); CP_COMMIT();
    issue(1, 1); CP_COMMIT();

    for (int kt = 0; kt < nk; kt++) {
        CP_WAIT1();
        __syncthreads();
        if (kt + 2 < nk) issue(kt + 2, (kt + 2) % 3);
        CP_COMMIT();

        const float* As = gsm + (kt % 3) * STAGE_FLOATS;
        const float* Bs = As + 128 * AST;

        #pragma unroll
        for (int ks = 0; ks < 32; ks += 8) {
            uint32_t af[4][4], bf[4][2];
            #pragma unroll
            for (int mt = 0; mt < 4; mt++) {
                int rm = m0 + mt * 16;
                af[mt][0] = ctf(As[(rm + g)     * AST + ks + tig]);
                af[mt][1] = ctf(As[(rm + g + 8) * AST + ks + tig]);
                af[mt][2] = ctf(As[(rm + g)     * AST + ks + tig + 4]);
                af[mt][3] = ctf(As[(rm + g + 8) * AST + ks + tig + 4]);
            }
            #pragma unroll
            for (int nt = 0; nt < 4; nt++) {
                int cn = n0 + nt * 8;
                bf[nt][0] = ctf(Bs[(ks + tig)     * BST + cn + g]);
                bf[nt][1] = ctf(Bs[(ks + tig + 4) * BST + cn + g]);
            }
            #pragma unroll
            for (int mt = 0; mt < 4; mt++)
                #pragma unroll
                for (int nt = 0; nt < 4; nt++)
                    MMA_TF32(acc[mt][nt][0], acc[mt][nt][1],
                             acc[mt][nt][2], acc[mt][nt][3],
                             af[mt][0], af[mt][1], af[mt][2], af[mt][3],
                             bf[nt][0], bf[nt][1]);
        }
    }

    #pragma unroll
    for (int mt = 0; mt < 4; mt++) {
        int row = brow + m0 + mt * 16 + g;
        int row2 = row + 8;
        #pragma unroll
        for (int nt = 0; nt < 4; nt++) {
            int col = bcol + n0 + nt * 8 + tig * 2;
            float c0 = acc[mt][nt][0], c1 = acc[mt][nt][1];
            float c2 = acc[mt][nt][2], c3 = acc[mt][nt][3];

            if (MODE == 0) {
                *(float2*)&C[(size_t)row  * N + col] = make_float2(c0, c1);
                *(float2*)&C[(size_t)row2 * N + col] = make_float2(c2, c3);
            } else {
                int d = col & (HD - 1);
                if (MODE != 3 && d < RD) {
                    int i = d >> 1;
                    int t1 = row  & (TT - 1);
                    int t2 = row2 & (TT - 1);
                    float cc1 = fcos[t1 * (RD / 2) + i];
                    float ss1 = fsin[t1 * (RD / 2) + i];
                    float cc2 = fcos[t2 * (RD / 2) + i];
                    float ss2 = fsin[t2 * (RD / 2) + i];
                    float r0 = c0 * cc1 - c1 * ss1;
                    float r1 = c0 * ss1 + c1 * cc1;
                    float r2 = c2 * cc2 - c3 * ss2;
                    float r3 = c2 * ss2 + c3 * cc2;
                    c0 = r0; c1 = r1; c2 = r2; c3 = r3;
                }
                if (MODE == 1) {
                    *(float2*)&C[(size_t)row  * N + col] = make_float2(c0, c1);
                    *(float2*)&C[(size_t)row2 * N + col] = make_float2(c2, c3);
                } else {
                    int kv = col >> 7;
                    int b1i = row >> 11, t1 = row & (TT - 1);
                    int b2i = row2 >> 11, t2 = row2 & (TT - 1);
                    size_t dst1 = ((size_t)(b1i * KVH + kv) * TT + t1) * HD + d;
                    size_t dst2 = ((size_t)(b2i * KVH + kv) * TT + t2) * HD + d;
                    *(float2*)&C[dst1] = make_float2(c0, c1);
                    *(float2*)&C[dst2] = make_float2(c2, c3);
                }
            }
        }
    }
}

// ------ tensor-core causal flash attention, cp.async double-buffer ----
// grid (T/64, H, B), 128 threads = 4 warps, warp = 16 q-rows, KV tile 32.
// Smem: stage s in [s*8448, s*8448+8448): K [32][132] then V [32][132].
// Q staging overlays stage 0 (consumed into regs before first cp.async).
// P: [4 warps][16*33] at 16896. All data raw f32; cvt.rna at frag load.
#define FST 132
#define STAGE_F (2 * 32 * FST)            // 8448 floats per stage
#define PS_OFF (2 * STAGE_F)              // 16896
#define FSMEM_FLOATS (PS_OFF + 4 * 16 * 33)
#define FSMEM_BYTES (FSMEM_FLOATS * 4)    // 76032

__global__ __launch_bounds__(128, 3) void flash_mma_kernel(
    const float* __restrict__ Q, const float* __restrict__ K,
    const float* __restrict__ V, float* __restrict__ O) {
    extern __shared__ float fsm[];
    uint32_t smem_u = (uint32_t)__cvta_generic_to_shared(fsm);

    int tid = threadIdx.x, lane = tid & 31, w = tid >> 5;
    int g = lane >> 2, tig = lane & 3;
    int b = blockIdx.z, h = blockIdx.y, q0 = blockIdx.x * 64;
    int kvh = h >> 2;
    const float scale = 0.08838834764831845f;  // 1/sqrt(128)

    size_t kvbase = (size_t)(b * KVH + kvh) * TT * HD;
    int ntiles = q0 / 32 + 2;

    // --- Q staging into stage-0 region (raw scaled f32) ---
    {
        int r = tid >> 2, cb = (tid & 3) * 4;
        const float* qg = Q + ((size_t)(b * TT + q0 + r)) * (HH * HD) + h * HD;
        const float* qg2 = qg + (size_t)32 * (HH * HD);
        #pragma unroll
        for (int i = 0; i < 8; i++) {
            float4 v = *(const float4*)(qg + cb + i * 16);
            float4 v2 = *(const float4*)(qg2 + cb + i * 16);
            float* d1 = &fsm[r * FST + cb + i * 16];
            float* d2 = &fsm[(r + 32) * FST + cb + i * 16];
            d1[0] = v.x * scale;  d1[1] = v.y * scale;
            d1[2] = v.z * scale;  d1[3] = v.w * scale;
            d2[0] = v2.x * scale; d2[1] = v2.y * scale;
            d2[2] = v2.z * scale; d2[3] = v2.w * scale;
        }
    }
    __syncthreads();

    uint32_t qf[16][4];
    int qw = w * 16;
    #pragma unroll
    for (int kf = 0; kf < 16; kf++) {
        qf[kf][0] = ctf(fsm[(qw + g)     * FST + kf * 8 + tig]);
        qf[kf][1] = ctf(fsm[(qw + g + 8) * FST + kf * 8 + tig]);
        qf[kf][2] = ctf(fsm[(qw + g)     * FST + kf * 8 + tig + 4]);
        qf[kf][3] = ctf(fsm[(qw + g + 8) * FST + kf * 8 + tig + 4]);
    }
    __syncthreads();  // Q staging fully consumed before cp.async overwrites

    // cp.async issue: 32x128 K + 32x128 V per tile, 16 chunks/thread
    auto issue = [&](int tile, int stage) {
        int kv0 = tile * 32;
        const float* kb = K + kvbase + (size_t)kv0 * HD;
        const float* vb = V + kvbase + (size_t)kv0 * HD;
        uint32_t sk = smem_u + stage * STAGE_F * 4;
        uint32_t sv = sk + 32 * FST * 4;
        #pragma unroll
        for (int i = 0; i < 8; i++) {
            int c = tid + i * 128;
            int row = c >> 5, col = (c & 31) * 4;
            uint32_t soff = (row * FST + col) * 4;
            CP_ASYNC16(sk + soff, kb + row * HD + col);
            CP_ASYNC16(sv + soff, vb + row * HD + col);
        }
    };

    issue(0, 0); CP_COMMIT();
    if (ntiles > 1) issue(1, 1);
    CP_COMMIT();

    float o[16][4];
    #pragma unroll
    for (int df = 0; df < 16; df++)
        o[df][0] = o[df][1] = o[df][2] = o[df][3] = 0.f;
    float m0 = -1e30f, m1 = -1e30f, l0 = 0.f, l1 = 0.f;

    int qglob = q0 + qw;
    float* Pw = fsm + PS_OFF + w * (16 * 33);

    for (int tile = 0; tile < ntiles; tile++) {
        int kv0 = tile * 32;
        const float* Ks = fsm + (tile & 1) * STAGE_F;
        const float* Vs = Ks + 32 * FST;

        CP_WAIT1();
        __syncthreads();

        // --- S = Q K^T ---
        float s[4][4];
        #pragma unroll
        for (int nf = 0; nf < 4; nf++) {
            s[nf][0] = s[nf][1] = s[nf][2] = s[nf][3] = 0.f;
            const float* kr = &Ks[(nf * 8 + g) * FST];
            #pragma unroll
            for (int kf = 0; kf < 16; kf++) {
                uint32_t b0 = ctf(kr[kf * 8 + tig]);
                uint32_t b1 = ctf(kr[kf * 8 + tig + 4]);
                MMA_TF32(s[nf][0], s[nf][1], s[nf][2], s[nf][3],
                         qf[kf][0], qf[kf][1], qf[kf][2], qf[kf][3], b0, b1);
            }
        }

        if (kv0 + 31 > qglob) {
            int r0 = qglob + g, r1 = qglob + g + 8;
            #pragma unroll
            for (int nf = 0; nf < 4; nf++) {
                int c = kv0 + nf * 8 + tig * 2;
                if (c     > r0) s[nf][0] = -1e30f;
                if (c + 1 > r0) s[nf][1] = -1e30f;
                if (c     > r1) s[nf][2] = -1e30f;
                if (c + 1 > r1) s[nf][3] = -1e30f;
            }
        }

        // --- online softmax ---
        float mx0 = -1e30f, mx1 = -1e30f;
        #pragma unroll
        for (int nf = 0; nf < 4; nf++) {
            mx0 = fmaxf(mx0, fmaxf(s[nf][0], s[nf][1]));
            mx1 = fmaxf(mx1, fmaxf(s[nf][2], s[nf][3]));
        }
        mx0 = fmaxf(mx0, __shfl_xor_sync(0xffffffffu, mx0, 1));
        mx0 = fmaxf(mx0, __shfl_xor_sync(0xffffffffu, mx0, 2));
        mx1 = fmaxf(mx1, __shfl_xor_sync(0xffffffffu, mx1, 1));
        mx1 = fmaxf(mx1, __shfl_xor_sync(0xffffffffu, mx1, 2));
        float mn0 = fmaxf(m0, mx0), mn1 = fmaxf(m1, mx1);
        float sc0 = __expf(m0 - mn0), sc1 = __expf(m1 - mn1);
        m0 = mn0; m1 = mn1;

        float ps0 = 0.f, ps1 = 0.f;
        #pragma unroll
        for (int nf = 0; nf < 4; nf++) {
            float p0 = __expf(s[nf][0] - mn0);
            float p1 = __expf(s[nf][1] - mn0);
            float p2 = __expf(s[nf][2] - mn1);
            float p3 = __expf(s[nf][3] - mn1);
            ps0 += p0 + p1; ps1 += p2 + p3;
            Pw[(g    ) * 33 + nf * 8 + tig * 2    ] = p0;
            Pw[(g    ) * 33 + nf * 8 + tig * 2 + 1] = p1;
            Pw[(g + 8) * 33 + nf * 8 + tig * 2    ] = p2;
            Pw[(g + 8) * 33 + nf * 8 + tig * 2 + 1] = p3;
        }
        ps0 += __shfl_xor_sync(0xffffffffu, ps0, 1);
        ps0 += __shfl_xor_sync(0xffffffffu, ps0, 2);
        ps1 += __shfl_xor_sync(0xffffffffu, ps1, 1);
        ps1 += __shfl_xor_sync(0xffffffffu, ps1, 2);
        l0 = l0 * sc0 + ps0;
        l1 = l1 * sc1 + ps1;

        #pragma unroll
        for (int df = 0; df < 16; df++) {
            o[df][0] *= sc0; o[df][1] *= sc0;
            o[df][2] *= sc1; o[df][3] *= sc1;
        }
        __syncwarp();

        uint32_t pa[4][4];
        #pragma unroll
        for (int kf = 0; kf < 4; kf++) {
            pa[kf][0] = ctf(Pw[(g    ) * 33 + kf * 8 + tig]);
            pa[kf][1] = ctf(Pw[(g + 8) * 33 + kf * 8 + tig]);
            pa[kf][2] = ctf(Pw[(g    ) * 33 + kf * 8 + tig + 4]);
            pa[kf][3] = ctf(Pw[(g + 8) * 33 + kf * 8 + tig + 4]);
        }
        __syncwarp();

        // --- O += P @ V ---
        #pragma unroll
        for (int df = 0; df < 16; df++) {
            #pragma unroll
            for (int kf = 0; kf < 4; kf++) {
                uint32_t b0 = ctf(Vs[(kf * 8 + tig)     * FST + df * 8 + g]);
                uint32_t b1 = ctf(Vs[(kf * 8 + tig + 4) * FST + df * 8 + g]);
                MMA_TF32(o[df][0], o[df][1], o[df][2], o[df][3],
                         pa[kf][0], pa[kf][1], pa[kf][2], pa[kf][3], b0, b1);
            }
        }

        __syncthreads();   // all warps done with this stage before re-fill
        if (tile + 2 < ntiles) issue(tile + 2, tile & 1);
        CP_COMMIT();
    }

    float inv0 = 1.f / l0, inv1 = 1.f / l1;
    float* ob0 = O + ((size_t)(b * TT + qglob + g))     * (HH * HD) + h * HD;
    float* ob1 = O + ((size_t)(b * TT + qglob + g + 8)) * (HH * HD) + h * HD;
    #pragma unroll
    for (int df = 0; df < 16; df++) {
        int col = df * 8 + tig * 2;
        *(float2*)(ob0 + col) = make_float2(o[df][0] * inv0, o[df][1] * inv0);
        *(float2*)(ob1 + col) = make_float2(o[df][2] * inv1, o[df][3] * inv1);
    }
}

// ---------------- launch --------------------------------------------
extern "C" void kernel_launch(void* const* d_in, const int* in_sizes, int n_in,
                              void* d_out, int out_size) {
    const float* x    = (const float*)d_in[0];
    const float* fcos = (const float*)d_in[1];
    const float* fsin = (const float*)d_in[2];
    const float* Wq   = (const float*)d_in[3];
    const float* Wk   = (const float*)d_in[4];
    const float* Wv   = (const float*)d_in[5];
    const float* Wo   = (const float*)d_in[6];

    float* y    = (float*)d_out;
    float* outK = y + (size_t)BB * TT * DD;
    float* outV = outK + (size_t)BB * KVH * TT * HD;

    float *qs, *att;
    cudaGetSymbolAddress((void**)&qs,  g_qs);
    cudaGetSymbolAddress((void**)&att, g_att);

    const int M = BB * TT;  // 4096
    static int smem_set = 0;
    if (!smem_set) {
        cudaFuncSetAttribute(flash_mma_kernel,
                             cudaFuncAttributeMaxDynamicSharedMemorySize, FSMEM_BYTES);
        cudaFuncSetAttribute(gemm_tf32<0>,
                             cudaFuncAttributeMaxDynamicSharedMemorySize, GSMEM_BYTES);
        cudaFuncSetAttribute(gemm_tf32<1>,
                             cudaFuncAttributeMaxDynamicSharedMemorySize, GSMEM_BYTES);
        cudaFuncSetAttribute(gemm_tf32<2>,
                             cudaFuncAttributeMaxDynamicSharedMemorySize, GSMEM_BYTES);
        cudaFuncSetAttribute(gemm_tf32<3>,
                             cudaFuncAttributeMaxDynamicSharedMemorySize, GSMEM_BYTES);
        smem_set = 1;
    }

    gemm_tf32<1><<<dim3(DD / 128, M / 128), 256, GSMEM_BYTES>>>(
        x, Wq, qs, M, HH * HD, DD, fcos, fsin);
    gemm_tf32<2><<<dim3((KVH * HD) / 128, M / 128), 256, GSMEM_BYTES>>>(
        x, Wk, outK, M, KVH * HD, DD, fcos, fsin);
    gemm_tf32<3><<<dim3((KVH * HD) / 128, M / 128), 256, GSMEM_BYTES>>>(
        x, Wv, outV, M, KVH * HD, DD, fcos, fsin);

    flash_mma_kernel<<<dim3(TT / 64, HH, BB), 128, FSMEM_BYTES>>>(
        qs, outK, outV, att);

    gemm_tf32<0><<<dim3(DD / 128, M / 128), 256, GSMEM_BYTES>>>(
        att, Wo, y, M, DD, DD, fcos, fsin);
}

// round 8
// speedup vs baseline: 1.4607x; 1.0775x over previous
#include <cuda_runtime.h>
#include <math.h>
#include <stdint.h>

#define BB 2
#define TT 2048
#define DD 2048
#define HH 16
#define KVH 4
#define HD 128
#define RD 64

// ---------------- device scratch (no allocs allowed) ----------------
__device__ float g_qs[4096 * 2048];    // tf32-rounded scaled roped Q
__device__ float g_att[4096 * 2048];   // attention out (tf32-rounded)
__device__ float g_xr[4096 * 2048];    // tf32-rounded x
__device__ float g_wqr[2048 * 2048];   // tf32-rounded Wq
__device__ float g_wkr[2048 * 512];
__device__ float g_wvr[2048 * 512];
__device__ float g_wor[2048 * 2048];
__device__ float g_kr[2 * 4 * 2048 * 128];  // tf32-rounded roped K [B,KV,T,HD]
__device__ float g_vr[2 * 4 * 2048 * 128];  // tf32-rounded V

__device__ __forceinline__ uint32_t f2tf(float x) {
    uint32_t r;
    asm("cvt.rna.tf32.f32 %0, %1;" : "=r"(r) : "f"(x));
    return r;
}
__device__ __forceinline__ float tfs(float x) {
    uint32_t r = f2tf(x);
    return __uint_as_float(r);
}
__device__ __forceinline__ uint32_t u(float x) { return __float_as_uint(x); }

#define MMA_TF32(d0,d1,d2,d3,a0,a1,a2,a3,b0,b1)                         \
    asm volatile(                                                        \
        "mma.sync.aligned.m16n8k8.row.col.f32.tf32.tf32.f32 "           \
        "{%0,%1,%2,%3}, {%4,%5,%6,%7}, {%8,%9}, {%0,%1,%2,%3};"         \
        : "+f"(d0), "+f"(d1), "+f"(d2), "+f"(d3)                         \
        : "r"(a0), "r"(a1), "r"(a2), "r"(a3), "r"(b0), "r"(b1))

#define CP_ASYNC16(smem_u32, gptr)                                       \
    asm volatile("cp.async.cg.shared.global [%0], [%1], 16;"             \
                 :: "r"(smem_u32), "l"(gptr))
#define CP_COMMIT() asm volatile("cp.async.commit_group;" ::: "memory")
#define CP_WAIT1()  asm volatile("cp.async.wait_group 1;"  ::: "memory")

// ---------------- pre-round f32 -> tf32 bits (float4 grid-stride) ----
__global__ void preround_kernel(const float* __restrict__ src,
                                float* __restrict__ dst, int n4) {
    int i = blockIdx.x * blockDim.x + threadIdx.x;
    int stride = gridDim.x * blockDim.x;
    for (; i < n4; i += stride) {
        float4 v = ((const float4*)src)[i];
        float4 r;
        r.x = tfs(v.x); r.y = tfs(v.y); r.z = tfs(v.z); r.w = tfs(v.w);
        ((float4*)dst)[i] = r;
    }
}

// -------- TF32 tensor-core GEMM, cp.async 3-stage pipeline ------------
// A,B must be tf32-pre-rounded. MODE epilogues:
//  0: plain C
//  1: RoPE -> C = tfs(rope * qscale)            (Q path, scratch only)
//  2: RoPE -> C exact fp32 [B,KV,T,HD], C2 = tfs(rope)  (K path)
//  3: transpose -> C exact [B,KV,T,HD], C2 = tfs(val)   (V path)
#define AST 36
#define BST 132
#define A_BYTES (128 * AST * 4)
#define STAGE_FLOATS (128 * AST + 32 * BST)
#define GSMEM_BYTES (3 * STAGE_FLOATS * 4)
#define QSCALE 0.08838834764831845f

template <int MODE>
__global__ __launch_bounds__(256, 2) void gemm_tf32(
    const float* __restrict__ A, const float* __restrict__ B,
    float* __restrict__ C, float* __restrict__ C2, int M, int N, int K,
    const float* __restrict__ fcos, const float* __restrict__ fsin) {
    extern __shared__ float gsm[];
    uint32_t smem_u = (uint32_t)__cvta_generic_to_shared(gsm);

    int tid = threadIdx.x, lane = tid & 31;
    int w = tid >> 5, wm = w & 1, wn = w >> 1;
    int m0 = wm * 64, n0 = wn * 32;
    int g = lane >> 2, tig = lane & 3;
    int brow = blockIdx.y * 128, bcol = blockIdx.x * 128;

    int a_row[4], a_kc[4], b_row[4], b_nc[4];
    #pragma unroll
    for (int i = 0; i < 4; i++) {
        int c = tid + i * 256;
        a_row[i] = c >> 3;  a_kc[i] = (c & 7) * 4;
        b_row[i] = c >> 5;  b_nc[i] = (c & 31) * 4;
    }

    float acc[4][4][4];
    #pragma unroll
    for (int mt = 0; mt < 4; mt++)
        #pragma unroll
        for (int nt = 0; nt < 4; nt++)
            #pragma unroll
            for (int i = 0; i < 4; i++) acc[mt][nt][i] = 0.f;

    int nk = K / 32;

    auto issue = [&](int kt, int stage) {
        uint32_t sa = smem_u + stage * STAGE_FLOATS * 4;
        uint32_t sb = sa + A_BYTES;
        int k0 = kt * 32;
        #pragma unroll
        for (int i = 0; i < 4; i++) {
            const float* src = A + (size_t)(brow + a_row[i]) * K + k0 + a_kc[i];
            CP_ASYNC16(sa + (a_row[i] * AST + a_kc[i]) * 4, src);
        }
        #pragma unroll
        for (int i = 0; i < 4; i++) {
            const float* src = B + (size_t)(k0 + b_row[i]) * N + bcol + b_nc[i];
            CP_ASYNC16(sb + (b_row[i] * BST + b_nc[i]) * 4, src);
        }
    };

    issue(0, 0); CP_COMMIT();
    issue(1, 1); CP_COMMIT();

    for (int kt = 0; kt < nk; kt++) {
        CP_WAIT1();
        __syncthreads();
        if (kt + 2 < nk) issue(kt + 2, (kt + 2) % 3);
        CP_COMMIT();

        const float* As = gsm + (kt % 3) * STAGE_FLOATS;
        const float* Bs = As + 128 * AST;

        #pragma unroll
        for (int ks = 0; ks < 32; ks += 8) {
            uint32_t af[4][4], bf[4][2];
            #pragma unroll
            for (int mt = 0; mt < 4; mt++) {
                int rm = m0 + mt * 16;
                af[mt][0] = u(As[(rm + g)     * AST + ks + tig]);
                af[mt][1] = u(As[(rm + g + 8) * AST + ks + tig]);
                af[mt][2] = u(As[(rm + g)     * AST + ks + tig + 4]);
                af[mt][3] = u(As[(rm + g + 8) * AST + ks + tig + 4]);
            }
            #pragma unroll
            for (int nt = 0; nt < 4; nt++) {
                int cn = n0 + nt * 8;
                bf[nt][0] = u(Bs[(ks + tig)     * BST + cn + g]);
                bf[nt][1] = u(Bs[(ks + tig + 4) * BST + cn + g]);
            }
            #pragma unroll
            for (int mt = 0; mt < 4; mt++)
                #pragma unroll
                for (int nt = 0; nt < 4; nt++)
                    MMA_TF32(acc[mt][nt][0], acc[mt][nt][1],
                             acc[mt][nt][2], acc[mt][nt][3],
                             af[mt][0], af[mt][1], af[mt][2], af[mt][3],
                             bf[nt][0], bf[nt][1]);
        }
    }

    #pragma unroll
    for (int mt = 0; mt < 4; mt++) {
        int row = brow + m0 + mt * 16 + g;
        int row2 = row + 8;
        #pragma unroll
        for (int nt = 0; nt < 4; nt++) {
            int col = bcol + n0 + nt * 8 + tig * 2;
            float c0 = acc[mt][nt][0], c1 = acc[mt][nt][1];
            float c2 = acc[mt][nt][2], c3 = acc[mt][nt][3];

            if (MODE == 0) {
                *(float2*)&C[(size_t)row  * N + col] = make_float2(c0, c1);
                *(float2*)&C[(size_t)row2 * N + col] = make_float2(c2, c3);
            } else {
                int d = col & (HD - 1);
                if (MODE != 3 && d < RD) {
                    int i = d >> 1;
                    int t1 = row  & (TT - 1);
                    int t2 = row2 & (TT - 1);
                    float cc1 = fcos[t1 * (RD / 2) + i];
                    float ss1 = fsin[t1 * (RD / 2) + i];
                    float cc2 = fcos[t2 * (RD / 2) + i];
                    float ss2 = fsin[t2 * (RD / 2) + i];
                    float r0 = c0 * cc1 - c1 * ss1;
                    float r1 = c0 * ss1 + c1 * cc1;
                    float r2 = c2 * cc2 - c3 * ss2;
                    float r3 = c2 * ss2 + c3 * cc2;
                    c0 = r0; c1 = r1; c2 = r2; c3 = r3;
                }
                if (MODE == 1) {
                    *(float2*)&C[(size_t)row  * N + col] =
                        make_float2(tfs(c0 * QSCALE), tfs(c1 * QSCALE));
                    *(float2*)&C[(size_t)row2 * N + col] =
                        make_float2(tfs(c2 * QSCALE), tfs(c3 * QSCALE));
                } else {
                    int kv = col >> 7;
                    int b1i = row >> 11, t1 = row & (TT - 1);
                    int b2i = row2 >> 11, t2 = row2 & (TT - 1);
                    size_t dst1 = ((size_t)(b1i * KVH + kv) * TT + t1) * HD + d;
                    size_t dst2 = ((size_t)(b2i * KVH + kv) * TT + t2) * HD + d;
                    *(float2*)&C[dst1] = make_float2(c0, c1);
                    *(float2*)&C[dst2] = make_float2(c2, c3);
                    *(float2*)&C2[dst1] = make_float2(tfs(c0), tfs(c1));
                    *(float2*)&C2[dst2] = make_float2(tfs(c2), tfs(c3));
                }
            }
        }
    }
}

// ------ tensor-core causal flash attention, cp.async double-buffer ----
// All K/V/Q data tf32-pre-rounded: fragment loads are raw LDS, no cvt.
#define FST 132
#define STAGE_F (2 * 32 * FST)
#define PS_OFF (2 * STAGE_F)
#define FSMEM_FLOATS (PS_OFF + 4 * 16 * 33)
#define FSMEM_BYTES (FSMEM_FLOATS * 4)

__global__ __launch_bounds__(128, 3) void flash_mma_kernel(
    const float* __restrict__ Q, const float* __restrict__ K,
    const float* __restrict__ V, float* __restrict__ O) {
    extern __shared__ float fsm[];
    uint32_t smem_u = (uint32_t)__cvta_generic_to_shared(fsm);

    int tid = threadIdx.x, lane = tid & 31, w = tid >> 5;
    int g = lane >> 2, tig = lane & 3;
    int b = blockIdx.z, h = blockIdx.y;
    int q0 = (gridDim.x - 1 - blockIdx.x) * 64;   // heavy tiles first
    int kvh = h >> 2;

    size_t kvbase = (size_t)(b * KVH + kvh) * TT * HD;
    int ntiles = q0 / 32 + 2;

    // --- Q staging into stage-0 region (already rounded & scaled) ---
    {
        int r = tid >> 2, cb = (tid & 3) * 4;
        const float* qg = Q + ((size_t)(b * TT + q0 + r)) * (HH * HD) + h * HD;
        const float* qg2 = qg + (size_t)32 * (HH * HD);
        #pragma unroll
        for (int i = 0; i < 8; i++) {
            *(float4*)&fsm[r * FST + cb + i * 16] =
                *(const float4*)(qg + cb + i * 16);
            *(float4*)&fsm[(r + 32) * FST + cb + i * 16] =
                *(const float4*)(qg2 + cb + i * 16);
        }
    }
    __syncthreads();

    uint32_t qf[16][4];
    int qw = w * 16;
    #pragma unroll
    for (int kf = 0; kf < 16; kf++) {
        qf[kf][0] = u(fsm[(qw + g)     * FST + kf * 8 + tig]);
        qf[kf][1] = u(fsm[(qw + g + 8) * FST + kf * 8 + tig]);
        qf[kf][2] = u(fsm[(qw + g)     * FST + kf * 8 + tig + 4]);
        qf[kf][3] = u(fsm[(qw + g + 8) * FST + kf * 8 + tig + 4]);
    }
    __syncthreads();  // Q staging consumed before cp.async overwrites

    auto issue = [&](int tile, int stage) {
        int kv0 = tile * 32;
        const float* kb = K + kvbase + (size_t)kv0 * HD;
        const float* vb = V + kvbase + (size_t)kv0 * HD;
        uint32_t sk = smem_u + stage * STAGE_F * 4;
        uint32_t sv = sk + 32 * FST * 4;
        #pragma unroll
        for (int i = 0; i < 8; i++) {
            int c = tid + i * 128;
            int row = c >> 5, col = (c & 31) * 4;
            uint32_t soff = (row * FST + col) * 4;
            CP_ASYNC16(sk + soff, kb + row * HD + col);
            CP_ASYNC16(sv + soff, vb + row * HD + col);
        }
    };

    issue(0, 0); CP_COMMIT();
    if (ntiles > 1) issue(1, 1);
    CP_COMMIT();

    float o[16][4];
    #pragma unroll
    for (int df = 0; df < 16; df++)
        o[df][0] = o[df][1] = o[df][2] = o[df][3] = 0.f;
    float m0 = -1e30f, m1 = -1e30f, l0 = 0.f, l1 = 0.f;

    int qglob = q0 + qw;
    float* Pw = fsm + PS_OFF + w * (16 * 33);

    for (int tile = 0; tile < ntiles; tile++) {
        int kv0 = tile * 32;
        const float* Ks = fsm + (tile & 1) * STAGE_F;
        const float* Vs = Ks + 32 * FST;

        CP_WAIT1();
        __syncthreads();

        float s[4][4];
        #pragma unroll
        for (int nf = 0; nf < 4; nf++) {
            s[nf][0] = s[nf][1] = s[nf][2] = s[nf][3] = 0.f;
            const float* kr = &Ks[(nf * 8 + g) * FST];
            #pragma unroll
            for (int kf = 0; kf < 16; kf++) {
                uint32_t b0 = u(kr[kf * 8 + tig]);
                uint32_t b1 = u(kr[kf * 8 + tig + 4]);
                MMA_TF32(s[nf][0], s[nf][1], s[nf][2], s[nf][3],
                         qf[kf][0], qf[kf][1], qf[kf][2], qf[kf][3], b0, b1);
            }
        }

        if (kv0 + 31 > qglob) {
            int r0 = qglob + g, r1 = qglob + g + 8;
            #pragma unroll
            for (int nf = 0; nf < 4; nf++) {
                int c = kv0 + nf * 8 + tig * 2;
                if (c     > r0) s[nf][0] = -1e30f;
                if (c + 1 > r0) s[nf][1] = -1e30f;
                if (c     > r1) s[nf][2] = -1e30f;
                if (c + 1 > r1) s[nf][3] = -1e30f;
            }
        }

        float mx0 = -1e30f, mx1 = -1e30f;
        #pragma unroll
        for (int nf = 0; nf < 4; nf++) {
            mx0 = fmaxf(mx0, fmaxf(s[nf][0], s[nf][1]));
            mx1 = fmaxf(mx1, fmaxf(s[nf][2], s[nf][3]));
        }
        mx0 = fmaxf(mx0, __shfl_xor_sync(0xffffffffu, mx0, 1));
        mx0 = fmaxf(mx0, __shfl_xor_sync(0xffffffffu, mx0, 2));
        mx1 = fmaxf(mx1, __shfl_xor_sync(0xffffffffu, mx1, 1));
        mx1 = fmaxf(mx1, __shfl_xor_sync(0xffffffffu, mx1, 2));
        float mn0 = fmaxf(m0, mx0), mn1 = fmaxf(m1, mx1);
        float sc0 = __expf(m0 - mn0), sc1 = __expf(m1 - mn1);
        m0 = mn0; m1 = mn1;

        float ps0 = 0.f, ps1 = 0.f;
        #pragma unroll
        for (int nf = 0; nf < 4; nf++) {
            float p0 = __expf(s[nf][0] - mn0);
            float p1 = __expf(s[nf][1] - mn0);
            float p2 = __expf(s[nf][2] - mn1);
            float p3 = __expf(s[nf][3] - mn1);
            ps0 += p0 + p1; ps1 += p2 + p3;
            Pw[(g    ) * 33 + nf * 8 + tig * 2    ] = tfs(p0);
            Pw[(g    ) * 33 + nf * 8 + tig * 2 + 1] = tfs(p1);
            Pw[(g + 8) * 33 + nf * 8 + tig * 2    ] = tfs(p2);
            Pw[(g + 8) * 33 + nf * 8 + tig * 2 + 1] = tfs(p3);
        }
        ps0 += __shfl_xor_sync(0xffffffffu, ps0, 1);
        ps0 += __shfl_xor_sync(0xffffffffu, ps0, 2);
        ps1 += __shfl_xor_sync(0xffffffffu, ps1, 1);
        ps1 += __shfl_xor_sync(0xffffffffu, ps1, 2);
        l0 = l0 * sc0 + ps0;
        l1 = l1 * sc1 + ps1;

        #pragma unroll
        for (int df = 0; df < 16; df++) {
            o[df][0] *= sc0; o[df][1] *= sc0;
            o[df][2] *= sc1; o[df][3] *= sc1;
        }
        __syncwarp();

        uint32_t pa[4][4];
        #pragma unroll
        for (int kf = 0; kf < 4; kf++) {
            pa[kf][0] = u(Pw[(g    ) * 33 + kf * 8 + tig]);
            pa[kf][1] = u(Pw[(g + 8) * 33 + kf * 8 + tig]);
            pa[kf][2] = u(Pw[(g    ) * 33 + kf * 8 + tig + 4]);
            pa[kf][3] = u(Pw[(g + 8) * 33 + kf * 8 + tig + 4]);
        }
        __syncwarp();

        #pragma unroll
        for (int df = 0; df < 16; df++) {
            #pragma unroll
            for (int kf = 0; kf < 4; kf++) {
                uint32_t b0 = u(Vs[(kf * 8 + tig)     * FST + df * 8 + g]);
                uint32_t b1 = u(Vs[(kf * 8 + tig + 4) * FST + df * 8 + g]);
                MMA_TF32(o[df][0], o[df][1], o[df][2], o[df][3],
                         pa[kf][0], pa[kf][1], pa[kf][2], pa[kf][3], b0, b1);
            }
        }

        __syncthreads();
        if (tile + 2 < ntiles) issue(tile + 2, tile & 1);
        CP_COMMIT();
    }

    // epilogue: write tf32-rounded O (next GEMM consumes same bits)
    float inv0 = 1.f / l0, inv1 = 1.f / l1;
    float* ob0 = O + ((size_t)(b * TT + qglob + g))     * (HH * HD) + h * HD;
    float* ob1 = O + ((size_t)(b * TT + qglob + g + 8)) * (HH * HD) + h * HD;
    #pragma unroll
    for (int df = 0; df < 16; df++) {
        int col = df * 8 + tig * 2;
        *(float2*)(ob0 + col) =
            make_float2(tfs(o[df][0] * inv0), tfs(o[df][1] * inv0));
        *(float2*)(ob1 + col) =
            make_float2(tfs(o[df][2] * inv1), tfs(o[df][3] * inv1));
    }
}

// ---------------- launch --------------------------------------------
extern "C" void kernel_launch(void* const* d_in, const int* in_sizes, int n_in,
                              void* d_out, int out_size) {
    const float* x    = (const float*)d_in[0];
    const float* fcos = (const float*)d_in[1];
    const float* fsin = (const float*)d_in[2];
    const float* Wq   = (const float*)d_in[3];
    const float* Wk   = (const float*)d_in[4];
    const float* Wv   = (const float*)d_in[5];
    const float* Wo   = (const float*)d_in[6];

    float* y    = (float*)d_out;
    float* outK = y + (size_t)BB * TT * DD;
    float* outV = outK + (size_t)BB * KVH * TT * HD;

    float *qs, *att, *xr, *wqr, *wkr, *wvr, *wor, *kr, *vr;
    cudaGetSymbolAddress((void**)&qs,  g_qs);
    cudaGetSymbolAddress((void**)&att, g_att);
    cudaGetSymbolAddress((void**)&xr,  g_xr);
    cudaGetSymbolAddress((void**)&wqr, g_wqr);
    cudaGetSymbolAddress((void**)&wkr, g_wkr);
    cudaGetSymbolAddress((void**)&wvr, g_wvr);
    cudaGetSymbolAddress((void**)&wor, g_wor);
    cudaGetSymbolAddress((void**)&kr,  g_kr);
    cudaGetSymbolAddress((void**)&vr,  g_vr);

    const int M = BB * TT;  // 4096
    static int smem_set = 0;
    if (!smem_set) {
        cudaFuncSetAttribute(flash_mma_kernel,
                             cudaFuncAttributeMaxDynamicSharedMemorySize, FSMEM_BYTES);
        cudaFuncSetAttribute(gemm_tf32<0>,
                             cudaFuncAttributeMaxDynamicSharedMemorySize, GSMEM_BYTES);
        cudaFuncSetAttribute(gemm_tf32<1>,
                             cudaFuncAttributeMaxDynamicSharedMemorySize, GSMEM_BYTES);
        cudaFuncSetAttribute(gemm_tf32<2>,
                             cudaFuncAttributeMaxDynamicSharedMemorySize, GSMEM_BYTES);
        cudaFuncSetAttribute(gemm_tf32<3>,
                             cudaFuncAttributeMaxDynamicSharedMemorySize, GSMEM_BYTES);
        smem_set = 1;
    }

    // pre-round inputs (one pass, pure bandwidth)
    preround_kernel<<<2048, 256>>>(x,  xr,  M * DD / 4);
    preround_kernel<<<1024, 256>>>(Wq, wqr, DD * HH * HD / 4);
    preround_kernel<<<512,  256>>>(Wk, wkr, DD * KVH * HD / 4);
    preround_kernel<<<512,  256>>>(Wv, wvr, DD * KVH * HD / 4);
    preround_kernel<<<1024, 256>>>(Wo, wor, HH * HD * DD / 4);

    gemm_tf32<1><<<dim3(DD / 128, M / 128), 256, GSMEM_BYTES>>>(
        xr, wqr, qs, nullptr, M, HH * HD, DD, fcos, fsin);
    gemm_tf32<2><<<dim3((KVH * HD) / 128, M / 128), 256, GSMEM_BYTES>>>(
        xr, wkr, outK, kr, M, KVH * HD, DD, fcos, fsin);
    gemm_tf32<3><<<dim3((KVH * HD) / 128, M / 128), 256, GSMEM_BYTES>>>(
        xr, wvr, outV, vr, M, KVH * HD, DD, fcos, fsin);

    flash_mma_kernel<<<dim3(TT / 64, HH, BB), 128, FSMEM_BYTES>>>(
        qs, kr, vr, att);

    gemm_tf32<0><<<dim3(DD / 128, M / 128), 256, GSMEM_BYTES>>>(
        att, wor, y, nullptr, M, DD, DD, fcos, fsin);
}

// round 9
// speedup vs baseline: 1.5086x; 1.0328x over previous
#include <cuda_runtime.h>
#include <math.h>
#include <stdint.h>

#define BB 2
#define TT 2048
#define DD 2048
#define HH 16
#define KVH 4
#define HD 128
#define RD 64

// ---------------- device scratch (no allocs allowed) ----------------
__device__ float g_qs[4096 * 2048];    // tf32-rounded scaled roped Q
__device__ float g_att[4096 * 2048];   // attention out (tf32-rounded)
__device__ float g_xr[4096 * 2048];    // tf32-rounded x
__device__ float g_wqr[2048 * 2048];
__device__ float g_wkr[2048 * 512];
__device__ float g_wvr[2048 * 512];
__device__ float g_wor[2048 * 2048];
__device__ float g_kr[2 * 4 * 2048 * 128];  // tf32-rounded roped K [B,KV,T,HD]
__device__ float g_vr[2 * 4 * 2048 * 128];  // tf32-rounded V

__device__ __forceinline__ uint32_t f2tf(float x) {
    uint32_t r;
    asm("cvt.rna.tf32.f32 %0, %1;" : "=r"(r) : "f"(x));
    return r;
}
__device__ __forceinline__ float tfs(float x) {
    uint32_t r = f2tf(x);
    return __uint_as_float(r);
}
__device__ __forceinline__ uint32_t u(float x) { return __float_as_uint(x); }

#define MMA_TF32(d0,d1,d2,d3,a0,a1,a2,a3,b0,b1)                         \
    asm volatile(                                                        \
        "mma.sync.aligned.m16n8k8.row.col.f32.tf32.tf32.f32 "           \
        "{%0,%1,%2,%3}, {%4,%5,%6,%7}, {%8,%9}, {%0,%1,%2,%3};"         \
        : "+f"(d0), "+f"(d1), "+f"(d2), "+f"(d3)                         \
        : "r"(a0), "r"(a1), "r"(a2), "r"(a3), "r"(b0), "r"(b1))

#define CP_ASYNC16(smem_u32, gptr)                                       \
    asm volatile("cp.async.cg.shared.global [%0], [%1], 16;"             \
                 :: "r"(smem_u32), "l"(gptr))
#define CP_COMMIT() asm volatile("cp.async.commit_group;" ::: "memory")
#define CP_WAIT1()  asm volatile("cp.async.wait_group 1;"  ::: "memory")

// ------- fused pre-round f32 -> tf32 bits for all 5 input tensors -----
#define S0 (4096 * 2048 / 4)
#define S1 (S0 + 2048 * 2048 / 4)
#define S2 (S1 + 2048 * 512 / 4)
#define S3 (S2 + 2048 * 512 / 4)
#define S4 (S3 + 2048 * 2048 / 4)

__global__ void preround_all(const float* __restrict__ x,  float* __restrict__ xr,
                             const float* __restrict__ wq, float* __restrict__ wqr,
                             const float* __restrict__ wk, float* __restrict__ wkr,
                             const float* __restrict__ wv, float* __restrict__ wvr,
                             const float* __restrict__ wo, float* __restrict__ wor) {
    int i = blockIdx.x * blockDim.x + threadIdx.x;
    int stride = gridDim.x * blockDim.x;
    for (; i < S4; i += stride) {
        const float4* src;
        float4* dst;
        if (i < S0)      { src = (const float4*)x  + i;       dst = (float4*)xr  + i; }
        else if (i < S1) { src = (const float4*)wq + (i - S0); dst = (float4*)wqr + (i - S0); }
        else if (i < S2) { src = (const float4*)wk + (i - S1); dst = (float4*)wkr + (i - S1); }
        else if (i < S3) { src = (const float4*)wv + (i - S2); dst = (float4*)wvr + (i - S2); }
        else             { src = (const float4*)wo + (i - S3); dst = (float4*)wor + (i - S3); }
        float4 v = *src;
        float4 r;
        r.x = tfs(v.x); r.y = tfs(v.y); r.z = tfs(v.z); r.w = tfs(v.w);
        *dst = r;
    }
}

// ---------------- shared GEMM plumbing --------------------------------
#define AST 36
#define BST 132
#define A_BYTES (128 * AST * 4)
#define STAGE_FLOATS (128 * AST + 32 * BST)
#define GSMEM_BYTES (3 * STAGE_FLOATS * 4)
#define QSCALE 0.08838834764831845f

// -------- fused Q/K/V projection GEMM (one launch fills the chip) -----
// grid (24, 32): x<16 -> Q col-block x (N=2048); x<20 -> K col x-16
// (N=512); else V col x-20 (N=512). K=2048, M=4096, 256 thr, occ 2.
__global__ __launch_bounds__(256, 2) void gemm_qkv(
    const float* __restrict__ A,
    const float* __restrict__ Bq, const float* __restrict__ Bk,
    const float* __restrict__ Bv,
    float* __restrict__ Cq, float* __restrict__ Ck, float* __restrict__ Cv,
    float* __restrict__ C2k, float* __restrict__ C2v,
    const float* __restrict__ fcos, const float* __restrict__ fsin) {
    extern __shared__ float gsm[];
    uint32_t smem_u = (uint32_t)__cvta_generic_to_shared(gsm);

    const int K = DD, M = BB * TT;
    int xb = blockIdx.x;
    int path, bcb, N;
    const float* B;
    if (xb < 16)      { path = 0; bcb = xb;      N = HH * HD;  B = Bq; }
    else if (xb < 20) { path = 1; bcb = xb - 16; N = KVH * HD; B = Bk; }
    else              { path = 2; bcb = xb - 20; N = KVH * HD; B = Bv; }

    int tid = threadIdx.x, lane = tid & 31;
    int w = tid >> 5, wm = w & 1, wn = w >> 1;
    int m0 = wm * 64, n0 = wn * 32;
    int g = lane >> 2, tig = lane & 3;
    int brow = blockIdx.y * 128, bcol = bcb * 128;

    int a_row[4], a_kc[4], b_row[4], b_nc[4];
    #pragma unroll
    for (int i = 0; i < 4; i++) {
        int c = tid + i * 256;
        a_row[i] = c >> 3;  a_kc[i] = (c & 7) * 4;
        b_row[i] = c >> 5;  b_nc[i] = (c & 31) * 4;
    }

    float acc[4][4][4];
    #pragma unroll
    for (int mt = 0; mt < 4; mt++)
        #pragma unroll
        for (int nt = 0; nt < 4; nt++)
            #pragma unroll
            for (int i = 0; i < 4; i++) acc[mt][nt][i] = 0.f;

    int nk = K / 32;
    auto issue = [&](int kt, int stage) {
        uint32_t sa = smem_u + stage * STAGE_FLOATS * 4;
        uint32_t sb = sa + A_BYTES;
        int k0 = kt * 32;
        #pragma unroll
        for (int i = 0; i < 4; i++) {
            const float* src = A + (size_t)(brow + a_row[i]) * K + k0 + a_kc[i];
            CP_ASYNC16(sa + (a_row[i] * AST + a_kc[i]) * 4, src);
        }
        #pragma unroll
        for (int i = 0; i < 4; i++) {
            const float* src = B + (size_t)(k0 + b_row[i]) * N + bcol + b_nc[i];
            CP_ASYNC16(sb + (b_row[i] * BST + b_nc[i]) * 4, src);
        }
    };

    issue(0, 0); CP_COMMIT();
    issue(1, 1); CP_COMMIT();

    for (int kt = 0; kt < nk; kt++) {
        CP_WAIT1();
        __syncthreads();
        if (kt + 2 < nk) issue(kt + 2, (kt + 2) % 3);
        CP_COMMIT();

        const float* As = gsm + (kt % 3) * STAGE_FLOATS;
        const float* Bs = As + 128 * AST;

        #pragma unroll
        for (int ks = 0; ks < 32; ks += 8) {
            uint32_t af[4][4], bf[4][2];
            #pragma unroll
            for (int mt = 0; mt < 4; mt++) {
                int rm = m0 + mt * 16;
                af[mt][0] = u(As[(rm + g)     * AST + ks + tig]);
                af[mt][1] = u(As[(rm + g + 8) * AST + ks + tig]);
                af[mt][2] = u(As[(rm + g)     * AST + ks + tig + 4]);
                af[mt][3] = u(As[(rm + g + 8) * AST + ks + tig + 4]);
            }
            #pragma unroll
            for (int nt = 0; nt < 4; nt++) {
                int cn = n0 + nt * 8;
                bf[nt][0] = u(Bs[(ks + tig)     * BST + cn + g]);
                bf[nt][1] = u(Bs[(ks + tig + 4) * BST + cn + g]);
            }
            #pragma unroll
            for (int mt = 0; mt < 4; mt++)
                #pragma unroll
                for (int nt = 0; nt < 4; nt++)
                    MMA_TF32(acc[mt][nt][0], acc[mt][nt][1],
                             acc[mt][nt][2], acc[mt][nt][3],
                             af[mt][0], af[mt][1], af[mt][2], af[mt][3],
                             bf[nt][0], bf[nt][1]);
        }
    }

    #pragma unroll
    for (int mt = 0; mt < 4; mt++) {
        int row = brow + m0 + mt * 16 + g;
        int row2 = row + 8;
        #pragma unroll
        for (int nt = 0; nt < 4; nt++) {
            int col = bcol + n0 + nt * 8 + tig * 2;
            float c0 = acc[mt][nt][0], c1 = acc[mt][nt][1];
            float c2 = acc[mt][nt][2], c3 = acc[mt][nt][3];

            int d = col & (HD - 1);
            if (path != 2 && d < RD) {
                int i = d >> 1;
                int t1 = row  & (TT - 1);
                int t2 = row2 & (TT - 1);
                float cc1 = fcos[t1 * (RD / 2) + i];
                float ss1 = fsin[t1 * (RD / 2) + i];
                float cc2 = fcos[t2 * (RD / 2) + i];
                float ss2 = fsin[t2 * (RD / 2) + i];
                float r0 = c0 * cc1 - c1 * ss1;
                float r1 = c0 * ss1 + c1 * cc1;
                float r2 = c2 * cc2 - c3 * ss2;
                float r3 = c2 * ss2 + c3 * cc2;
                c0 = r0; c1 = r1; c2 = r2; c3 = r3;
            }
            if (path == 0) {
                *(float2*)&Cq[(size_t)row  * (HH * HD) + col] =
                    make_float2(tfs(c0 * QSCALE), tfs(c1 * QSCALE));
                *(float2*)&Cq[(size_t)row2 * (HH * HD) + col] =
                    make_float2(tfs(c2 * QSCALE), tfs(c3 * QSCALE));
            } else {
                float* C  = (path == 1) ? Ck  : Cv;
                float* C2 = (path == 1) ? C2k : C2v;
                int kv = col >> 7;
                int b1i = row >> 11, t1 = row & (TT - 1);
                int b2i = row2 >> 11, t2 = row2 & (TT - 1);
                size_t dst1 = ((size_t)(b1i * KVH + kv) * TT + t1) * HD + d;
                size_t dst2 = ((size_t)(b2i * KVH + kv) * TT + t2) * HD + d;
                *(float2*)&C[dst1] = make_float2(c0, c1);
                *(float2*)&C[dst2] = make_float2(c2, c3);
                *(float2*)&C2[dst1] = make_float2(tfs(c0), tfs(c1));
                *(float2*)&C2[dst2] = make_float2(tfs(c2), tfs(c3));
            }
        }
    }
}

// -------- plain TF32 GEMM for the Wo projection (unchanged R8) --------
__global__ __launch_bounds__(256, 2) void gemm_wo(
    const float* __restrict__ A, const float* __restrict__ B,
    float* __restrict__ C, int M, int N, int K) {
    extern __shared__ float gsm[];
    uint32_t smem_u = (uint32_t)__cvta_generic_to_shared(gsm);

    int tid = threadIdx.x, lane = tid & 31;
    int w = tid >> 5, wm = w & 1, wn = w >> 1;
    int m0 = wm * 64, n0 = wn * 32;
    int g = lane >> 2, tig = lane & 3;
    int brow = blockIdx.y * 128, bcol = blockIdx.x * 128;

    int a_row[4], a_kc[4], b_row[4], b_nc[4];
    #pragma unroll
    for (int i = 0; i < 4; i++) {
        int c = tid + i * 256;
        a_row[i] = c >> 3;  a_kc[i] = (c & 7) * 4;
        b_row[i] = c >> 5;  b_nc[i] = (c & 31) * 4;
    }

    float acc[4][4][4];
    #pragma unroll
    for (int mt = 0; mt < 4; mt++)
        #pragma unroll
        for (int nt = 0; nt < 4; nt++)
            #pragma unroll
            for (int i = 0; i < 4; i++) acc[mt][nt][i] = 0.f;

    int nk = K / 32;
    auto issue = [&](int kt, int stage) {
        uint32_t sa = smem_u + stage * STAGE_FLOATS * 4;
        uint32_t sb = sa + A_BYTES;
        int k0 = kt * 32;
        #pragma unroll
        for (int i = 0; i < 4; i++) {
            const float* src = A + (size_t)(brow + a_row[i]) * K + k0 + a_kc[i];
            CP_ASYNC16(sa + (a_row[i] * AST + a_kc[i]) * 4, src);
        }
        #pragma unroll
        for (int i = 0; i < 4; i++) {
            const float* src = B + (size_t)(k0 + b_row[i]) * N + bcol + b_nc[i];
            CP_ASYNC16(sb + (b_row[i] * BST + b_nc[i]) * 4, src);
        }
    };

    issue(0, 0); CP_COMMIT();
    issue(1, 1); CP_COMMIT();

    for (int kt = 0; kt < nk; kt++) {
        CP_WAIT1();
        __syncthreads();
        if (kt + 2 < nk) issue(kt + 2, (kt + 2) % 3);
        CP_COMMIT();

        const float* As = gsm + (kt % 3) * STAGE_FLOATS;
        const float* Bs = As + 128 * AST;

        #pragma unroll
        for (int ks = 0; ks < 32; ks += 8) {
            uint32_t af[4][4], bf[4][2];
            #pragma unroll
            for (int mt = 0; mt < 4; mt++) {
                int rm = m0 + mt * 16;
                af[mt][0] = u(As[(rm + g)     * AST + ks + tig]);
                af[mt][1] = u(As[(rm + g + 8) * AST + ks + tig]);
                af[mt][2] = u(As[(rm + g)     * AST + ks + tig + 4]);
                af[mt][3] = u(As[(rm + g + 8) * AST + ks + tig + 4]);
            }
            #pragma unroll
            for (int nt = 0; nt < 4; nt++) {
                int cn = n0 + nt * 8;
                bf[nt][0] = u(Bs[(ks + tig)     * BST + cn + g]);
                bf[nt][1] = u(Bs[(ks + tig + 4) * BST + cn + g]);
            }
            #pragma unroll
            for (int mt = 0; mt < 4; mt++)
                #pragma unroll
                for (int nt = 0; nt < 4; nt++)
                    MMA_TF32(acc[mt][nt][0], acc[mt][nt][1],
                             acc[mt][nt][2], acc[mt][nt][3],
                             af[mt][0], af[mt][1], af[mt][2], af[mt][3],
                             bf[nt][0], bf[nt][1]);
        }
    }

    #pragma unroll
    for (int mt = 0; mt < 4; mt++) {
        int row = brow + m0 + mt * 16 + g;
        int row2 = row + 8;
        #pragma unroll
        for (int nt = 0; nt < 4; nt++) {
            int col = bcol + n0 + nt * 8 + tig * 2;
            *(float2*)&C[(size_t)row  * N + col] =
                make_float2(acc[mt][nt][0], acc[mt][nt][1]);
            *(float2*)&C[(size_t)row2 * N + col] =
                make_float2(acc[mt][nt][2], acc[mt][nt][3]);
        }
    }
}

// ------ tensor-core causal flash attention (unchanged R8) --------------
#define FST 132
#define STAGE_F (2 * 32 * FST)
#define PS_OFF (2 * STAGE_F)
#define FSMEM_FLOATS (PS_OFF + 4 * 16 * 33)
#define FSMEM_BYTES (FSMEM_FLOATS * 4)

__global__ __launch_bounds__(128, 3) void flash_mma_kernel(
    const float* __restrict__ Q, const float* __restrict__ K,
    const float* __restrict__ V, float* __restrict__ O) {
    extern __shared__ float fsm[];
    uint32_t smem_u = (uint32_t)__cvta_generic_to_shared(fsm);

    int tid = threadIdx.x, lane = tid & 31, w = tid >> 5;
    int g = lane >> 2, tig = lane & 3;
    int b = blockIdx.z, h = blockIdx.y;
    int q0 = (gridDim.x - 1 - blockIdx.x) * 64;   // heavy tiles first
    int kvh = h >> 2;

    size_t kvbase = (size_t)(b * KVH + kvh) * TT * HD;
    int ntiles = q0 / 32 + 2;

    {
        int r = tid >> 2, cb = (tid & 3) * 4;
        const float* qg = Q + ((size_t)(b * TT + q0 + r)) * (HH * HD) + h * HD;
        const float* qg2 = qg + (size_t)32 * (HH * HD);
        #pragma unroll
        for (int i = 0; i < 8; i++) {
            *(float4*)&fsm[r * FST + cb + i * 16] =
                *(const float4*)(qg + cb + i * 16);
            *(float4*)&fsm[(r + 32) * FST + cb + i * 16] =
                *(const float4*)(qg2 + cb + i * 16);
        }
    }
    __syncthreads();

    uint32_t qf[16][4];
    int qw = w * 16;
    #pragma unroll
    for (int kf = 0; kf < 16; kf++) {
        qf[kf][0] = u(fsm[(qw + g)     * FST + kf * 8 + tig]);
        qf[kf][1] = u(fsm[(qw + g + 8) * FST + kf * 8 + tig]);
        qf[kf][2] = u(fsm[(qw + g)     * FST + kf * 8 + tig + 4]);
        qf[kf][3] = u(fsm[(qw + g + 8) * FST + kf * 8 + tig + 4]);
    }
    __syncthreads();

    auto issue = [&](int tile, int stage) {
        int kv0 = tile * 32;
        const float* kb = K + kvbase + (size_t)kv0 * HD;
        const float* vb = V + kvbase + (size_t)kv0 * HD;
        uint32_t sk = smem_u + stage * STAGE_F * 4;
        uint32_t sv = sk + 32 * FST * 4;
        #pragma unroll
        for (int i = 0; i < 8; i++) {
            int c = tid + i * 128;
            int row = c >> 5, col = (c & 31) * 4;
            uint32_t soff = (row * FST + col) * 4;
            CP_ASYNC16(sk + soff, kb + row * HD + col);
            CP_ASYNC16(sv + soff, vb + row * HD + col);
        }
    };

    issue(0, 0); CP_COMMIT();
    if (ntiles > 1) issue(1, 1);
    CP_COMMIT();

    float o[16][4];
    #pragma unroll
    for (int df = 0; df < 16; df++)
        o[df][0] = o[df][1] = o[df][2] = o[df][3] = 0.f;
    float m0 = -1e30f, m1 = -1e30f, l0 = 0.f, l1 = 0.f;

    int qglob = q0 + qw;
    float* Pw = fsm + PS_OFF + w * (16 * 33);

    for (int tile = 0; tile < ntiles; tile++) {
        int kv0 = tile * 32;
        const float* Ks = fsm + (tile & 1) * STAGE_F;
        const float* Vs = Ks + 32 * FST;

        CP_WAIT1();
        __syncthreads();

        float s[4][4];
        #pragma unroll
        for (int nf = 0; nf < 4; nf++) {
            s[nf][0] = s[nf][1] = s[nf][2] = s[nf][3] = 0.f;
            const float* kr = &Ks[(nf * 8 + g) * FST];
            #pragma unroll
            for (int kf = 0; kf < 16; kf++) {
                uint32_t b0 = u(kr[kf * 8 + tig]);
                uint32_t b1 = u(kr[kf * 8 + tig + 4]);
                MMA_TF32(s[nf][0], s[nf][1], s[nf][2], s[nf][3],
                         qf[kf][0], qf[kf][1], qf[kf][2], qf[kf][3], b0, b1);
            }
        }

        if (kv0 + 31 > qglob) {
            int r0 = qglob + g, r1 = qglob + g + 8;
            #pragma unroll
            for (int nf = 0; nf < 4; nf++) {
                int c = kv0 + nf * 8 + tig * 2;
                if (c     > r0) s[nf][0] = -1e30f;
                if (c + 1 > r0) s[nf][1] = -1e30f;
                if (c     > r1) s[nf][2] = -1e30f;
                if (c + 1 > r1) s[nf][3] = -1e30f;
            }
        }

        float mx0 = -1e30f, mx1 = -1e30f;
        #pragma unroll
        for (int nf = 0; nf < 4; nf++) {
            mx0 = fmaxf(mx0, fmaxf(s[nf][0], s[nf][1]));
            mx1 = fmaxf(mx1, fmaxf(s[nf][2], s[nf][3]));
        }
        mx0 = fmaxf(mx0, __shfl_xor_sync(0xffffffffu, mx0, 1));
        mx0 = fmaxf(mx0, __shfl_xor_sync(0xffffffffu, mx0, 2));
        mx1 = fmaxf(mx1, __shfl_xor_sync(0xffffffffu, mx1, 1));
        mx1 = fmaxf(mx1, __shfl_xor_sync(0xffffffffu, mx1, 2));
        float mn0 = fmaxf(m0, mx0), mn1 = fmaxf(m1, mx1);
        float sc0 = __expf(m0 - mn0), sc1 = __expf(m1 - mn1);
        m0 = mn0; m1 = mn1;

        float ps0 = 0.f, ps1 = 0.f;
        #pragma unroll
        for (int nf = 0; nf < 4; nf++) {
            float p0 = __expf(s[nf][0] - mn0);
            float p1 = __expf(s[nf][1] - mn0);
            float p2 = __expf(s[nf][2] - mn1);
            float p3 = __expf(s[nf][3] - mn1);
            ps0 += p0 + p1; ps1 += p2 + p3;
            Pw[(g    ) * 33 + nf * 8 + tig * 2    ] = tfs(p0);
            Pw[(g    ) * 33 + nf * 8 + tig * 2 + 1] = tfs(p1);
            Pw[(g + 8) * 33 + nf * 8 + tig * 2    ] = tfs(p2);
            Pw[(g + 8) * 33 + nf * 8 + tig * 2 + 1] = tfs(p3);
        }
        ps0 += __shfl_xor_sync(0xffffffffu, ps0, 1);
        ps0 += __shfl_xor_sync(0xffffffffu, ps0, 2);
        ps1 += __shfl_xor_sync(0xffffffffu, ps1, 1);
        ps1 += __shfl_xor_sync(0xffffffffu, ps1, 2);
        l0 = l0 * sc0 + ps0;
        l1 = l1 * sc1 + ps1;

        #pragma unroll
        for (int df = 0; df < 16; df++) {
            o[df][0] *= sc0; o[df][1] *= sc0;
            o[df][2] *= sc1; o[df][3] *= sc1;
        }
        __syncwarp();

        uint32_t pa[4][4];
        #pragma unroll
        for (int kf = 0; kf < 4; kf++) {
            pa[kf][0] = u(Pw[(g    ) * 33 + kf * 8 + tig]);
            pa[kf][1] = u(Pw[(g + 8) * 33 + kf * 8 + tig]);
            pa[kf][2] = u(Pw[(g    ) * 33 + kf * 8 + tig + 4]);
            pa[kf][3] = u(Pw[(g + 8) * 33 + kf * 8 + tig + 4]);
        }
        __syncwarp();

        #pragma unroll
        for (int df = 0; df < 16; df++) {
            #pragma unroll
            for (int kf = 0; kf < 4; kf++) {
                uint32_t b0 = u(Vs[(kf * 8 + tig)     * FST + df * 8 + g]);
                uint32_t b1 = u(Vs[(kf * 8 + tig + 4) * FST + df * 8 + g]);
                MMA_TF32(o[df][0], o[df][1], o[df][2], o[df][3],
                         pa[kf][0], pa[kf][1], pa[kf][2], pa[kf][3], b0, b1);
            }
        }

        __syncthreads();
        if (tile + 2 < ntiles) issue(tile + 2, tile & 1);
        CP_COMMIT();
    }

    float inv0 = 1.f / l0, inv1 = 1.f / l1;
    float* ob0 = O + ((size_t)(b * TT + qglob + g))     * (HH * HD) + h * HD;
    float* ob1 = O + ((size_t)(b * TT + qglob + g + 8)) * (HH * HD) + h * HD;
    #pragma unroll
    for (int df = 0; df < 16; df++) {
        int col = df * 8 + tig * 2;
        *(float2*)(ob0 + col) =
            make_float2(tfs(o[df][0] * inv0), tfs(o[df][1] * inv0));
        *(float2*)(ob1 + col) =
            make_float2(tfs(o[df][2] * inv1), tfs(o[df][3] * inv1));
    }
}

// ---------------- launch --------------------------------------------
extern "C" void kernel_launch(void* const* d_in, const int* in_sizes, int n_in,
                              void* d_out, int out_size) {
    const float* x    = (const float*)d_in[0];
    const float* fcos = (const float*)d_in[1];
    const float* fsin = (const float*)d_in[2];
    const float* Wq   = (const float*)d_in[3];
    const float* Wk   = (const float*)d_in[4];
    const float* Wv   = (const float*)d_in[5];
    const float* Wo   = (const float*)d_in[6];

    float* y    = (float*)d_out;
    float* outK = y + (size_t)BB * TT * DD;
    float* outV = outK + (size_t)BB * KVH * TT * HD;

    float *qs, *att, *xr, *wqr, *wkr, *wvr, *wor, *kr, *vr;
    cudaGetSymbolAddress((void**)&qs,  g_qs);
    cudaGetSymbolAddress((void**)&att, g_att);
    cudaGetSymbolAddress((void**)&xr,  g_xr);
    cudaGetSymbolAddress((void**)&wqr, g_wqr);
    cudaGetSymbolAddress((void**)&wkr, g_wkr);
    cudaGetSymbolAddress((void**)&wvr, g_wvr);
    cudaGetSymbolAddress((void**)&wor, g_wor);
    cudaGetSymbolAddress((void**)&kr,  g_kr);
    cudaGetSymbolAddress((void**)&vr,  g_vr);

    const int M = BB * TT;  // 4096
    static int smem_set = 0;
    if (!smem_set) {
        cudaFuncSetAttribute(flash_mma_kernel,
                             cudaFuncAttributeMaxDynamicSharedMemorySize, FSMEM_BYTES);
        cudaFuncSetAttribute(gemm_qkv,
                             cudaFuncAttributeMaxDynamicSharedMemorySize, GSMEM_BYTES);
        cudaFuncSetAttribute(gemm_wo,
                             cudaFuncAttributeMaxDynamicSharedMemorySize, GSMEM_BYTES);
        smem_set = 1;
    }

    preround_all<<<2048, 256>>>(x, xr, Wq, wqr, Wk, wkr, Wv, wvr, Wo, wor);

    gemm_qkv<<<dim3(24, M / 128), 256, GSMEM_BYTES>>>(
        xr, wqr, wkr, wvr, qs, outK, outV, kr, vr, fcos, fsin);

    flash_mma_kernel<<<dim3(TT / 64, HH, BB), 128, FSMEM_BYTES>>>(
        qs, kr, vr, att);

    gemm_wo<<<dim3(DD / 128, M / 128), 256, GSMEM_BYTES>>>(
        att, wor, y, M, DD, DD);
}

// round 10
// speedup vs baseline: 1.6185x; 1.0729x over previous
#include <cuda_runtime.h>
#include <math.h>
#include <stdint.h>

#define BB 2
#define TT 2048
#define DD 2048
#define HH 16
#define KVH 4
#define HD 128
#define RD 64

// ---------------- device scratch (no allocs allowed) ----------------
__device__ float g_qs[4096 * 2048];    // tf32-rounded scaled roped Q
__device__ float g_att[4096 * 2048];   // attention out (tf32-rounded)
__device__ float g_xr[4096 * 2048];    // tf32-rounded x
__device__ float g_wqr[2048 * 2048];
__device__ float g_wkr[2048 * 512];
__device__ float g_wvr[2048 * 512];
__device__ float g_wor[2048 * 2048];
__device__ float g_kr[2 * 4 * 2048 * 128];  // perm-tiled tf32 roped K
__device__ float g_vr[2 * 4 * 2048 * 128];  // perm-tiled tf32 V

__device__ __forceinline__ uint32_t f2tf(float x) {
    uint32_t r;
    asm("cvt.rna.tf32.f32 %0, %1;" : "=r"(r) : "f"(x));
    return r;
}
__device__ __forceinline__ float tfs(float x) {
    uint32_t r = f2tf(x);
    return __uint_as_float(r);
}
__device__ __forceinline__ uint32_t u(float x) { return __float_as_uint(x); }

// fragment-permuted tile index maps (32 kv-rows x 128 d), tile = 4096 floats
// K consumed as B-frag of QK^T:  thread(g,tig) reads K[n=nb*8+g][k]
__device__ __forceinline__ int kperm(int kvl, int d) {
    return (((d >> 4) << 2) + (kvl >> 3)) * 128
         + ((((kvl & 7) << 2) + (d & 3)) << 2)
         + (((d >> 3) & 1) << 1) + ((d >> 2) & 1);
}
// V consumed as B-frag of P@V:  thread(g,tig) reads V[kv=kf*8+tig(+4)][d=df*8+g]
__device__ __forceinline__ int vperm(int kvl, int d) {
    return (((kvl >> 3) << 3) + (d >> 4)) * 128
         + ((((d & 7) << 2) + (kvl & 3)) << 2)
         + (((d >> 3) & 1) << 1) + ((kvl >> 2) & 1);
}

#define MMA_TF32(d0,d1,d2,d3,a0,a1,a2,a3,b0,b1)                         \
    asm volatile(                                                        \
        "mma.sync.aligned.m16n8k8.row.col.f32.tf32.tf32.f32 "           \
        "{%0,%1,%2,%3}, {%4,%5,%6,%7}, {%8,%9}, {%0,%1,%2,%3};"         \
        : "+f"(d0), "+f"(d1), "+f"(d2), "+f"(d3)                         \
        : "r"(a0), "r"(a1), "r"(a2), "r"(a3), "r"(b0), "r"(b1))

#define CP_ASYNC16(smem_u32, gptr)                                       \
    asm volatile("cp.async.cg.shared.global [%0], [%1], 16;"             \
                 :: "r"(smem_u32), "l"(gptr))
#define CP_COMMIT() asm volatile("cp.async.commit_group;" ::: "memory")
#define CP_WAIT1()  asm volatile("cp.async.wait_group 1;"  ::: "memory")

// ------- fused pre-round f32 -> tf32 bits for all 5 input tensors -----
#define S0 (4096 * 2048 / 4)
#define S1 (S0 + 2048 * 2048 / 4)
#define S2 (S1 + 2048 * 512 / 4)
#define S3 (S2 + 2048 * 512 / 4)
#define S4 (S3 + 2048 * 2048 / 4)

__global__ void preround_all(const float* __restrict__ x,  float* __restrict__ xr,
                             const float* __restrict__ wq, float* __restrict__ wqr,
                             const float* __restrict__ wk, float* __restrict__ wkr,
                             const float* __restrict__ wv, float* __restrict__ wvr,
                             const float* __restrict__ wo, float* __restrict__ wor) {
    int i = blockIdx.x * blockDim.x + threadIdx.x;
    int stride = gridDim.x * blockDim.x;
    for (; i < S4; i += stride) {
        const float4* src;
        float4* dst;
        if (i < S0)      { src = (const float4*)x  + i;       dst = (float4*)xr  + i; }
        else if (i < S1) { src = (const float4*)wq + (i - S0); dst = (float4*)wqr + (i - S0); }
        else if (i < S2) { src = (const float4*)wk + (i - S1); dst = (float4*)wkr + (i - S1); }
        else if (i < S3) { src = (const float4*)wv + (i - S2); dst = (float4*)wvr + (i - S2); }
        else             { src = (const float4*)wo + (i - S3); dst = (float4*)wor + (i - S3); }
        float4 v = *src;
        float4 r;
        r.x = tfs(v.x); r.y = tfs(v.y); r.z = tfs(v.z); r.w = tfs(v.w);
        *dst = r;
    }
}

// ---------------- shared GEMM plumbing --------------------------------
#define AST 36
#define BST 132
#define A_BYTES (128 * AST * 4)
#define STAGE_FLOATS (128 * AST + 32 * BST)
#define GSMEM_BYTES (3 * STAGE_FLOATS * 4)
#define QSCALE 0.08838834764831845f

// -------- fused Q/K/V projection GEMM (one launch fills the chip) -----
__global__ __launch_bounds__(256, 2) void gemm_qkv(
    const float* __restrict__ A,
    const float* __restrict__ Bq, const float* __restrict__ Bk,
    const float* __restrict__ Bv,
    float* __restrict__ Cq, float* __restrict__ Ck, float* __restrict__ Cv,
    float* __restrict__ C2k, float* __restrict__ C2v,
    const float* __restrict__ fcos, const float* __restrict__ fsin) {
    extern __shared__ float gsm[];
    uint32_t smem_u = (uint32_t)__cvta_generic_to_shared(gsm);

    const int K = DD;
    int xb = blockIdx.x;
    int path, bcb, N;
    const float* B;
    if (xb < 16)      { path = 0; bcb = xb;      N = HH * HD;  B = Bq; }
    else if (xb < 20) { path = 1; bcb = xb - 16; N = KVH * HD; B = Bk; }
    else              { path = 2; bcb = xb - 20; N = KVH * HD; B = Bv; }

    int tid = threadIdx.x, lane = tid & 31;
    int w = tid >> 5, wm = w & 1, wn = w >> 1;
    int m0 = wm * 64, n0 = wn * 32;
    int g = lane >> 2, tig = lane & 3;
    int brow = blockIdx.y * 128, bcol = bcb * 128;

    int a_row[4], a_kc[4], b_row[4], b_nc[4];
    #pragma unroll
    for (int i = 0; i < 4; i++) {
        int c = tid + i * 256;
        a_row[i] = c >> 3;  a_kc[i] = (c & 7) * 4;
        b_row[i] = c >> 5;  b_nc[i] = (c & 31) * 4;
    }

    float acc[4][4][4];
    #pragma unroll
    for (int mt = 0; mt < 4; mt++)
        #pragma unroll
        for (int nt = 0; nt < 4; nt++)
            #pragma unroll
            for (int i = 0; i < 4; i++) acc[mt][nt][i] = 0.f;

    int nk = K / 32;
    auto issue = [&](int kt, int stage) {
        uint32_t sa = smem_u + stage * STAGE_FLOATS * 4;
        uint32_t sb = sa + A_BYTES;
        int k0 = kt * 32;
        #pragma unroll
        for (int i = 0; i < 4; i++) {
            const float* src = A + (size_t)(brow + a_row[i]) * K + k0 + a_kc[i];
            CP_ASYNC16(sa + (a_row[i] * AST + a_kc[i]) * 4, src);
        }
        #pragma unroll
        for (int i = 0; i < 4; i++) {
            const float* src = B + (size_t)(k0 + b_row[i]) * N + bcol + b_nc[i];
            CP_ASYNC16(sb + (b_row[i] * BST + b_nc[i]) * 4, src);
        }
    };

    issue(0, 0); CP_COMMIT();
    issue(1, 1); CP_COMMIT();

    for (int kt = 0; kt < nk; kt++) {
        CP_WAIT1();
        __syncthreads();
        if (kt + 2 < nk) issue(kt + 2, (kt + 2) % 3);
        CP_COMMIT();

        const float* As = gsm + (kt % 3) * STAGE_FLOATS;
        const float* Bs = As + 128 * AST;

        #pragma unroll
        for (int ks = 0; ks < 32; ks += 8) {
            uint32_t af[4][4], bf[4][2];
            #pragma unroll
            for (int mt = 0; mt < 4; mt++) {
                int rm = m0 + mt * 16;
                af[mt][0] = u(As[(rm + g)     * AST + ks + tig]);
                af[mt][1] = u(As[(rm + g + 8) * AST + ks + tig]);
                af[mt][2] = u(As[(rm + g)     * AST + ks + tig + 4]);
                af[mt][3] = u(As[(rm + g + 8) * AST + ks + tig + 4]);
            }
            #pragma unroll
            for (int nt = 0; nt < 4; nt++) {
                int cn = n0 + nt * 8;
                bf[nt][0] = u(Bs[(ks + tig)     * BST + cn + g]);
                bf[nt][1] = u(Bs[(ks + tig + 4) * BST + cn + g]);
            }
            #pragma unroll
            for (int mt = 0; mt < 4; mt++)
                #pragma unroll
                for (int nt = 0; nt < 4; nt++)
                    MMA_TF32(acc[mt][nt][0], acc[mt][nt][1],
                             acc[mt][nt][2], acc[mt][nt][3],
                             af[mt][0], af[mt][1], af[mt][2], af[mt][3],
                             bf[nt][0], bf[nt][1]);
        }
    }

    #pragma unroll
    for (int mt = 0; mt < 4; mt++) {
        int row = brow + m0 + mt * 16 + g;
        int row2 = row + 8;
        #pragma unroll
        for (int nt = 0; nt < 4; nt++) {
            int col = bcol + n0 + nt * 8 + tig * 2;
            float c0 = acc[mt][nt][0], c1 = acc[mt][nt][1];
            float c2 = acc[mt][nt][2], c3 = acc[mt][nt][3];

            int d = col & (HD - 1);
            if (path != 2 && d < RD) {
                int i = d >> 1;
                int t1 = row  & (TT - 1);
                int t2 = row2 & (TT - 1);
                float cc1 = fcos[t1 * (RD / 2) + i];
                float ss1 = fsin[t1 * (RD / 2) + i];
                float cc2 = fcos[t2 * (RD / 2) + i];
                float ss2 = fsin[t2 * (RD / 2) + i];
                float r0 = c0 * cc1 - c1 * ss1;
                float r1 = c0 * ss1 + c1 * cc1;
                float r2 = c2 * cc2 - c3 * ss2;
                float r3 = c2 * ss2 + c3 * cc2;
                c0 = r0; c1 = r1; c2 = r2; c3 = r3;
            }
            if (path == 0) {
                *(float2*)&Cq[(size_t)row  * (HH * HD) + col] =
                    make_float2(tfs(c0 * QSCALE), tfs(c1 * QSCALE));
                *(float2*)&Cq[(size_t)row2 * (HH * HD) + col] =
                    make_float2(tfs(c2 * QSCALE), tfs(c3 * QSCALE));
            } else {
                float* C  = (path == 1) ? Ck  : Cv;
                float* C2 = (path == 1) ? C2k : C2v;
                int kv = col >> 7;
                int b1i = row >> 11, t1 = row & (TT - 1);
                int b2i = row2 >> 11, t2 = row2 & (TT - 1);
                int bkv1 = b1i * KVH + kv, bkv2 = b2i * KVH + kv;
                size_t dst1 = ((size_t)bkv1 * TT + t1) * HD + d;
                size_t dst2 = ((size_t)bkv2 * TT + t2) * HD + d;
                *(float2*)&C[dst1] = make_float2(c0, c1);
                *(float2*)&C[dst2] = make_float2(c2, c3);
                // rounded copies in fragment-permuted tile layout
                size_t tb1 = ((size_t)bkv1 * (TT / 32) + (t1 >> 5)) * 4096;
                size_t tb2 = ((size_t)bkv2 * (TT / 32) + (t2 >> 5)) * 4096;
                int kvl1 = t1 & 31, kvl2 = t2 & 31;
                if (path == 1) {
                    C2[tb1 + kperm(kvl1, d)]     = tfs(c0);
                    C2[tb1 + kperm(kvl1, d + 1)] = tfs(c1);
                    C2[tb2 + kperm(kvl2, d)]     = tfs(c2);
                    C2[tb2 + kperm(kvl2, d + 1)] = tfs(c3);
                } else {
                    C2[tb1 + vperm(kvl1, d)]     = tfs(c0);
                    C2[tb1 + vperm(kvl1, d + 1)] = tfs(c1);
                    C2[tb2 + vperm(kvl2, d)]     = tfs(c2);
                    C2[tb2 + vperm(kvl2, d + 1)] = tfs(c3);
                }
            }
        }
    }
}

// -------- plain TF32 GEMM for the Wo projection (unchanged) -----------
__global__ __launch_bounds__(256, 2) void gemm_wo(
    const float* __restrict__ A, const float* __restrict__ B,
    float* __restrict__ C, int M, int N, int K) {
    extern __shared__ float gsm[];
    uint32_t smem_u = (uint32_t)__cvta_generic_to_shared(gsm);

    int tid = threadIdx.x, lane = tid & 31;
    int w = tid >> 5, wm = w & 1, wn = w >> 1;
    int m0 = wm * 64, n0 = wn * 32;
    int g = lane >> 2, tig = lane & 3;
    int brow = blockIdx.y * 128, bcol = blockIdx.x * 128;

    int a_row[4], a_kc[4], b_row[4], b_nc[4];
    #pragma unroll
    for (int i = 0; i < 4; i++) {
        int c = tid + i * 256;
        a_row[i] = c >> 3;  a_kc[i] = (c & 7) * 4;
        b_row[i] = c >> 5;  b_nc[i] = (c & 31) * 4;
    }

    float acc[4][4][4];
    #pragma unroll
    for (int mt = 0; mt < 4; mt++)
        #pragma unroll
        for (int nt = 0; nt < 4; nt++)
            #pragma unroll
            for (int i = 0; i < 4; i++) acc[mt][nt][i] = 0.f;

    int nk = K / 32;
    auto issue = [&](int kt, int stage) {
        uint32_t sa = smem_u + stage * STAGE_FLOATS * 4;
        uint32_t sb = sa + A_BYTES;
        int k0 = kt * 32;
        #pragma unroll
        for (int i = 0; i < 4; i++) {
            const float* src = A + (size_t)(brow + a_row[i]) * K + k0 + a_kc[i];
            CP_ASYNC16(sa + (a_row[i] * AST + a_kc[i]) * 4, src);
        }
        #pragma unroll
        for (int i = 0; i < 4; i++) {
            const float* src = B + (size_t)(k0 + b_row[i]) * N + bcol + b_nc[i];
            CP_ASYNC16(sb + (b_row[i] * BST + b_nc[i]) * 4, src);
        }
    };

    issue(0, 0); CP_COMMIT();
    issue(1, 1); CP_COMMIT();

    for (int kt = 0; kt < nk; kt++) {
        CP_WAIT1();
        __syncthreads();
        if (kt + 2 < nk) issue(kt + 2, (kt + 2) % 3);
        CP_COMMIT();

        const float* As = gsm + (kt % 3) * STAGE_FLOATS;
        const float* Bs = As + 128 * AST;

        #pragma unroll
        for (int ks = 0; ks < 32; ks += 8) {
            uint32_t af[4][4], bf[4][2];
            #pragma unroll
            for (int mt = 0; mt < 4; mt++) {
                int rm = m0 + mt * 16;
                af[mt][0] = u(As[(rm + g)     * AST + ks + tig]);
                af[mt][1] = u(As[(rm + g + 8) * AST + ks + tig]);
                af[mt][2] = u(As[(rm + g)     * AST + ks + tig + 4]);
                af[mt][3] = u(As[(rm + g + 8) * AST + ks + tig + 4]);
            }
            #pragma unroll
            for (int nt = 0; nt < 4; nt++) {
                int cn = n0 + nt * 8;
                bf[nt][0] = u(Bs[(ks + tig)     * BST + cn + g]);
                bf[nt][1] = u(Bs[(ks + tig + 4) * BST + cn + g]);
            }
            #pragma unroll
            for (int mt = 0; mt < 4; mt++)
                #pragma unroll
                for (int nt = 0; nt < 4; nt++)
                    MMA_TF32(acc[mt][nt][0], acc[mt][nt][1],
                             acc[mt][nt][2], acc[mt][nt][3],
                             af[mt][0], af[mt][1], af[mt][2], af[mt][3],
                             bf[nt][0], bf[nt][1]);
        }
    }

    #pragma unroll
    for (int mt = 0; mt < 4; mt++) {
        int row = brow + m0 + mt * 16 + g;
        int row2 = row + 8;
        #pragma unroll
        for (int nt = 0; nt < 4; nt++) {
            int col = bcol + n0 + nt * 8 + tig * 2;
            *(float2*)&C[(size_t)row  * N + col] =
                make_float2(acc[mt][nt][0], acc[mt][nt][1]);
            *(float2*)&C[(size_t)row2 * N + col] =
                make_float2(acc[mt][nt][2], acc[mt][nt][3]);
        }
    }
}

// ------ tensor-core causal flash attention, perm-tiled K/V ------------
// Smem: stage s = [s*8192, s*8192+8192): K tile 4096 | V tile 4096.
// Q staging overlays both stages (consumed to regs before cp.async).
#define FST 132
#define STAGE_F 8192
#define PS_OFF (2 * STAGE_F)
#define FSMEM_FLOATS (PS_OFF + 4 * 16 * 33)
#define FSMEM_BYTES (FSMEM_FLOATS * 4)

__global__ __launch_bounds__(128, 3) void flash_mma_kernel(
    const float* __restrict__ Q, const float* __restrict__ K,
    const float* __restrict__ V, float* __restrict__ O) {
    extern __shared__ float fsm[];
    uint32_t smem_u = (uint32_t)__cvta_generic_to_shared(fsm);

    int tid = threadIdx.x, lane = tid & 31, w = tid >> 5;
    int g = lane >> 2, tig = lane & 3;
    int b = blockIdx.z, h = blockIdx.y;
    int q0 = (gridDim.x - 1 - blockIdx.x) * 64;   // heavy tiles first
    int kvh = h >> 2;

    size_t kvbase = (size_t)(b * KVH + kvh) * (TT / 32) * 4096;
    int ntiles = q0 / 32 + 2;

    // --- Q staging (rounded & scaled already); uses full stage area ---
    {
        int r = tid >> 2, cb = (tid & 3) * 4;
        const float* qg = Q + ((size_t)(b * TT + q0 + r)) * (HH * HD) + h * HD;
        const float* qg2 = qg + (size_t)32 * (HH * HD);
        #pragma unroll
        for (int i = 0; i < 8; i++) {
            *(float4*)&fsm[r * FST + cb + i * 16] =
                *(const float4*)(qg + cb + i * 16);
            *(float4*)&fsm[(r + 32) * FST + cb + i * 16] =
                *(const float4*)(qg2 + cb + i * 16);
        }
    }
    __syncthreads();

    uint32_t qf[16][4];
    int qw = w * 16;
    #pragma unroll
    for (int kf = 0; kf < 16; kf++) {
        qf[kf][0] = u(fsm[(qw + g)     * FST + kf * 8 + tig]);
        qf[kf][1] = u(fsm[(qw + g + 8) * FST + kf * 8 + tig]);
        qf[kf][2] = u(fsm[(qw + g)     * FST + kf * 8 + tig + 4]);
        qf[kf][3] = u(fsm[(qw + g + 8) * FST + kf * 8 + tig + 4]);
    }
    __syncthreads();  // Q staging consumed before cp.async overwrites

    // linear tile copy: 1024 16B-chunks per K tile and per V tile
    auto issue = [&](int tile, int stage) {
        const float* kb = K + kvbase + (size_t)tile * 4096;
        const float* vb = V + kvbase + (size_t)tile * 4096;
        uint32_t sk = smem_u + stage * STAGE_F * 4;
        uint32_t sv = sk + 4096 * 4;
        #pragma unroll
        for (int i = 0; i < 8; i++) {
            int c = tid + i * 128;
            CP_ASYNC16(sk + c * 16, kb + c * 4);
            CP_ASYNC16(sv + c * 16, vb + c * 4);
        }
    };

    issue(0, 0); CP_COMMIT();
    if (ntiles > 1) issue(1, 1);
    CP_COMMIT();

    float o[16][4];
    #pragma unroll
    for (int df = 0; df < 16; df++)
        o[df][0] = o[df][1] = o[df][2] = o[df][3] = 0.f;
    float m0 = -1e30f, m1 = -1e30f, l0 = 0.f, l1 = 0.f;

    int qglob = q0 + qw;
    float* Pw = fsm + PS_OFF + w * (16 * 33);

    for (int tile = 0; tile < ntiles; tile++) {
        int kv0 = tile * 32;
        const float* Ks = fsm + (tile & 1) * STAGE_F;
        const float* Vs = Ks + 4096;

        CP_WAIT1();
        __syncthreads();

        // --- S = Q K^T : vectorized B-frag loads ---
        float s[4][4];
        #pragma unroll
        for (int nf = 0; nf < 4; nf++) {
            s[nf][0] = s[nf][1] = s[nf][2] = s[nf][3] = 0.f;
            #pragma unroll
            for (int kp = 0; kp < 8; kp++) {
                float4 bv = *(const float4*)&Ks[(kp * 4 + nf) * 128 + lane * 4];
                MMA_TF32(s[nf][0], s[nf][1], s[nf][2], s[nf][3],
                         qf[2 * kp][0], qf[2 * kp][1],
                         qf[2 * kp][2], qf[2 * kp][3],
                         u(bv.x), u(bv.y));
                MMA_TF32(s[nf][0], s[nf][1], s[nf][2], s[nf][3],
                         qf[2 * kp + 1][0], qf[2 * kp + 1][1],
                         qf[2 * kp + 1][2], qf[2 * kp + 1][3],
                         u(bv.z), u(bv.w));
            }
        }

        if (kv0 + 31 > qglob) {
            int r0 = qglob + g, r1 = qglob + g + 8;
            #pragma unroll
            for (int nf = 0; nf < 4; nf++) {
                int c = kv0 + nf * 8 + tig * 2;
                if (c     > r0) s[nf][0] = -1e30f;
                if (c + 1 > r0) s[nf][1] = -1e30f;
                if (c     > r1) s[nf][2] = -1e30f;
                if (c + 1 > r1) s[nf][3] = -1e30f;
            }
        }

        float mx0 = -1e30f, mx1 = -1e30f;
        #pragma unroll
        for (int nf = 0; nf < 4; nf++) {
            mx0 = fmaxf(mx0, fmaxf(s[nf][0], s[nf][1]));
            mx1 = fmaxf(mx1, fmaxf(s[nf][2], s[nf][3]));
        }
        mx0 = fmaxf(mx0, __shfl_xor_sync(0xffffffffu, mx0, 1));
        mx0 = fmaxf(mx0, __shfl_xor_sync(0xffffffffu, mx0, 2));
        mx1 = fmaxf(mx1, __shfl_xor_sync(0xffffffffu, mx1, 1));
        mx1 = fmaxf(mx1, __shfl_xor_sync(0xffffffffu, mx1, 2));
        float mn0 = fmaxf(m0, mx0), mn1 = fmaxf(m1, mx1);
        float sc0 = __expf(m0 - mn0), sc1 = __expf(m1 - mn1);
        m0 = mn0; m1 = mn1;

        float ps0 = 0.f, ps1 = 0.f;
        #pragma unroll
        for (int nf = 0; nf < 4; nf++) {
            float p0 = __expf(s[nf][0] - mn0);
            float p1 = __expf(s[nf][1] - mn0);
            float p2 = __expf(s[nf][2] - mn1);
            float p3 = __expf(s[nf][3] - mn1);
            ps0 += p0 + p1; ps1 += p2 + p3;
            Pw[(g    ) * 33 + nf * 8 + tig * 2    ] = tfs(p0);
            Pw[(g    ) * 33 + nf * 8 + tig * 2 + 1] = tfs(p1);
            Pw[(g + 8) * 33 + nf * 8 + tig * 2    ] = tfs(p2);
            Pw[(g + 8) * 33 + nf * 8 + tig * 2 + 1] = tfs(p3);
        }
        ps0 += __shfl_xor_sync(0xffffffffu, ps0, 1);
        ps0 += __shfl_xor_sync(0xffffffffu, ps0, 2);
        ps1 += __shfl_xor_sync(0xffffffffu, ps1, 1);
        ps1 += __shfl_xor_sync(0xffffffffu, ps1, 2);
        l0 = l0 * sc0 + ps0;
        l1 = l1 * sc1 + ps1;

        #pragma unroll
        for (int df = 0; df < 16; df++) {
            o[df][0] *= sc0; o[df][1] *= sc0;
            o[df][2] *= sc1; o[df][3] *= sc1;
        }
        __syncwarp();

        uint32_t pa[4][4];
        #pragma unroll
        for (int kf = 0; kf < 4; kf++) {
            pa[kf][0] = u(Pw[(g    ) * 33 + kf * 8 + tig]);
            pa[kf][1] = u(Pw[(g + 8) * 33 + kf * 8 + tig]);
            pa[kf][2] = u(Pw[(g    ) * 33 + kf * 8 + tig + 4]);
            pa[kf][3] = u(Pw[(g + 8) * 33 + kf * 8 + tig + 4]);
        }
        __syncwarp();

        // --- O += P @ V : vectorized B-frag loads ---
        #pragma unroll
        for (int dfp = 0; dfp < 8; dfp++) {
            #pragma unroll
            for (int kf = 0; kf < 4; kf++) {
                float4 vv = *(const float4*)&Vs[(kf * 8 + dfp) * 128 + lane * 4];
                MMA_TF32(o[2 * dfp][0], o[2 * dfp][1],
                         o[2 * dfp][2], o[2 * dfp][3],
                         pa[kf][0], pa[kf][1], pa[kf][2], pa[kf][3],
                         u(vv.x), u(vv.y));
                MMA_TF32(o[2 * dfp + 1][0], o[2 * dfp + 1][1],
                         o[2 * dfp + 1][2], o[2 * dfp + 1][3],
                         pa[kf][0], pa[kf][1], pa[kf][2], pa[kf][3],
                         u(vv.z), u(vv.w));
            }
        }

        __syncthreads();
        if (tile + 2 < ntiles) issue(tile + 2, tile & 1);
        CP_COMMIT();
    }

    float inv0 = 1.f / l0, inv1 = 1.f / l1;
    float* ob0 = O + ((size_t)(b * TT + qglob + g))     * (HH * HD) + h * HD;
    float* ob1 = O + ((size_t)(b * TT + qglob + g + 8)) * (HH * HD) + h * HD;
    #pragma unroll
    for (int df = 0; df < 16; df++) {
        int col = df * 8 + tig * 2;
        *(float2*)(ob0 + col) =
            make_float2(tfs(o[df][0] * inv0), tfs(o[df][1] * inv0));
        *(float2*)(ob1 + col) =
            make_float2(tfs(o[df][2] * inv1), tfs(o[df][3] * inv1));
    }
}

// ---------------- launch --------------------------------------------
extern "C" void kernel_launch(void* const* d_in, const int* in_sizes, int n_in,
                              void* d_out, int out_size) {
    const float* x    = (const float*)d_in[0];
    const float* fcos = (const float*)d_in[1];
    const float* fsin = (const float*)d_in[2];
    const float* Wq   = (const float*)d_in[3];
    const float* Wk   = (const float*)d_in[4];
    const float* Wv   = (const float*)d_in[5];
    const float* Wo   = (const float*)d_in[6];

    float* y    = (float*)d_out;
    float* outK = y + (size_t)BB * TT * DD;
    float* outV = outK + (size_t)BB * KVH * TT * HD;

    float *qs, *att, *xr, *wqr, *wkr, *wvr, *wor, *kr, *vr;
    cudaGetSymbolAddress((void**)&qs,  g_qs);
    cudaGetSymbolAddress((void**)&att, g_att);
    cudaGetSymbolAddress((void**)&xr,  g_xr);
    cudaGetSymbolAddress((void**)&wqr, g_wqr);
    cudaGetSymbolAddress((void**)&wkr, g_wkr);
    cudaGetSymbolAddress((void**)&wvr, g_wvr);
    cudaGetSymbolAddress((void**)&wor, g_wor);
    cudaGetSymbolAddress((void**)&kr,  g_kr);
    cudaGetSymbolAddress((void**)&vr,  g_vr);

    const int M = BB * TT;  // 4096
    static int smem_set = 0;
    if (!smem_set) {
        cudaFuncSetAttribute(flash_mma_kernel,
                             cudaFuncAttributeMaxDynamicSharedMemorySize, FSMEM_BYTES);
        cudaFuncSetAttribute(gemm_qkv,
                             cudaFuncAttributeMaxDynamicSharedMemorySize, GSMEM_BYTES);
        cudaFuncSetAttribute(gemm_wo,
                             cudaFuncAttributeMaxDynamicSharedMemorySize, GSMEM_BYTES);
        smem_set = 1;
    }

    preround_all<<<2048, 256>>>(x, xr, Wq, wqr, Wk, wkr, Wv, wvr, Wo, wor);

    gemm_qkv<<<dim3(24, M / 128), 256, GSMEM_BYTES>>>(
        xr, wqr, wkr, wvr, qs, outK, outV, kr, vr, fcos, fsin);

    flash_mma_kernel<<<dim3(TT / 64, HH, BB), 128, FSMEM_BYTES>>>(
        qs, kr, vr, att);

    gemm_wo<<<dim3(DD / 128, M / 128), 256, GSMEM_BYTES>>>(
        att, wor, y, M, DD, DD);
}

// round 11
// speedup vs baseline: 1.7875x; 1.1044x over previous
#include <cuda_runtime.h>
#include <math.h>
#include <stdint.h>

#define BB 2
#define TT 2048
#define DD 2048
#define HH 16
#define KVH 4
#define HD 128
#define RD 64

// ---------------- device scratch (no allocs allowed) ----------------
__device__ float g_qs[4096 * 2048];    // tf32-rounded scaled roped Q (row-major)
__device__ float g_att[4096 * 2048];   // attention out, A-perm tiles
__device__ float g_xr[4096 * 2048];    // tf32 x, A-perm tiles
__device__ float g_wqr[2048 * 2048];   // tf32 Wq, B-perm tiles
__device__ float g_wkr[2048 * 512];
__device__ float g_wvr[2048 * 512];
__device__ float g_wor[2048 * 2048];
__device__ float g_kr[2 * 4 * 2048 * 128];  // perm-tiled tf32 roped K
__device__ float g_vr[2 * 4 * 2048 * 128];  // perm-tiled tf32 V

__device__ __forceinline__ uint32_t f2tf(float x) {
    uint32_t r;
    asm("cvt.rna.tf32.f32 %0, %1;" : "=r"(r) : "f"(x));
    return r;
}
__device__ __forceinline__ float tfs(float x) {
    uint32_t r = f2tf(x);
    return __uint_as_float(r);
}
__device__ __forceinline__ uint32_t u(float x) { return __float_as_uint(x); }

// ---- flash K/V tile perms (unchanged R10) ----
__device__ __forceinline__ int kperm(int kvl, int d) {
    return (((d >> 4) << 2) + (kvl >> 3)) * 128
         + ((((kvl & 7) << 2) + (d & 3)) << 2)
         + (((d >> 3) & 1) << 1) + ((d >> 2) & 1);
}
__device__ __forceinline__ int vperm(int kvl, int d) {
    return (((kvl >> 3) << 3) + (d >> 4)) * 128
         + ((((d & 7) << 2) + (kvl & 3)) << 2)
         + (((d >> 3) & 1) << 1) + ((kvl >> 2) & 1);
}

// ---- GEMM operand perms: A tile 128m x 32k, B tile 32k x 128n ----
// A: fragment (fm,fk) 16m x 8k; element(mi,ki): lane=(mi&7)*4+(ki&3),
//    pos = ((ki&7)>>2)<<1 | (mi>>3)&1
__device__ __forceinline__ int aperm(int mi, int ki) {
    return ((mi >> 4) * 4 + (ki >> 3)) * 128
         + (((mi & 7) << 2) + (ki & 3)) * 4
         + ((((ki & 7) >> 2) << 1) | ((mi >> 3) & 1));
}
// B: fragment (fn,kp) 8n x 16k; lane=(ni&7)*4+(ki&3), pos=(ki>>2)&3
__device__ __forceinline__ int bperm(int ki, int ni) {
    return ((ni >> 3) * 2 + (ki >> 4)) * 128
         + (((ni & 7) << 2) + (ki & 3)) * 4
         + ((ki >> 2) & 3);
}

#define MMA_TF32(d0,d1,d2,d3,a0,a1,a2,a3,b0,b1)                         \
    asm volatile(                                                        \
        "mma.sync.aligned.m16n8k8.row.col.f32.tf32.tf32.f32 "           \
        "{%0,%1,%2,%3}, {%4,%5,%6,%7}, {%8,%9}, {%0,%1,%2,%3};"         \
        : "+f"(d0), "+f"(d1), "+f"(d2), "+f"(d3)                         \
        : "r"(a0), "r"(a1), "r"(a2), "r"(a3), "r"(b0), "r"(b1))

#define CP_ASYNC16(smem_u32, gptr)                                       \
    asm volatile("cp.async.cg.shared.global [%0], [%1], 16;"             \
                 :: "r"(smem_u32), "l"(gptr))
#define CP_COMMIT() asm volatile("cp.async.commit_group;" ::: "memory")
#define CP_WAIT1()  asm volatile("cp.async.wait_group 1;"  ::: "memory")

// ------- fused pre-round + permute of all 5 input tensors -------------
#define S0 (4096 * 2048 / 4)
#define S1 (S0 + 2048 * 2048 / 4)
#define S2 (S1 + 2048 * 512 / 4)
#define S3 (S2 + 2048 * 512 / 4)
#define S4 (S3 + 2048 * 2048 / 4)

template <int N>
__device__ __forceinline__ void bstore(const float* __restrict__ src,
                                       float* __restrict__ dst, int e) {
    float4 v = ((const float4*)src)[e];
    int k = e / (N / 4);
    int n = (e % (N / 4)) << 2;
    size_t base = ((size_t)(k >> 5) * (N >> 7) + (n >> 7)) * 4096;
    int ki = k & 31, ni = n & 127;
    float* o = dst + base + ((ni >> 3) * 2 + (ki >> 4)) * 128 + ((ki >> 2) & 3);
    int t = ki & 3, L0 = ni & 7;
    o[((L0 + 0) * 4 + t) * 4] = tfs(v.x);
    o[((L0 + 1) * 4 + t) * 4] = tfs(v.y);
    o[((L0 + 2) * 4 + t) * 4] = tfs(v.z);
    o[((L0 + 3) * 4 + t) * 4] = tfs(v.w);
}

__global__ void preround_all(const float* __restrict__ x,  float* __restrict__ xr,
                             const float* __restrict__ wq, float* __restrict__ wqr,
                             const float* __restrict__ wk, float* __restrict__ wkr,
                             const float* __restrict__ wv, float* __restrict__ wvr,
                             const float* __restrict__ wo, float* __restrict__ wor) {
    int i = blockIdx.x * blockDim.x + threadIdx.x;
    int stride = gridDim.x * blockDim.x;
    for (; i < S4; i += stride) {
        if (i < S0) {
            int e = i;
            float4 v = ((const float4*)x)[e];
            int m = e >> 9;                // DD/4 = 512
            int k = (e & 511) << 2;
            size_t base = ((size_t)(m >> 7) * (DD / 32) + (k >> 5)) * 4096;
            int mi = m & 127, ki = k & 31;
            float* o = xr + base + ((mi >> 4) * 4 + (ki >> 3)) * 128
                     + ((((ki & 7) >> 2) << 1) | ((mi >> 3) & 1));
            int L0 = (mi & 7) << 2;
            o[(L0 + 0) * 4] = tfs(v.x);
            o[(L0 + 1) * 4] = tfs(v.y);
            o[(L0 + 2) * 4] = tfs(v.z);
            o[(L0 + 3) * 4] = tfs(v.w);
        }
        else if (i < S1) bstore<2048>(wq, wqr, i - S0);
        else if (i < S2) bstore<512>(wk, wkr, i - S1);
        else if (i < S3) bstore<512>(wv, wvr, i - S2);
        else             bstore<2048>(wo, wor, i - S3);
    }
}

// ---------------- shared GEMM plumbing --------------------------------
#define STAGE_FLOATS 8192
#define GSMEM_BYTES (3 * STAGE_FLOATS * 4)
#define QSCALE 0.08838834764831845f

// mainloop body (both GEMMs): vectorized fragment loads
#define GEMM_MAINLOOP(NK)                                                 \
    issue(0, 0); CP_COMMIT();                                             \
    issue(1, 1); CP_COMMIT();                                             \
    for (int kt = 0; kt < (NK); kt++) {                                   \
        CP_WAIT1();                                                       \
        __syncthreads();                                                  \
        if (kt + 2 < (NK)) issue(kt + 2, (kt + 2) % 3);                   \
        CP_COMMIT();                                                      \
        const float4* As = (const float4*)(gsm + (kt % 3) * STAGE_FLOATS);\
        const float4* Bs = As + 1024;                                     \
        _Pragma("unroll")                                                 \
        for (int kp = 0; kp < 2; kp++) {                                  \
            float4 b4[4];                                                 \
            _Pragma("unroll")                                             \
            for (int nt = 0; nt < 4; nt++)                                \
                b4[nt] = Bs[((wn * 4 + nt) * 2 + kp) * 32 + lane];        \
            _Pragma("unroll")                                             \
            for (int s2 = 0; s2 < 2; s2++) {                              \
                float4 a4[4];                                             \
                _Pragma("unroll")                                         \
                for (int mt = 0; mt < 4; mt++)                            \
                    a4[mt] = As[((wm * 4 + mt) * 4 + kp * 2 + s2) * 32 + lane];\
                _Pragma("unroll")                                         \
                for (int mt = 0; mt < 4; mt++)                            \
                    _Pragma("unroll")                                     \
                    for (int nt = 0; nt < 4; nt++)                        \
                        MMA_TF32(acc[mt][nt][0], acc[mt][nt][1],          \
                                 acc[mt][nt][2], acc[mt][nt][3],          \
                                 u(a4[mt].x), u(a4[mt].y),                \
                                 u(a4[mt].z), u(a4[mt].w),                \
                                 s2 ? u(b4[nt].z) : u(b4[nt].x),          \
                                 s2 ? u(b4[nt].w) : u(b4[nt].y));         \
            }                                                             \
        }                                                                 \
    }

// -------- fused Q/K/V projection GEMM ----------------------------------
__global__ __launch_bounds__(256, 2) void gemm_qkv(
    const float* __restrict__ A,
    const float* __restrict__ Bq, const float* __restrict__ Bk,
    const float* __restrict__ Bv,
    float* __restrict__ Cq, float* __restrict__ Ck, float* __restrict__ Cv,
    float* __restrict__ C2k, float* __restrict__ C2v,
    const float* __restrict__ fcos, const float* __restrict__ fsin) {
    extern __shared__ float gsm[];
    uint32_t smem_u = (uint32_t)__cvta_generic_to_shared(gsm);

    int xb = blockIdx.x;
    int path, bcb, nbt;             // nbt = N/128
    const float* B;
    if (xb < 16)      { path = 0; bcb = xb;      nbt = 16; B = Bq; }
    else if (xb < 20) { path = 1; bcb = xb - 16; nbt = 4;  B = Bk; }
    else              { path = 2; bcb = xb - 20; nbt = 4;  B = Bv; }

    int tid = threadIdx.x, lane = tid & 31;
    int w = tid >> 5, wm = w & 1, wn = w >> 1;
    int m0 = wm * 64, n0 = wn * 32;
    int g = lane >> 2, tig = lane & 3;
    int brow = blockIdx.y * 128, bcol = bcb * 128;

    float acc[4][4][4];
    #pragma unroll
    for (int mt = 0; mt < 4; mt++)
        #pragma unroll
        for (int nt = 0; nt < 4; nt++)
            #pragma unroll
            for (int i = 0; i < 4; i++) acc[mt][nt][i] = 0.f;

    auto issue = [&](int kt, int stage) {
        const float* atile = A + ((size_t)(brow >> 7) * (DD / 32) + kt) * 4096;
        const float* btile = B + ((size_t)kt * nbt + bcb) * 4096;
        uint32_t sa = smem_u + stage * STAGE_FLOATS * 4;
        uint32_t sb = sa + 4096 * 4;
        #pragma unroll
        for (int i = 0; i < 4; i++) {
            int c = tid + i * 256;
            CP_ASYNC16(sa + c * 16, atile + c * 4);
            CP_ASYNC16(sb + c * 16, btile + c * 4);
        }
    };

    GEMM_MAINLOOP(DD / 32)

    #pragma unroll
    for (int mt = 0; mt < 4; mt++) {
        int row = brow + m0 + mt * 16 + g;
        int row2 = row + 8;
        #pragma unroll
        for (int nt = 0; nt < 4; nt++) {
            int col = bcol + n0 + nt * 8 + tig * 2;
            float c0 = acc[mt][nt][0], c1 = acc[mt][nt][1];
            float c2 = acc[mt][nt][2], c3 = acc[mt][nt][3];

            int d = col & (HD - 1);
            if (path != 2 && d < RD) {
                int i = d >> 1;
                int t1 = row  & (TT - 1);
                int t2 = row2 & (TT - 1);
                float cc1 = fcos[t1 * (RD / 2) + i];
                float ss1 = fsin[t1 * (RD / 2) + i];
                float cc2 = fcos[t2 * (RD / 2) + i];
                float ss2 = fsin[t2 * (RD / 2) + i];
                float r0 = c0 * cc1 - c1 * ss1;
                float r1 = c0 * ss1 + c1 * cc1;
                float r2 = c2 * cc2 - c3 * ss2;
                float r3 = c2 * ss2 + c3 * cc2;
                c0 = r0; c1 = r1; c2 = r2; c3 = r3;
            }
            if (path == 0) {
                *(float2*)&Cq[(size_t)row  * (HH * HD) + col] =
                    make_float2(tfs(c0 * QSCALE), tfs(c1 * QSCALE));
                *(float2*)&Cq[(size_t)row2 * (HH * HD) + col] =
                    make_float2(tfs(c2 * QSCALE), tfs(c3 * QSCALE));
            } else {
                float* C  = (path == 1) ? Ck  : Cv;
                float* C2 = (path == 1) ? C2k : C2v;
                int kv = col >> 7;
                int b1i = row >> 11, t1 = row & (TT - 1);
                int b2i = row2 >> 11, t2 = row2 & (TT - 1);
                int bkv1 = b1i * KVH + kv, bkv2 = b2i * KVH + kv;
                size_t dst1 = ((size_t)bkv1 * TT + t1) * HD + d;
                size_t dst2 = ((size_t)bkv2 * TT + t2) * HD + d;
                *(float2*)&C[dst1] = make_float2(c0, c1);
                *(float2*)&C[dst2] = make_float2(c2, c3);
                size_t tb1 = ((size_t)bkv1 * (TT / 32) + (t1 >> 5)) * 4096;
                size_t tb2 = ((size_t)bkv2 * (TT / 32) + (t2 >> 5)) * 4096;
                int kvl1 = t1 & 31, kvl2 = t2 & 31;
                if (path == 1) {
                    C2[tb1 + kperm(kvl1, d)]     = tfs(c0);
                    C2[tb1 + kperm(kvl1, d + 1)] = tfs(c1);
                    C2[tb2 + kperm(kvl2, d)]     = tfs(c2);
                    C2[tb2 + kperm(kvl2, d + 1)] = tfs(c3);
                } else {
                    C2[tb1 + vperm(kvl1, d)]     = tfs(c0);
                    C2[tb1 + vperm(kvl1, d + 1)] = tfs(c1);
                    C2[tb2 + vperm(kvl2, d)]     = tfs(c2);
                    C2[tb2 + vperm(kvl2, d + 1)] = tfs(c3);
                }
            }
        }
    }
}

// -------- Wo projection GEMM (perm operands, plain output) -------------
__global__ __launch_bounds__(256, 2) void gemm_wo(
    const float* __restrict__ A, const float* __restrict__ B,
    float* __restrict__ C) {
    extern __shared__ float gsm[];
    uint32_t smem_u = (uint32_t)__cvta_generic_to_shared(gsm);
    const int N = DD;

    int tid = threadIdx.x, lane = tid & 31;
    int w = tid >> 5, wm = w & 1, wn = w >> 1;
    int m0 = wm * 64, n0 = wn * 32;
    int g = lane >> 2, tig = lane & 3;
    int brow = blockIdx.y * 128, bcol = blockIdx.x * 128;

    float acc[4][4][4];
    #pragma unroll
    for (int mt = 0; mt < 4; mt++)
        #pragma unroll
        for (int nt = 0; nt < 4; nt++)
            #pragma unroll
            for (int i = 0; i < 4; i++) acc[mt][nt][i] = 0.f;

    auto issue = [&](int kt, int stage) {
        const float* atile = A + ((size_t)(brow >> 7) * (DD / 32) + kt) * 4096;
        const float* btile = B + ((size_t)kt * (N >> 7) + (bcol >> 7)) * 4096;
        uint32_t sa = smem_u + stage * STAGE_FLOATS * 4;
        uint32_t sb = sa + 4096 * 4;
        #pragma unroll
        for (int i = 0; i < 4; i++) {
            int c = tid + i * 256;
            CP_ASYNC16(sa + c * 16, atile + c * 4);
            CP_ASYNC16(sb + c * 16, btile + c * 4);
        }
    };

    GEMM_MAINLOOP(DD / 32)

    #pragma unroll
    for (int mt = 0; mt < 4; mt++) {
        int row = brow + m0 + mt * 16 + g;
        int row2 = row + 8;
        #pragma unroll
        for (int nt = 0; nt < 4; nt++) {
            int col = bcol + n0 + nt * 8 + tig * 2;
            *(float2*)&C[(size_t)row  * N + col] =
                make_float2(acc[mt][nt][0], acc[mt][nt][1]);
            *(float2*)&C[(size_t)row2 * N + col] =
                make_float2(acc[mt][nt][2], acc[mt][nt][3]);
        }
    }
}

// ------ tensor-core causal flash attention (R10 loop; A-perm output) ---
#define FST 132
#define STAGE_F 8192
#define PS_OFF (2 * STAGE_F)
#define FSMEM_FLOATS (PS_OFF + 4 * 16 * 33)
#define FSMEM_BYTES (FSMEM_FLOATS * 4)

__global__ __launch_bounds__(128, 3) void flash_mma_kernel(
    const float* __restrict__ Q, const float* __restrict__ K,
    const float* __restrict__ V, float* __restrict__ O) {
    extern __shared__ float fsm[];
    uint32_t smem_u = (uint32_t)__cvta_generic_to_shared(fsm);

    int tid = threadIdx.x, lane = tid & 31, w = tid >> 5;
    int g = lane >> 2, tig = lane & 3;
    int b = blockIdx.z, h = blockIdx.y;
    int q0 = (gridDim.x - 1 - blockIdx.x) * 64;
    int kvh = h >> 2;

    size_t kvbase = (size_t)(b * KVH + kvh) * (TT / 32) * 4096;
    int ntiles = q0 / 32 + 2;

    {
        int r = tid >> 2, cb = (tid & 3) * 4;
        const float* qg = Q + ((size_t)(b * TT + q0 + r)) * (HH * HD) + h * HD;
        const float* qg2 = qg + (size_t)32 * (HH * HD);
        #pragma unroll
        for (int i = 0; i < 8; i++) {
            *(float4*)&fsm[r * FST + cb + i * 16] =
                *(const float4*)(qg + cb + i * 16);
            *(float4*)&fsm[(r + 32) * FST + cb + i * 16] =
                *(const float4*)(qg2 + cb + i * 16);
        }
    }
    __syncthreads();

    uint32_t qf[16][4];
    int qw = w * 16;
    #pragma unroll
    for (int kf = 0; kf < 16; kf++) {
        qf[kf][0] = u(fsm[(qw + g)     * FST + kf * 8 + tig]);
        qf[kf][1] = u(fsm[(qw + g + 8) * FST + kf * 8 + tig]);
        qf[kf][2] = u(fsm[(qw + g)     * FST + kf * 8 + tig + 4]);
        qf[kf][3] = u(fsm[(qw + g + 8) * FST + kf * 8 + tig + 4]);
    }
    __syncthreads();

    auto issue = [&](int tile, int stage) {
        const float* kb = K + kvbase + (size_t)tile * 4096;
        const float* vb = V + kvbase + (size_t)tile * 4096;
        uint32_t sk = smem_u + stage * STAGE_F * 4;
        uint32_t sv = sk + 4096 * 4;
        #pragma unroll
        for (int i = 0; i < 8; i++) {
            int c = tid + i * 128;
            CP_ASYNC16(sk + c * 16, kb + c * 4);
            CP_ASYNC16(sv + c * 16, vb + c * 4);
        }
    };

    issue(0, 0); CP_COMMIT();
    if (ntiles > 1) issue(1, 1);
    CP_COMMIT();

    float o[16][4];
    #pragma unroll
    for (int df = 0; df < 16; df++)
        o[df][0] = o[df][1] = o[df][2] = o[df][3] = 0.f;
    float m0 = -1e30f, m1 = -1e30f, l0 = 0.f, l1 = 0.f;

    int qglob = q0 + qw;
    float* Pw = fsm + PS_OFF + w * (16 * 33);

    for (int tile = 0; tile < ntiles; tile++) {
        int kv0 = tile * 32;
        const float* Ks = fsm + (tile & 1) * STAGE_F;
        const float* Vs = Ks + 4096;

        CP_WAIT1();
        __syncthreads();

        float s[4][4];
        #pragma unroll
        for (int nf = 0; nf < 4; nf++) {
            s[nf][0] = s[nf][1] = s[nf][2] = s[nf][3] = 0.f;
            #pragma unroll
            for (int kp = 0; kp < 8; kp++) {
                float4 bv = *(const float4*)&Ks[(kp * 4 + nf) * 128 + lane * 4];
                MMA_TF32(s[nf][0], s[nf][1], s[nf][2], s[nf][3],
                         qf[2 * kp][0], qf[2 * kp][1],
                         qf[2 * kp][2], qf[2 * kp][3],
                         u(bv.x), u(bv.y));
                MMA_TF32(s[nf][0], s[nf][1], s[nf][2], s[nf][3],
                         qf[2 * kp + 1][0], qf[2 * kp + 1][1],
                         qf[2 * kp + 1][2], qf[2 * kp + 1][3],
                         u(bv.z), u(bv.w));
            }
        }

        if (kv0 + 31 > qglob) {
            int r0 = qglob + g, r1 = qglob + g + 8;
            #pragma unroll
            for (int nf = 0; nf < 4; nf++) {
                int c = kv0 + nf * 8 + tig * 2;
                if (c     > r0) s[nf][0] = -1e30f;
                if (c + 1 > r0) s[nf][1] = -1e30f;
                if (c     > r1) s[nf][2] = -1e30f;
                if (c + 1 > r1) s[nf][3] = -1e30f;
            }
        }

        float mx0 = -1e30f, mx1 = -1e30f;
        #pragma unroll
        for (int nf = 0; nf < 4; nf++) {
            mx0 = fmaxf(mx0, fmaxf(s[nf][0], s[nf][1]));
            mx1 = fmaxf(mx1, fmaxf(s[nf][2], s[nf][3]));
        }
        mx0 = fmaxf(mx0, __shfl_xor_sync(0xffffffffu, mx0, 1));
        mx0 = fmaxf(mx0, __shfl_xor_sync(0xffffffffu, mx0, 2));
        mx1 = fmaxf(mx1, __shfl_xor_sync(0xffffffffu, mx1, 1));
        mx1 = fmaxf(mx1, __shfl_xor_sync(0xffffffffu, mx1, 2));
        float mn0 = fmaxf(m0, mx0), mn1 = fmaxf(m1, mx1);
        float sc0 = __expf(m0 - mn0), sc1 = __expf(m1 - mn1);
        m0 = mn0; m1 = mn1;

        float ps0 = 0.f, ps1 = 0.f;
        #pragma unroll
        for (int nf = 0; nf < 4; nf++) {
            float p0 = __expf(s[nf][0] - mn0);
            float p1 = __expf(s[nf][1] - mn0);
            float p2 = __expf(s[nf][2] - mn1);
            float p3 = __expf(s[nf][3] - mn1);
            ps0 += p0 + p1; ps1 += p2 + p3;
            Pw[(g    ) * 33 + nf * 8 + tig * 2    ] = tfs(p0);
            Pw[(g    ) * 33 + nf * 8 + tig * 2 + 1] = tfs(p1);
            Pw[(g + 8) * 33 + nf * 8 + tig * 2    ] = tfs(p2);
            Pw[(g + 8) * 33 + nf * 8 + tig * 2 + 1] = tfs(p3);
        }
        ps0 += __shfl_xor_sync(0xffffffffu, ps0, 1);
        ps0 += __shfl_xor_sync(0xffffffffu, ps0, 2);
        ps1 += __shfl_xor_sync(0xffffffffu, ps1, 1);
        ps1 += __shfl_xor_sync(0xffffffffu, ps1, 2);
        l0 = l0 * sc0 + ps0;
        l1 = l1 * sc1 + ps1;

        #pragma unroll
        for (int df = 0; df < 16; df++) {
            o[df][0] *= sc0; o[df][1] *= sc0;
            o[df][2] *= sc1; o[df][3] *= sc1;
        }
        __syncwarp();

        uint32_t pa[4][4];
        #pragma unroll
        for (int kf = 0; kf < 4; kf++) {
            pa[kf][0] = u(Pw[(g    ) * 33 + kf * 8 + tig]);
            pa[kf][1] = u(Pw[(g + 8) * 33 + kf * 8 + tig]);
            pa[kf][2] = u(Pw[(g    ) * 33 + kf * 8 + tig + 4]);
            pa[kf][3] = u(Pw[(g + 8) * 33 + kf * 8 + tig + 4]);
        }
        __syncwarp();

        #pragma unroll
        for (int dfp = 0; dfp < 8; dfp++) {
            #pragma unroll
            for (int kf = 0; kf < 4; kf++) {
                float4 vv = *(const float4*)&Vs[(kf * 8 + dfp) * 128 + lane * 4];
                MMA_TF32(o[2 * dfp][0], o[2 * dfp][1],
                         o[2 * dfp][2], o[2 * dfp][3],
                         pa[kf][0], pa[kf][1], pa[kf][2], pa[kf][3],
                         u(vv.x), u(vv.y));
                MMA_TF32(o[2 * dfp + 1][0], o[2 * dfp + 1][1],
                         o[2 * dfp + 1][2], o[2 * dfp + 1][3],
                         pa[kf][0], pa[kf][1], pa[kf][2], pa[kf][3],
                         u(vv.z), u(vv.w));
            }
        }

        __syncthreads();
        if (tile + 2 < ntiles) issue(tile + 2, tile & 1);
        CP_COMMIT();
    }

    // epilogue: write tf32-rounded O into A-perm tiles for gemm_wo
    float inv0 = 1.f / l0, inv1 = 1.f / l1;
    auto aidx = [](int r, int c) -> size_t {
        int mi = r & 127, ki = c & 31;
        return ((size_t)(r >> 7) * (DD / 32) + (c >> 5)) * 4096
             + (size_t)aperm(mi, ki);
    };
    int r0g = b * TT + qglob + g;
    int r1g = r0g + 8;
    #pragma unroll
    for (int df = 0; df < 16; df++) {
        int c = h * HD + df * 8 + tig * 2;
        O[aidx(r0g, c)]     = tfs(o[df][0] * inv0);
        O[aidx(r0g, c + 1)] = tfs(o[df][1] * inv0);
        O[aidx(r1g, c)]     = tfs(o[df][2] * inv1);
        O[aidx(r1g, c + 1)] = tfs(o[df][3] * inv1);
    }
}

// ---------------- launch --------------------------------------------
extern "C" void kernel_launch(void* const* d_in, const int* in_sizes, int n_in,
                              void* d_out, int out_size) {
    const float* x    = (const float*)d_in[0];
    const float* fcos = (const float*)d_in[1];
    const float* fsin = (const float*)d_in[2];
    const float* Wq   = (const float*)d_in[3];
    const float* Wk   = (const float*)d_in[4];
    const float* Wv   = (const float*)d_in[5];
    const float* Wo   = (const float*)d_in[6];

    float* y    = (float*)d_out;
    float* outK = y + (size_t)BB * TT * DD;
    float* outV = outK + (size_t)BB * KVH * TT * HD;

    float *qs, *att, *xr, *wqr, *wkr, *wvr, *wor, *kr, *vr;
    cudaGetSymbolAddress((void**)&qs,  g_qs);
    cudaGetSymbolAddress((void**)&att, g_att);
    cudaGetSymbolAddress((void**)&xr,  g_xr);
    cudaGetSymbolAddress((void**)&wqr, g_wqr);
    cudaGetSymbolAddress((void**)&wkr, g_wkr);
    cudaGetSymbolAddress((void**)&wvr, g_wvr);
    cudaGetSymbolAddress((void**)&wor, g_wor);
    cudaGetSymbolAddress((void**)&kr,  g_kr);
    cudaGetSymbolAddress((void**)&vr,  g_vr);

    const int M = BB * TT;  // 4096
    static int smem_set = 0;
    if (!smem_set) {
        cudaFuncSetAttribute(flash_mma_kernel,
                             cudaFuncAttributeMaxDynamicSharedMemorySize, FSMEM_BYTES);
        cudaFuncSetAttribute(gemm_qkv,
                             cudaFuncAttributeMaxDynamicSharedMemorySize, GSMEM_BYTES);
        cudaFuncSetAttribute(gemm_wo,
                             cudaFuncAttributeMaxDynamicSharedMemorySize, GSMEM_BYTES);
        smem_set = 1;
    }

    preround_all<<<2048, 256>>>(x, xr, Wq, wqr, Wk, wkr, Wv, wvr, Wo, wor);

    gemm_qkv<<<dim3(24, M / 128), 256, GSMEM_BYTES>>>(
        xr, wqr, wkr, wvr, qs, outK, outV, kr, vr, fcos, fsin);

    flash_mma_kernel<<<dim3(TT / 64, HH, BB), 128, FSMEM_BYTES>>>(
        qs, kr, vr, att);

    gemm_wo<<<dim3(DD / 128, M / 128), 256, GSMEM_BYTES>>>(att, wor, y);
}

// round 12
// speedup vs baseline: 1.8826x; 1.0532x over previous
#include <cuda_runtime.h>
#include <math.h>
#include <stdint.h>

#define BB 2
#define TT 2048
#define DD 2048
#define HH 16
#define KVH 4
#define HD 128
#define RD 64

// ---------------- device scratch (no allocs allowed) ----------------
__device__ float g_qs[4096 * 2048];    // tf32-rounded scaled roped Q (row-major)
__device__ float g_att[4096 * 2048];   // attention out, A-perm tiles
__device__ float g_xr[4096 * 2048];    // tf32 x, A-perm tiles
__device__ float g_wqr[2048 * 2048];   // tf32 Wq, B-perm tiles
__device__ float g_wkr[2048 * 512];
__device__ float g_wvr[2048 * 512];
__device__ float g_wor[2048 * 2048];
__device__ float g_kr[2 * 4 * 2048 * 128];  // perm-tiled tf32 roped K
__device__ float g_vr[2 * 4 * 2048 * 128];  // perm-tiled tf32 V

__device__ __forceinline__ uint32_t f2tf(float x) {
    uint32_t r;
    asm("cvt.rna.tf32.f32 %0, %1;" : "=r"(r) : "f"(x));
    return r;
}
__device__ __forceinline__ float tfs(float x) {
    uint32_t r = f2tf(x);
    return __uint_as_float(r);
}
__device__ __forceinline__ uint32_t u(float x) { return __float_as_uint(x); }

// ---- flash K/V tile perms ----
__device__ __forceinline__ int kperm(int kvl, int d) {
    return (((d >> 4) << 2) + (kvl >> 3)) * 128
         + ((((kvl & 7) << 2) + (d & 3)) << 2)
         + (((d >> 3) & 1) << 1) + ((d >> 2) & 1);
}
__device__ __forceinline__ int vperm(int kvl, int d) {
    return (((kvl >> 3) << 3) + (d >> 4)) * 128
         + ((((d & 7) << 2) + (kvl & 3)) << 2)
         + (((d >> 3) & 1) << 1) + ((kvl >> 2) & 1);
}

// ---- GEMM operand perms: A tile 128m x 32k, B tile 32k x 128n ----
__device__ __forceinline__ int aperm(int mi, int ki) {
    return ((mi >> 4) * 4 + (ki >> 3)) * 128
         + (((mi & 7) << 2) + (ki & 3)) * 4
         + ((((ki & 7) >> 2) << 1) | ((mi >> 3) & 1));
}
__device__ __forceinline__ int bperm(int ki, int ni) {
    return ((ni >> 3) * 2 + (ki >> 4)) * 128
         + (((ni & 7) << 2) + (ki & 3)) * 4
         + ((ki >> 2) & 3);
}

#define MMA_TF32(d0,d1,d2,d3,a0,a1,a2,a3,b0,b1)                         \
    asm volatile(                                                        \
        "mma.sync.aligned.m16n8k8.row.col.f32.tf32.tf32.f32 "           \
        "{%0,%1,%2,%3}, {%4,%5,%6,%7}, {%8,%9}, {%0,%1,%2,%3};"         \
        : "+f"(d0), "+f"(d1), "+f"(d2), "+f"(d3)                         \
        : "r"(a0), "r"(a1), "r"(a2), "r"(a3), "r"(b0), "r"(b1))

#define CP_ASYNC16(smem_u32, gptr)                                       \
    asm volatile("cp.async.cg.shared.global [%0], [%1], 16;"             \
                 :: "r"(smem_u32), "l"(gptr))
#define CP_COMMIT() asm volatile("cp.async.commit_group;" ::: "memory")
#define CP_WAIT1()  asm volatile("cp.async.wait_group 1;"  ::: "memory")

// ------- tile-staged coalesced pre-round + permute ---------------------
// One block per 4096-float tile: coalesced reads -> smem permute ->
// coalesced linear writes. Tile ranges:
// [0,2048): x (A-perm) | [2048,3072): Wq | [3072,3328): Wk |
// [3328,3584): Wv | [3584,4608): Wo   (all B-perm)
__global__ __launch_bounds__(128) void preround_tiles(
    const float* __restrict__ x,  float* __restrict__ xr,
    const float* __restrict__ wq, float* __restrict__ wqr,
    const float* __restrict__ wk, float* __restrict__ wkr,
    const float* __restrict__ wv, float* __restrict__ wvr,
    const float* __restrict__ wo, float* __restrict__ wor) {
    __shared__ float sm[4096];
    int t = blockIdx.x, tid = threadIdx.x;

    if (t < 2048) {
        // x: A-perm tile (128 m-rows x 32 k), tile id = mb*64 + kb
        int mb = t >> 6, kb = t & 63;
        const float4* src = (const float4*)x;
        #pragma unroll
        for (int i = 0; i < 8; i++) {
            int c = tid + i * 128;
            int row = c >> 3, c4 = c & 7;
            float4 v = src[(size_t)(mb * 128 + row) * 512 + kb * 8 + c4];
            int ki = c4 * 4;
            sm[aperm(row, ki + 0)] = tfs(v.x);
            sm[aperm(row, ki + 1)] = tfs(v.y);
            sm[aperm(row, ki + 2)] = tfs(v.z);
            sm[aperm(row, ki + 3)] = tfs(v.w);
        }
        __syncthreads();
        float4* dst = (float4*)xr + (size_t)t * 1024;
        #pragma unroll
        for (int i = 0; i < 8; i++)
            dst[tid + i * 128] = ((const float4*)sm)[tid + i * 128];
    } else {
        const float* S; float* D; int N, tt;
        if (t < 3072)      { S = wq; D = wqr; N = 2048; tt = t - 2048; }
        else if (t < 3328) { S = wk; D = wkr; N = 512;  tt = t - 3072; }
        else if (t < 3584) { S = wv; D = wvr; N = 512;  tt = t - 3328; }
        else               { S = wo; D = wor; N = 2048; tt = t - 3584; }
        int nbt = N >> 7;
        int kb = tt / nbt, nb = tt % nbt;
        const float4* src = (const float4*)S;
        #pragma unroll
        for (int i = 0; i < 8; i++) {
            int c = tid + i * 128;
            int kr = c >> 5, n4 = c & 31;
            float4 v = src[(size_t)(kb * 32 + kr) * (N >> 2) + nb * 32 + n4];
            int ni = n4 * 4;
            sm[bperm(kr, ni + 0)] = tfs(v.x);
            sm[bperm(kr, ni + 1)] = tfs(v.y);
            sm[bperm(kr, ni + 2)] = tfs(v.z);
            sm[bperm(kr, ni + 3)] = tfs(v.w);
        }
        __syncthreads();
        float4* dst = (float4*)D + (size_t)tt * 1024;
        #pragma unroll
        for (int i = 0; i < 8; i++)
            dst[tid + i * 128] = ((const float4*)sm)[tid + i * 128];
    }
}

// ---------------- shared GEMM plumbing --------------------------------
#define STAGE_FLOATS 8192
#define GSMEM_BYTES (3 * STAGE_FLOATS * 4)
#define QSCALE 0.08838834764831845f

#define GEMM_MAINLOOP(NK)                                                 \
    issue(0, 0); CP_COMMIT();                                             \
    issue(1, 1); CP_COMMIT();                                             \
    for (int kt = 0; kt < (NK); kt++) {                                   \
        CP_WAIT1();                                                       \
        __syncthreads();                                                  \
        if (kt + 2 < (NK)) issue(kt + 2, (kt + 2) % 3);                   \
        CP_COMMIT();                                                      \
        const float4* As = (const float4*)(gsm + (kt % 3) * STAGE_FLOATS);\
        const float4* Bs = As + 1024;                                     \
        _Pragma("unroll")                                                 \
        for (int kp = 0; kp < 2; kp++) {                                  \
            float4 b4[4];                                                 \
            _Pragma("unroll")                                             \
            for (int nt = 0; nt < 4; nt++)                                \
                b4[nt] = Bs[((wn * 4 + nt) * 2 + kp) * 32 + lane];        \
            _Pragma("unroll")                                             \
            for (int s2 = 0; s2 < 2; s2++) {                              \
                float4 a4[4];                                             \
                _Pragma("unroll")                                         \
                for (int mt = 0; mt < 4; mt++)                            \
                    a4[mt] = As[((wm * 4 + mt) * 4 + kp * 2 + s2) * 32 + lane];\
                _Pragma("unroll")                                         \
                for (int mt = 0; mt < 4; mt++)                            \
                    _Pragma("unroll")                                     \
                    for (int nt = 0; nt < 4; nt++)                        \
                        MMA_TF32(acc[mt][nt][0], acc[mt][nt][1],          \
                                 acc[mt][nt][2], acc[mt][nt][3],          \
                                 u(a4[mt].x), u(a4[mt].y),                \
                                 u(a4[mt].z), u(a4[mt].w),                \
                                 s2 ? u(b4[nt].z) : u(b4[nt].x),          \
                                 s2 ? u(b4[nt].w) : u(b4[nt].y));         \
            }                                                             \
        }                                                                 \
    }

// -------- fused Q/K/V projection GEMM ----------------------------------
__global__ __launch_bounds__(256, 2) void gemm_qkv(
    const float* __restrict__ A,
    const float* __restrict__ Bq, const float* __restrict__ Bk,
    const float* __restrict__ Bv,
    float* __restrict__ Cq, float* __restrict__ Ck, float* __restrict__ Cv,
    float* __restrict__ C2k, float* __restrict__ C2v,
    const float* __restrict__ fcos, const float* __restrict__ fsin) {
    extern __shared__ float gsm[];
    uint32_t smem_u = (uint32_t)__cvta_generic_to_shared(gsm);

    int xb = blockIdx.x;
    int path, bcb, nbt;
    const float* B;
    if (xb < 16)      { path = 0; bcb = xb;      nbt = 16; B = Bq; }
    else if (xb < 20) { path = 1; bcb = xb - 16; nbt = 4;  B = Bk; }
    else              { path = 2; bcb = xb - 20; nbt = 4;  B = Bv; }

    int tid = threadIdx.x, lane = tid & 31;
    int w = tid >> 5, wm = w & 1, wn = w >> 1;
    int m0 = wm * 64, n0 = wn * 32;
    int g = lane >> 2, tig = lane & 3;
    int brow = blockIdx.y * 128, bcol = bcb * 128;

    float acc[4][4][4];
    #pragma unroll
    for (int mt = 0; mt < 4; mt++)
        #pragma unroll
        for (int nt = 0; nt < 4; nt++)
            #pragma unroll
            for (int i = 0; i < 4; i++) acc[mt][nt][i] = 0.f;

    auto issue = [&](int kt, int stage) {
        const float* atile = A + ((size_t)(brow >> 7) * (DD / 32) + kt) * 4096;
        const float* btile = B + ((size_t)kt * nbt + bcb) * 4096;
        uint32_t sa = smem_u + stage * STAGE_FLOATS * 4;
        uint32_t sb = sa + 4096 * 4;
        #pragma unroll
        for (int i = 0; i < 4; i++) {
            int c = tid + i * 256;
            CP_ASYNC16(sa + c * 16, atile + c * 4);
            CP_ASYNC16(sb + c * 16, btile + c * 4);
        }
    };

    GEMM_MAINLOOP(DD / 32)

    #pragma unroll
    for (int mt = 0; mt < 4; mt++) {
        int row = brow + m0 + mt * 16 + g;
        int row2 = row + 8;
        #pragma unroll
        for (int nt = 0; nt < 4; nt++) {
            int col = bcol + n0 + nt * 8 + tig * 2;
            float c0 = acc[mt][nt][0], c1 = acc[mt][nt][1];
            float c2 = acc[mt][nt][2], c3 = acc[mt][nt][3];

            int d = col & (HD - 1);
            if (path != 2 && d < RD) {
                int i = d >> 1;
                int t1 = row  & (TT - 1);
                int t2 = row2 & (TT - 1);
                float cc1 = fcos[t1 * (RD / 2) + i];
                float ss1 = fsin[t1 * (RD / 2) + i];
                float cc2 = fcos[t2 * (RD / 2) + i];
                float ss2 = fsin[t2 * (RD / 2) + i];
                float r0 = c0 * cc1 - c1 * ss1;
                float r1 = c0 * ss1 + c1 * cc1;
                float r2 = c2 * cc2 - c3 * ss2;
                float r3 = c2 * ss2 + c3 * cc2;
                c0 = r0; c1 = r1; c2 = r2; c3 = r3;
            }
            if (path == 0) {
                *(float2*)&Cq[(size_t)row  * (HH * HD) + col] =
                    make_float2(tfs(c0 * QSCALE), tfs(c1 * QSCALE));
                *(float2*)&Cq[(size_t)row2 * (HH * HD) + col] =
                    make_float2(tfs(c2 * QSCALE), tfs(c3 * QSCALE));
            } else {
                float* C  = (path == 1) ? Ck  : Cv;
                float* C2 = (path == 1) ? C2k : C2v;
                int kv = col >> 7;
                int b1i = row >> 11, t1 = row & (TT - 1);
                int b2i = row2 >> 11, t2 = row2 & (TT - 1);
                int bkv1 = b1i * KVH + kv, bkv2 = b2i * KVH + kv;
                size_t dst1 = ((size_t)bkv1 * TT + t1) * HD + d;
                size_t dst2 = ((size_t)bkv2 * TT + t2) * HD + d;
                *(float2*)&C[dst1] = make_float2(c0, c1);
                *(float2*)&C[dst2] = make_float2(c2, c3);
                size_t tb1 = ((size_t)bkv1 * (TT / 32) + (t1 >> 5)) * 4096;
                size_t tb2 = ((size_t)bkv2 * (TT / 32) + (t2 >> 5)) * 4096;
                int kvl1 = t1 & 31, kvl2 = t2 & 31;
                if (path == 1) {
                    C2[tb1 + kperm(kvl1, d)]     = tfs(c0);
                    C2[tb1 + kperm(kvl1, d + 1)] = tfs(c1);
                    C2[tb2 + kperm(kvl2, d)]     = tfs(c2);
                    C2[tb2 + kperm(kvl2, d + 1)] = tfs(c3);
                } else {
                    C2[tb1 + vperm(kvl1, d)]     = tfs(c0);
                    C2[tb1 + vperm(kvl1, d + 1)] = tfs(c1);
                    C2[tb2 + vperm(kvl2, d)]     = tfs(c2);
                    C2[tb2 + vperm(kvl2, d + 1)] = tfs(c3);
                }
            }
        }
    }
}

// -------- Wo projection GEMM (perm operands, plain output) -------------
__global__ __launch_bounds__(256, 2) void gemm_wo(
    const float* __restrict__ A, const float* __restrict__ B,
    float* __restrict__ C) {
    extern __shared__ float gsm[];
    uint32_t smem_u = (uint32_t)__cvta_generic_to_shared(gsm);
    const int N = DD;

    int tid = threadIdx.x, lane = tid & 31;
    int w = tid >> 5, wm = w & 1, wn = w >> 1;
    int m0 = wm * 64, n0 = wn * 32;
    int g = lane >> 2, tig = lane & 3;
    int brow = blockIdx.y * 128, bcol = blockIdx.x * 128;

    float acc[4][4][4];
    #pragma unroll
    for (int mt = 0; mt < 4; mt++)
        #pragma unroll
        for (int nt = 0; nt < 4; nt++)
            #pragma unroll
            for (int i = 0; i < 4; i++) acc[mt][nt][i] = 0.f;

    auto issue = [&](int kt, int stage) {
        const float* atile = A + ((size_t)(brow >> 7) * (DD / 32) + kt) * 4096;
        const float* btile = B + ((size_t)kt * (N >> 7) + (bcol >> 7)) * 4096;
        uint32_t sa = smem_u + stage * STAGE_FLOATS * 4;
        uint32_t sb = sa + 4096 * 4;
        #pragma unroll
        for (int i = 0; i < 4; i++) {
            int c = tid + i * 256;
            CP_ASYNC16(sa + c * 16, atile + c * 4);
            CP_ASYNC16(sb + c * 16, btile + c * 4);
        }
    };

    GEMM_MAINLOOP(DD / 32)

    #pragma unroll
    for (int mt = 0; mt < 4; mt++) {
        int row = brow + m0 + mt * 16 + g;
        int row2 = row + 8;
        #pragma unroll
        for (int nt = 0; nt < 4; nt++) {
            int col = bcol + n0 + nt * 8 + tig * 2;
            *(float2*)&C[(size_t)row  * N + col] =
                make_float2(acc[mt][nt][0], acc[mt][nt][1]);
            *(float2*)&C[(size_t)row2 * N + col] =
                make_float2(acc[mt][nt][2], acc[mt][nt][3]);
        }
    }
}

// ------ tensor-core causal flash attention (perm K/V; A-perm output) ---
#define FST 132
#define STAGE_F 8192
#define PS_OFF (2 * STAGE_F)
#define FSMEM_FLOATS (PS_OFF + 4 * 16 * 33)
#define FSMEM_BYTES (FSMEM_FLOATS * 4)

__global__ __launch_bounds__(128, 3) void flash_mma_kernel(
    const float* __restrict__ Q, const float* __restrict__ K,
    const float* __restrict__ V, float* __restrict__ O) {
    extern __shared__ float fsm[];
    uint32_t smem_u = (uint32_t)__cvta_generic_to_shared(fsm);

    int tid = threadIdx.x, lane = tid & 31, w = tid >> 5;
    int g = lane >> 2, tig = lane & 3;
    int b = blockIdx.z, h = blockIdx.y;
    int q0 = (gridDim.x - 1 - blockIdx.x) * 64;
    int kvh = h >> 2;

    size_t kvbase = (size_t)(b * KVH + kvh) * (TT / 32) * 4096;
    int ntiles = q0 / 32 + 2;

    {
        int r = tid >> 2, cb = (tid & 3) * 4;
        const float* qg = Q + ((size_t)(b * TT + q0 + r)) * (HH * HD) + h * HD;
        const float* qg2 = qg + (size_t)32 * (HH * HD);
        #pragma unroll
        for (int i = 0; i < 8; i++) {
            *(float4*)&fsm[r * FST + cb + i * 16] =
                *(const float4*)(qg + cb + i * 16);
            *(float4*)&fsm[(r + 32) * FST + cb + i * 16] =
                *(const float4*)(qg2 + cb + i * 16);
        }
    }
    __syncthreads();

    uint32_t qf[16][4];
    int qw = w * 16;
    #pragma unroll
    for (int kf = 0; kf < 16; kf++) {
        qf[kf][0] = u(fsm[(qw + g)     * FST + kf * 8 + tig]);
        qf[kf][1] = u(fsm[(qw + g + 8) * FST + kf * 8 + tig]);
        qf[kf][2] = u(fsm[(qw + g)     * FST + kf * 8 + tig + 4]);
        qf[kf][3] = u(fsm[(qw + g + 8) * FST + kf * 8 + tig + 4]);
    }
    __syncthreads();

    auto issue = [&](int tile, int stage) {
        const float* kb = K + kvbase + (size_t)tile * 4096;
        const float* vb = V + kvbase + (size_t)tile * 4096;
        uint32_t sk = smem_u + stage * STAGE_F * 4;
        uint32_t sv = sk + 4096 * 4;
        #pragma unroll
        for (int i = 0; i < 8; i++) {
            int c = tid + i * 128;
            CP_ASYNC16(sk + c * 16, kb + c * 4);
            CP_ASYNC16(sv + c * 16, vb + c * 4);
        }
    };

    issue(0, 0); CP_COMMIT();
    if (ntiles > 1) issue(1, 1);
    CP_COMMIT();

    float o[16][4];
    #pragma unroll
    for (int df = 0; df < 16; df++)
        o[df][0] = o[df][1] = o[df][2] = o[df][3] = 0.f;
    float m0 = -1e30f, m1 = -1e30f, l0 = 0.f, l1 = 0.f;

    int qglob = q0 + qw;
    float* Pw = fsm + PS_OFF + w * (16 * 33);

    for (int tile = 0; tile < ntiles; tile++) {
        int kv0 = tile * 32;
        const float* Ks = fsm + (tile & 1) * STAGE_F;
        const float* Vs = Ks + 4096;

        CP_WAIT1();
        __syncthreads();

        float s[4][4];
        #pragma unroll
        for (int nf = 0; nf < 4; nf++) {
            s[nf][0] = s[nf][1] = s[nf][2] = s[nf][3] = 0.f;
            #pragma unroll
            for (int kp = 0; kp < 8; kp++) {
                float4 bv = *(const float4*)&Ks[(kp * 4 + nf) * 128 + lane * 4];
                MMA_TF32(s[nf][0], s[nf][1], s[nf][2], s[nf][3],
                         qf[2 * kp][0], qf[2 * kp][1],
                         qf[2 * kp][2], qf[2 * kp][3],
                         u(bv.x), u(bv.y));
                MMA_TF32(s[nf][0], s[nf][1], s[nf][2], s[nf][3],
                         qf[2 * kp + 1][0], qf[2 * kp + 1][1],
                         qf[2 * kp + 1][2], qf[2 * kp + 1][3],
                         u(bv.z), u(bv.w));
            }
        }

        if (kv0 + 31 > qglob) {
            int r0 = qglob + g, r1 = qglob + g + 8;
            #pragma unroll
            for (int nf = 0; nf < 4; nf++) {
                int c = kv0 + nf * 8 + tig * 2;
                if (c     > r0) s[nf][0] = -1e30f;
                if (c + 1 > r0) s[nf][1] = -1e30f;
                if (c     > r1) s[nf][2] = -1e30f;
                if (c + 1 > r1) s[nf][3] = -1e30f;
            }
        }

        float mx0 = -1e30f, mx1 = -1e30f;
        #pragma unroll
        for (int nf = 0; nf < 4; nf++) {
            mx0 = fmaxf(mx0, fmaxf(s[nf][0], s[nf][1]));
            mx1 = fmaxf(mx1, fmaxf(s[nf][2], s[nf][3]));
        }
        mx0 = fmaxf(mx0, __shfl_xor_sync(0xffffffffu, mx0, 1));
        mx0 = fmaxf(mx0, __shfl_xor_sync(0xffffffffu, mx0, 2));
        mx1 = fmaxf(mx1, __shfl_xor_sync(0xffffffffu, mx1, 1));
        mx1 = fmaxf(mx1, __shfl_xor_sync(0xffffffffu, mx1, 2));
        float mn0 = fmaxf(m0, mx0), mn1 = fmaxf(m1, mx1);
        float sc0 = __expf(m0 - mn0), sc1 = __expf(m1 - mn1);
        m0 = mn0; m1 = mn1;

        float ps0 = 0.f, ps1 = 0.f;
        #pragma unroll
        for (int nf = 0; nf < 4; nf++) {
            float p0 = __expf(s[nf][0] - mn0);
            float p1 = __expf(s[nf][1] - mn0);
            float p2 = __expf(s[nf][2] - mn1);
            float p3 = __expf(s[nf][3] - mn1);
            ps0 += p0 + p1; ps1 += p2 + p3;
            Pw[(g    ) * 33 + nf * 8 + tig * 2    ] = tfs(p0);
            Pw[(g    ) * 33 + nf * 8 + tig * 2 + 1] = tfs(p1);
            Pw[(g + 8) * 33 + nf * 8 + tig * 2    ] = tfs(p2);
            Pw[(g + 8) * 33 + nf * 8 + tig * 2 + 1] = tfs(p3);
        }
        ps0 += __shfl_xor_sync(0xffffffffu, ps0, 1);
        ps0 += __shfl_xor_sync(0xffffffffu, ps0, 2);
        ps1 += __shfl_xor_sync(0xffffffffu, ps1, 1);
        ps1 += __shfl_xor_sync(0xffffffffu, ps1, 2);
        l0 = l0 * sc0 + ps0;
        l1 = l1 * sc1 + ps1;

        #pragma unroll
        for (int df = 0; df < 16; df++) {
            o[df][0] *= sc0; o[df][1] *= sc0;
            o[df][2] *= sc1; o[df][3] *= sc1;
        }
        __syncwarp();

        uint32_t pa[4][4];
        #pragma unroll
        for (int kf = 0; kf < 4; kf++) {
            pa[kf][0] = u(Pw[(g    ) * 33 + kf * 8 + tig]);
            pa[kf][1] = u(Pw[(g + 8) * 33 + kf * 8 + tig]);
            pa[kf][2] = u(Pw[(g    ) * 33 + kf * 8 + tig + 4]);
            pa[kf][3] = u(Pw[(g + 8) * 33 + kf * 8 + tig + 4]);
        }

        #pragma unroll
        for (int dfp = 0; dfp < 8; dfp++) {
            #pragma unroll
            for (int kf = 0; kf < 4; kf++) {
                float4 vv = *(const float4*)&Vs[(kf * 8 + dfp) * 128 + lane * 4];
                MMA_TF32(o[2 * dfp][0], o[2 * dfp][1],
                         o[2 * dfp][2], o[2 * dfp][3],
                         pa[kf][0], pa[kf][1], pa[kf][2], pa[kf][3],
                         u(vv.x), u(vv.y));
                MMA_TF32(o[2 * dfp + 1][0], o[2 * dfp + 1][1],
                         o[2 * dfp + 1][2], o[2 * dfp + 1][3],
                         pa[kf][0], pa[kf][1], pa[kf][2], pa[kf][3],
                         u(vv.z), u(vv.w));
            }
        }

        __syncthreads();
        if (tile + 2 < ntiles) issue(tile + 2, tile & 1);
        CP_COMMIT();
    }

    // epilogue: write tf32-rounded O into A-perm tiles for gemm_wo
    float inv0 = 1.f / l0, inv1 = 1.f / l1;
    auto aidx = [](int r, int c) -> size_t {
        int mi = r & 127, ki = c & 31;
        return ((size_t)(r >> 7) * (DD / 32) + (c >> 5)) * 4096
             + (size_t)aperm(mi, ki);
    };
    int r0g = b * TT + qglob + g;
    int r1g = r0g + 8;
    #pragma unroll
    for (int df = 0; df < 16; df++) {
        int c = h * HD + df * 8 + tig * 2;
        O[aidx(r0g, c)]     = tfs(o[df][0] * inv0);
        O[aidx(r0g, c + 1)] = tfs(o[df][1] * inv0);
        O[aidx(r1g, c)]     = tfs(o[df][2] * inv1);
        O[aidx(r1g, c + 1)] = tfs(o[df][3] * inv1);
    }
}

// ---------------- launch --------------------------------------------
extern "C" void kernel_launch(void* const* d_in, const int* in_sizes, int n_in,
                              void* d_out, int out_size) {
    const float* x    = (const float*)d_in[0];
    const float* fcos = (const float*)d_in[1];
    const float* fsin = (const float*)d_in[2];
    const float* Wq   = (const float*)d_in[3];
    const float* Wk   = (const float*)d_in[4];
    const float* Wv   = (const float*)d_in[5];
    const float* Wo   = (const float*)d_in[6];

    float* y    = (float*)d_out;
    float* outK = y + (size_t)BB * TT * DD;
    float* outV = outK + (size_t)BB * KVH * TT * HD;

    float *qs, *att, *xr, *wqr, *wkr, *wvr, *wor, *kr, *vr;
    cudaGetSymbolAddress((void**)&qs,  g_qs);
    cudaGetSymbolAddress((void**)&att, g_att);
    cudaGetSymbolAddress((void**)&xr,  g_xr);
    cudaGetSymbolAddress((void**)&wqr, g_wqr);
    cudaGetSymbolAddress((void**)&wkr, g_wkr);
    cudaGetSymbolAddress((void**)&wvr, g_wvr);
    cudaGetSymbolAddress((void**)&wor, g_wor);
    cudaGetSymbolAddress((void**)&kr,  g_kr);
    cudaGetSymbolAddress((void**)&vr,  g_vr);

    const int M = BB * TT;  // 4096
    static int smem_set = 0;
    if (!smem_set) {
        cudaFuncSetAttribute(flash_mma_kernel,
                             cudaFuncAttributeMaxDynamicSharedMemorySize, FSMEM_BYTES);
        cudaFuncSetAttribute(gemm_qkv,
                             cudaFuncAttributeMaxDynamicSharedMemorySize, GSMEM_BYTES);
        cudaFuncSetAttribute(gemm_wo,
                             cudaFuncAttributeMaxDynamicSharedMemorySize, GSMEM_BYTES);
        smem_set = 1;
    }

    preround_tiles<<<4608, 128>>>(x, xr, Wq, wqr, Wk, wkr, Wv, wvr, Wo, wor);

    gemm_qkv<<<dim3(24, M / 128), 256, GSMEM_BYTES>>>(
        xr, wqr, wkr, wvr, qs, outK, outV, kr, vr, fcos, fsin);

    flash_mma_kernel<<<dim3(TT / 64, HH, BB), 128, FSMEM_BYTES>>>(
        qs, kr, vr, att);

    gemm_wo<<<dim3(DD / 128, M / 128), 256, GSMEM_BYTES>>>(att, wor, y);
}